// round 2
// baseline (speedup 1.0000x reference)
#include <cuda_runtime.h>
#include <math_constants.h>

// Problem constants
#define N_EMBED 1024
#define HEAD    64
#define BATCH   8
#define SEQ     2048
#define MROWS   (BATCH * SEQ)   // 16384

// Scratch for q, k, v projections (device globals: no allocation allowed)
__device__ float g_q[MROWS * HEAD];
__device__ float g_k[MROWS * HEAD];
__device__ float g_v[MROWS * HEAD];

// ---------------------------------------------------------------------------
// Kernel 1: fused QKV projection.
// out[m][n] = sum_k x[m][k] * W[k][n],  M=16384, K=1024, N=64.
// Grid: (M/64, 3). Block: 256 threads. Each block computes a 64x64 output
// tile; each thread computes a 4x4 micro-tile. K is streamed in chunks of 16.
// ---------------------------------------------------------------------------
__global__ __launch_bounds__(256) void proj_kernel(
    const float* __restrict__ x,
    const float* __restrict__ Wq,
    const float* __restrict__ Wk,
    const float* __restrict__ Wv)
{
    const int which = blockIdx.y;
    const float* __restrict__ W = (which == 0) ? Wq : (which == 1) ? Wk : Wv;
    float* __restrict__ out = (which == 0) ? g_q : (which == 1) ? g_k : g_v;

    const int m0 = blockIdx.x * 64;
    const int tid = threadIdx.x;
    const int tx = tid & 15;          // col group: cols tx*4 .. tx*4+3
    const int ty = tid >> 4;          // row group: rows ty*4 .. ty*4+3

    __shared__ float  xs[64][17];     // pad 17: avoids bank conflicts on column reads
    __shared__ float4 ws4[16][16];    // ws4[kk][c/4]

    float4 acc[4];
    #pragma unroll
    for (int i = 0; i < 4; i++) acc[i] = make_float4(0.f, 0.f, 0.f, 0.f);

    // load indices for the staging phase
    const int lrow = tid >> 2;        // 0..63
    const int lqd  = tid & 3;         // 0..3  (which float4 of 16 cols)
    const int wkk  = tid >> 4;        // 0..15
    const int wq   = tid & 15;        // 0..15

    for (int ch = 0; ch < N_EMBED / 16; ch++) {
        const int kc0 = ch * 16;
        // stage x tile: 64 rows x 16 cols
        float4 xv = *reinterpret_cast<const float4*>(
            &x[(size_t)(m0 + lrow) * N_EMBED + kc0 + lqd * 4]);
        xs[lrow][lqd * 4 + 0] = xv.x;
        xs[lrow][lqd * 4 + 1] = xv.y;
        xs[lrow][lqd * 4 + 2] = xv.z;
        xs[lrow][lqd * 4 + 3] = xv.w;
        // stage W tile: 16 rows x 64 cols
        ws4[wkk][wq] = reinterpret_cast<const float4*>(
            W + (size_t)(kc0 + wkk) * HEAD)[wq];
        __syncthreads();

        #pragma unroll
        for (int kk = 0; kk < 16; kk++) {
            float4 b = ws4[kk][tx];
            float a0 = xs[ty * 4 + 0][kk];
            float a1 = xs[ty * 4 + 1][kk];
            float a2 = xs[ty * 4 + 2][kk];
            float a3 = xs[ty * 4 + 3][kk];
            acc[0].x += a0 * b.x; acc[0].y += a0 * b.y; acc[0].z += a0 * b.z; acc[0].w += a0 * b.w;
            acc[1].x += a1 * b.x; acc[1].y += a1 * b.y; acc[1].z += a1 * b.z; acc[1].w += a1 * b.w;
            acc[2].x += a2 * b.x; acc[2].y += a2 * b.y; acc[2].z += a2 * b.z; acc[2].w += a2 * b.w;
            acc[3].x += a3 * b.x; acc[3].y += a3 * b.y; acc[3].z += a3 * b.z; acc[3].w += a3 * b.w;
        }
        __syncthreads();
    }

    #pragma unroll
    for (int i = 0; i < 4; i++) {
        *reinterpret_cast<float4*>(
            &out[(size_t)(m0 + ty * 4 + i) * HEAD + tx * 4]) = acc[i];
    }
}

// ---------------------------------------------------------------------------
// Kernel 2: flash-attention-style causal attention.
// Grid: (SEQ/64, BATCH). Block: 256 threads. Each block handles one 64-row
// query tile of one batch, streaming 64-row K/V tiles j = 0..qi with online
// softmax. Thread micro-tile: 4 rows (tr) x 4 cols (tc) of the 64x64 S tile,
// and 4 rows x 4 head-cols of the O accumulator.
// ---------------------------------------------------------------------------
// Dynamic smem layout (floats):
//   qs: 64*65, ks: 64*65, ps: 64*65, vs: 64*68  -> 16832 floats = 67328 B
#define QS_PITCH 65
#define KS_PITCH 65
#define PS_PITCH 65
#define VS_PITCH 68
#define SMEM_FLOATS (64 * QS_PITCH + 64 * KS_PITCH + 64 * PS_PITCH + 64 * VS_PITCH)

__global__ __launch_bounds__(256) void attn_kernel(float* __restrict__ out)
{
    extern __shared__ float sm[];
    float* qs = sm;
    float* ks = qs + 64 * QS_PITCH;
    float* ps = ks + 64 * KS_PITCH;
    float* vs = ps + 64 * PS_PITCH;

    const int qi = blockIdx.x;     // query tile index (0..31)
    const int b  = blockIdx.y;     // batch
    const int tid = threadIdx.x;
    const int tc = tid & 15;       // col group
    const int tr = tid >> 4;       // row group

    const float* __restrict__ gq = g_q + (size_t)b * SEQ * HEAD;
    const float* __restrict__ gk = g_k + (size_t)b * SEQ * HEAD;
    const float* __restrict__ gv = g_v + (size_t)b * SEQ * HEAD;

    const float scale = 0.125f;    // 1/sqrt(64)

    // Load Q tile (rows qi*64 .. +63)
    for (int idx = tid; idx < 64 * 64; idx += 256) {
        int r = idx >> 6, c = idx & 63;
        qs[r * QS_PITCH + c] = gq[(size_t)(qi * 64 + r) * HEAD + c];
    }

    float m_i[4], l_i[4];
    float4 o_i[4];
    #pragma unroll
    for (int i = 0; i < 4; i++) {
        m_i[i] = -CUDART_INF_F;
        l_i[i] = 0.f;
        o_i[i] = make_float4(0.f, 0.f, 0.f, 0.f);
    }
    __syncthreads();

    const int vrow = tid >> 2;     // 0..63
    const int vq   = tid & 3;      // float4 quarters handled in loop

    for (int j = 0; j <= qi; j++) {
        // stage K tile (scalar, coalesced) and V tile (float4)
        for (int idx = tid; idx < 64 * 64; idx += 256) {
            int r = idx >> 6, c = idx & 63;
            ks[r * KS_PITCH + c] = gk[(size_t)(j * 64 + r) * HEAD + c];
        }
        {
            // 64 rows x 16 float4 = 1024 float4; 4 per thread
            #pragma unroll
            for (int rep = 0; rep < 4; rep++) {
                int r = vrow;
                int q4 = vq + rep * 4;
                float4 v = *reinterpret_cast<const float4*>(
                    &gv[(size_t)(j * 64 + r) * HEAD + q4 * 4]);
                *reinterpret_cast<float4*>(&vs[r * VS_PITCH + q4 * 4]) = v;
            }
        }
        __syncthreads();

        // S = Q K^T  (4x4 micro-tile per thread)
        float s[4][4];
        #pragma unroll
        for (int i = 0; i < 4; i++)
            #pragma unroll
            for (int jj = 0; jj < 4; jj++) s[i][jj] = 0.f;

        #pragma unroll 4
        for (int h = 0; h < HEAD; h++) {
            float qa[4], kb[4];
            #pragma unroll
            for (int i = 0; i < 4; i++)  qa[i] = qs[(tr * 4 + i) * QS_PITCH + h];
            #pragma unroll
            for (int jj = 0; jj < 4; jj++) kb[jj] = ks[(tc * 4 + jj) * KS_PITCH + h];
            #pragma unroll
            for (int i = 0; i < 4; i++)
                #pragma unroll
                for (int jj = 0; jj < 4; jj++)
                    s[i][jj] += qa[i] * kb[jj];
        }

        // scale + causal mask (only the diagonal tile needs masking)
        #pragma unroll
        for (int i = 0; i < 4; i++) {
            const int rg = qi * 64 + tr * 4 + i;
            #pragma unroll
            for (int jj = 0; jj < 4; jj++) {
                const int cg = j * 64 + tc * 4 + jj;
                s[i][jj] = (cg > rg) ? -CUDART_INF_F : s[i][jj] * scale;
            }
        }

        // online softmax update per row
        float p[4][4];
        float alpha[4];
        #pragma unroll
        for (int i = 0; i < 4; i++) {
            float rmax = s[i][0];
            #pragma unroll
            for (int jj = 1; jj < 4; jj++) rmax = fmaxf(rmax, s[i][jj]);
            #pragma unroll
            for (int m = 1; m < 16; m <<= 1)
                rmax = fmaxf(rmax, __shfl_xor_sync(0xffffffffu, rmax, m));
            const float mnew = fmaxf(m_i[i], rmax);
            float rsum = 0.f;
            #pragma unroll
            for (int jj = 0; jj < 4; jj++) {
                p[i][jj] = __expf(s[i][jj] - mnew);   // exp(-inf)=0 handles mask
                rsum += p[i][jj];
            }
            #pragma unroll
            for (int m = 1; m < 16; m <<= 1)
                rsum += __shfl_xor_sync(0xffffffffu, rsum, m);
            alpha[i] = __expf(m_i[i] - mnew);
            l_i[i] = l_i[i] * alpha[i] + rsum;
            m_i[i] = mnew;
            o_i[i].x *= alpha[i]; o_i[i].y *= alpha[i];
            o_i[i].z *= alpha[i]; o_i[i].w *= alpha[i];
        }

        // share P through smem for the O accumulation
        #pragma unroll
        for (int i = 0; i < 4; i++)
            #pragma unroll
            for (int jj = 0; jj < 4; jj++)
                ps[(tr * 4 + i) * PS_PITCH + tc * 4 + jj] = p[i][jj];
        __syncthreads();

        // O += P V   (each thread: 4 rows x 4 head-cols, h0 = tc*4)
        #pragma unroll 4
        for (int c = 0; c < 64; c++) {
            float4 vb = *reinterpret_cast<const float4*>(&vs[c * VS_PITCH + tc * 4]);
            #pragma unroll
            for (int i = 0; i < 4; i++) {
                float pv = ps[(tr * 4 + i) * PS_PITCH + c];
                o_i[i].x += pv * vb.x; o_i[i].y += pv * vb.y;
                o_i[i].z += pv * vb.z; o_i[i].w += pv * vb.w;
            }
        }
        __syncthreads();   // protect ks/vs/ps for next iteration
    }

    // normalize and write out
    #pragma unroll
    for (int i = 0; i < 4; i++) {
        const float inv = __frcp_rn(l_i[i]);
        float4 o = o_i[i];
        o.x *= inv; o.y *= inv; o.z *= inv; o.w *= inv;
        *reinterpret_cast<float4*>(
            &out[((size_t)b * SEQ + qi * 64 + tr * 4 + i) * HEAD + tc * 4]) = o;
    }
}

// ---------------------------------------------------------------------------
extern "C" void kernel_launch(void* const* d_in, const int* in_sizes, int n_in,
                              void* d_out, int out_size)
{
    const float* x  = (const float*)d_in[0];
    const float* Wq = (const float*)d_in[1];
    const float* Wk = (const float*)d_in[2];
    const float* Wv = (const float*)d_in[3];
    float* out = (float*)d_out;

    (void)in_sizes; (void)n_in; (void)out_size;

    cudaFuncSetAttribute(attn_kernel,
                         cudaFuncAttributeMaxDynamicSharedMemorySize,
                         SMEM_FLOATS * (int)sizeof(float));

    proj_kernel<<<dim3(MROWS / 64, 3), 256>>>(x, Wq, Wk, Wv);
    attn_kernel<<<dim3(SEQ / 64, BATCH), 256,
                  SMEM_FLOATS * (int)sizeof(float)>>>(out);
}

// round 3
// speedup vs baseline: 1.5364x; 1.5364x over previous
#include <cuda_runtime.h>
#include <math_constants.h>
#include <cstdint>

#define N_EMBED 1024
#define HEAD    64
#define BATCH   8
#define SEQ     2048
#define MROWS   (BATCH * SEQ)   // 16384

// Scratch for q, k, v projections
__device__ float g_q[MROWS * HEAD];
__device__ float g_k[MROWS * HEAD];
__device__ float g_v[MROWS * HEAD];

// ---------------------------------------------------------------------------
// tf32 helpers
// ---------------------------------------------------------------------------
__device__ __forceinline__ uint32_t f2tf(float x) {
    uint32_t u;
    asm("cvt.rna.tf32.f32 %0, %1;" : "=r"(u) : "f"(x));
    return u;
}

// D += A(16x8,row) * B(8x8,col), tf32 inputs, f32 accumulate
__device__ __forceinline__ void mma8(float4& c,
                                     uint32_t a0, uint32_t a1, uint32_t a2, uint32_t a3,
                                     uint32_t b0, uint32_t b1) {
    asm volatile(
        "mma.sync.aligned.m16n8k8.row.col.f32.tf32.tf32.f32 "
        "{%0,%1,%2,%3}, {%4,%5,%6,%7}, {%8,%9}, {%0,%1,%2,%3};"
        : "+f"(c.x), "+f"(c.y), "+f"(c.z), "+f"(c.w)
        : "r"(a0), "r"(a1), "r"(a2), "r"(a3), "r"(b0), "r"(b1));
}

// ---------------------------------------------------------------------------
// Kernel 1: QKV projection, 3xtf32 tensor-core GEMM.
// M=16384, K=1024, N=64. Grid (128, 3), 256 threads (8 warps).
// Block tile 128x64; warp tile 16x64 (8 n-tiles of m16n8k8). K chunk = 32.
// ---------------------------------------------------------------------------
#define XS_PITCH 36   // (4*g + tg) unique mod 32 -> conflict-free A loads
#define WS_PITCH 68   // (4*tg + g) unique mod 32 -> conflict-free B loads

__global__ __launch_bounds__(256) void proj_kernel(
    const float* __restrict__ x,
    const float* __restrict__ Wq,
    const float* __restrict__ Wk,
    const float* __restrict__ Wv)
{
    const int which = blockIdx.y;
    const float* __restrict__ W = (which == 0) ? Wq : (which == 1) ? Wk : Wv;
    float* __restrict__ out = (which == 0) ? g_q : (which == 1) ? g_k : g_v;

    const int m0   = blockIdx.x * 128;
    const int tid  = threadIdx.x;
    const int warp = tid >> 5, lane = tid & 31;
    const int g = lane >> 2, tg = lane & 3;
    const int wr = warp * 16;

    __shared__ float xs[128 * XS_PITCH];
    __shared__ float wh[32 * WS_PITCH];
    __shared__ float wl[32 * WS_PITCH];

    float4 acc[8] = {};

    const int xrow = tid >> 1;
    const int xc0  = (tid & 1) * 16;

    for (int ch = 0; ch < N_EMBED / 32; ch++) {
        const int kc0 = ch * 32;
        // stage x tile 128x32 (raw fp32)
        #pragma unroll
        for (int rep = 0; rep < 4; rep++) {
            float4 v = *reinterpret_cast<const float4*>(
                &x[(size_t)(m0 + xrow) * N_EMBED + kc0 + xc0 + rep * 4]);
            float* d = &xs[xrow * XS_PITCH + xc0 + rep * 4];
            d[0] = v.x; d[1] = v.y; d[2] = v.z; d[3] = v.w;
        }
        // stage W tile 32x64 as hi/lo
        #pragma unroll
        for (int rep = 0; rep < 2; rep++) {
            int f = tid + rep * 256;           // 0..511 float4s
            int r = f >> 4, c4 = (f & 15) * 4;
            float4 v = *reinterpret_cast<const float4*>(
                &W[(size_t)(kc0 + r) * HEAD + c4]);
            float e[4] = {v.x, v.y, v.z, v.w};
            float* dh = &wh[r * WS_PITCH + c4];
            float* dl = &wl[r * WS_PITCH + c4];
            #pragma unroll
            for (int i = 0; i < 4; i++) {
                float h = __uint_as_float(f2tf(e[i]));
                dh[i] = h;
                dl[i] = e[i] - h;   // residual; HW truncation of lo -> eps^2, negligible
            }
        }
        __syncthreads();

        #pragma unroll
        for (int kk = 0; kk < 4; kk++) {
            float ar[4];
            ar[0] = xs[(wr + g    ) * XS_PITCH + kk * 8 + tg    ];
            ar[1] = xs[(wr + g + 8) * XS_PITCH + kk * 8 + tg    ];
            ar[2] = xs[(wr + g    ) * XS_PITCH + kk * 8 + tg + 4];
            ar[3] = xs[(wr + g + 8) * XS_PITCH + kk * 8 + tg + 4];
            uint32_t ah[4], al[4];
            #pragma unroll
            for (int i = 0; i < 4; i++) {
                ah[i] = f2tf(ar[i]);
                al[i] = __float_as_uint(ar[i] - __uint_as_float(ah[i]));
            }
            #pragma unroll
            for (int nt = 0; nt < 8; nt++) {
                int br0 = (kk * 8 + tg    ) * WS_PITCH + nt * 8 + g;
                int br1 = (kk * 8 + tg + 4) * WS_PITCH + nt * 8 + g;
                uint32_t bh0 = __float_as_uint(wh[br0]);
                uint32_t bh1 = __float_as_uint(wh[br1]);
                uint32_t bl0 = __float_as_uint(wl[br0]);
                uint32_t bl1 = __float_as_uint(wl[br1]);
                mma8(acc[nt], ah[0], ah[1], ah[2], ah[3], bh0, bh1);
                mma8(acc[nt], ah[0], ah[1], ah[2], ah[3], bl0, bl1);
                mma8(acc[nt], al[0], al[1], al[2], al[3], bh0, bh1);
            }
        }
        __syncthreads();
    }

    #pragma unroll
    for (int nt = 0; nt < 8; nt++) {
        int col = nt * 8 + 2 * tg;
        *reinterpret_cast<float2*>(&out[(size_t)(m0 + wr + g    ) * HEAD + col]) =
            make_float2(acc[nt].x, acc[nt].y);
        *reinterpret_cast<float2*>(&out[(size_t)(m0 + wr + g + 8) * HEAD + col]) =
            make_float2(acc[nt].z, acc[nt].w);
    }
}

// ---------------------------------------------------------------------------
// Kernel 2: causal flash attention on tensor cores.
// Grid (16, 8), 128 threads (4 warps). Block bx handles query tiles bx and
// 31-bx -> every block does exactly 33 KV chunks (perfect balance).
// S = QK^T via 3xtf32; P.V via tf32 (P in [0,1], error ~1e-4).
// ---------------------------------------------------------------------------
#define AP 68   // pitch: all fragment access patterns conflict-free mod 32

// smem tiles (floats): qsh, qsl, ksh, ksl, vs, ps -> 6 * 64 * AP
#define ATTN_SMEM_FLOATS (6 * 64 * AP)

__global__ __launch_bounds__(128) void attn_kernel(float* __restrict__ out)
{
    extern __shared__ float sm[];
    float* qsh = sm;
    float* qsl = qsh + 64 * AP;
    float* ksh = qsl + 64 * AP;
    float* ksl = ksh + 64 * AP;
    float* vs  = ksl + 64 * AP;
    float* ps  = vs  + 64 * AP;

    const int bx  = blockIdx.x;   // 0..15
    const int b   = blockIdx.y;
    const int tid = threadIdx.x;
    const int warp = tid >> 5, lane = tid & 31;
    const int g = lane >> 2, tg = lane & 3;
    const int qr = warp * 16;

    const float* __restrict__ gq = g_q + (size_t)b * SEQ * HEAD;
    const float* __restrict__ gk = g_k + (size_t)b * SEQ * HEAD;
    const float* __restrict__ gv = g_v + (size_t)b * SEQ * HEAD;

    const int srow = tid >> 1;        // 0..63
    const int sc0  = (tid & 1) * 32;  // 2 threads per row, 8 float4 each

    const float SC = 0.125f;          // 1/sqrt(64)

    for (int t = 0; t < 2; t++) {
        const int tile = (t == 0) ? bx : 31 - bx;
        __syncthreads();
        // stage Q tile as hi/lo
        #pragma unroll
        for (int rep = 0; rep < 8; rep++) {
            float4 v = *reinterpret_cast<const float4*>(
                &gq[(size_t)(tile * 64 + srow) * HEAD + sc0 + rep * 4]);
            float e[4] = {v.x, v.y, v.z, v.w};
            float* dh = &qsh[srow * AP + sc0 + rep * 4];
            float* dl = &qsl[srow * AP + sc0 + rep * 4];
            #pragma unroll
            for (int i = 0; i < 4; i++) {
                float h = __uint_as_float(f2tf(e[i]));
                dh[i] = h;
                dl[i] = e[i] - h;
            }
        }

        float m0 = -CUDART_INF_F, m1 = -CUDART_INF_F;
        float l0 = 0.f, l1 = 0.f;
        float4 o[8] = {};

        for (int j = 0; j <= tile; j++) {
            __syncthreads();
            // stage K (hi/lo) and V (tf32-rounded)
            #pragma unroll
            for (int rep = 0; rep < 8; rep++) {
                float4 kv = *reinterpret_cast<const float4*>(
                    &gk[(size_t)(j * 64 + srow) * HEAD + sc0 + rep * 4]);
                float ke[4] = {kv.x, kv.y, kv.z, kv.w};
                float* dh = &ksh[srow * AP + sc0 + rep * 4];
                float* dl = &ksl[srow * AP + sc0 + rep * 4];
                #pragma unroll
                for (int i = 0; i < 4; i++) {
                    float h = __uint_as_float(f2tf(ke[i]));
                    dh[i] = h;
                    dl[i] = ke[i] - h;
                }
                float4 vv = *reinterpret_cast<const float4*>(
                    &gv[(size_t)(j * 64 + srow) * HEAD + sc0 + rep * 4]);
                float* dv = &vs[srow * AP + sc0 + rep * 4];
                dv[0] = __uint_as_float(f2tf(vv.x));
                dv[1] = __uint_as_float(f2tf(vv.y));
                dv[2] = __uint_as_float(f2tf(vv.z));
                dv[3] = __uint_as_float(f2tf(vv.w));
            }
            __syncthreads();

            // ---- S = Q K^T (3xtf32) ----
            float4 s[8] = {};
            #pragma unroll
            for (int kk = 0; kk < 8; kk++) {
                uint32_t ah[4], al[4];
                ah[0] = __float_as_uint(qsh[(qr + g    ) * AP + kk * 8 + tg    ]);
                ah[1] = __float_as_uint(qsh[(qr + g + 8) * AP + kk * 8 + tg    ]);
                ah[2] = __float_as_uint(qsh[(qr + g    ) * AP + kk * 8 + tg + 4]);
                ah[3] = __float_as_uint(qsh[(qr + g + 8) * AP + kk * 8 + tg + 4]);
                al[0] = __float_as_uint(qsl[(qr + g    ) * AP + kk * 8 + tg    ]);
                al[1] = __float_as_uint(qsl[(qr + g + 8) * AP + kk * 8 + tg    ]);
                al[2] = __float_as_uint(qsl[(qr + g    ) * AP + kk * 8 + tg + 4]);
                al[3] = __float_as_uint(qsl[(qr + g + 8) * AP + kk * 8 + tg + 4]);
                #pragma unroll
                for (int nt = 0; nt < 8; nt++) {
                    int br0 = (nt * 8 + g) * AP + kk * 8 + tg;
                    uint32_t bh0 = __float_as_uint(ksh[br0]);
                    uint32_t bh1 = __float_as_uint(ksh[br0 + 4]);
                    uint32_t bl0 = __float_as_uint(ksl[br0]);
                    uint32_t bl1 = __float_as_uint(ksl[br0 + 4]);
                    mma8(s[nt], ah[0], ah[1], ah[2], ah[3], bh0, bh1);
                    mma8(s[nt], ah[0], ah[1], ah[2], ah[3], bl0, bl1);
                    mma8(s[nt], al[0], al[1], al[2], al[3], bh0, bh1);
                }
            }

            // ---- scale + causal mask ----
            if (j == tile) {
                const int rg0 = tile * 64 + qr + g;
                const int rg1 = rg0 + 8;
                #pragma unroll
                for (int nt = 0; nt < 8; nt++) {
                    const int cg = j * 64 + nt * 8 + 2 * tg;
                    s[nt].x = (cg     > rg0) ? -CUDART_INF_F : s[nt].x * SC;
                    s[nt].y = (cg + 1 > rg0) ? -CUDART_INF_F : s[nt].y * SC;
                    s[nt].z = (cg     > rg1) ? -CUDART_INF_F : s[nt].z * SC;
                    s[nt].w = (cg + 1 > rg1) ? -CUDART_INF_F : s[nt].w * SC;
                }
            } else {
                #pragma unroll
                for (int nt = 0; nt < 8; nt++) {
                    s[nt].x *= SC; s[nt].y *= SC; s[nt].z *= SC; s[nt].w *= SC;
                }
            }

            // ---- online softmax (2 rows per thread: qr+g and qr+g+8) ----
            float rm0 = -CUDART_INF_F, rm1 = -CUDART_INF_F;
            #pragma unroll
            for (int nt = 0; nt < 8; nt++) {
                rm0 = fmaxf(rm0, fmaxf(s[nt].x, s[nt].y));
                rm1 = fmaxf(rm1, fmaxf(s[nt].z, s[nt].w));
            }
            rm0 = fmaxf(rm0, __shfl_xor_sync(0xffffffffu, rm0, 1));
            rm0 = fmaxf(rm0, __shfl_xor_sync(0xffffffffu, rm0, 2));
            rm1 = fmaxf(rm1, __shfl_xor_sync(0xffffffffu, rm1, 1));
            rm1 = fmaxf(rm1, __shfl_xor_sync(0xffffffffu, rm1, 2));
            const float nm0 = fmaxf(m0, rm0);
            const float nm1 = fmaxf(m1, rm1);
            const float a0 = __expf(m0 - nm0);
            const float a1 = __expf(m1 - nm1);

            float rs0 = 0.f, rs1 = 0.f;
            #pragma unroll
            for (int nt = 0; nt < 8; nt++) {
                float px = __expf(s[nt].x - nm0);
                float py = __expf(s[nt].y - nm0);
                float pz = __expf(s[nt].z - nm1);
                float pw = __expf(s[nt].w - nm1);
                rs0 += px + py;
                rs1 += pz + pw;
                int pc = nt * 8 + 2 * tg;
                ps[(qr + g    ) * AP + pc    ] = __uint_as_float(f2tf(px));
                ps[(qr + g    ) * AP + pc + 1] = __uint_as_float(f2tf(py));
                ps[(qr + g + 8) * AP + pc    ] = __uint_as_float(f2tf(pz));
                ps[(qr + g + 8) * AP + pc + 1] = __uint_as_float(f2tf(pw));
            }
            rs0 += __shfl_xor_sync(0xffffffffu, rs0, 1);
            rs0 += __shfl_xor_sync(0xffffffffu, rs0, 2);
            rs1 += __shfl_xor_sync(0xffffffffu, rs1, 1);
            rs1 += __shfl_xor_sync(0xffffffffu, rs1, 2);
            l0 = l0 * a0 + rs0;
            l1 = l1 * a1 + rs1;
            m0 = nm0; m1 = nm1;
            #pragma unroll
            for (int nt = 0; nt < 8; nt++) {
                o[nt].x *= a0; o[nt].y *= a0;
                o[nt].z *= a1; o[nt].w *= a1;
            }
            __syncwarp();   // ps written/read within the warp only

            // ---- O += P V (tf32) ----
            #pragma unroll
            for (int kk = 0; kk < 8; kk++) {
                uint32_t pa[4];
                pa[0] = __float_as_uint(ps[(qr + g    ) * AP + kk * 8 + tg    ]);
                pa[1] = __float_as_uint(ps[(qr + g + 8) * AP + kk * 8 + tg    ]);
                pa[2] = __float_as_uint(ps[(qr + g    ) * AP + kk * 8 + tg + 4]);
                pa[3] = __float_as_uint(ps[(qr + g + 8) * AP + kk * 8 + tg + 4]);
                #pragma unroll
                for (int nt = 0; nt < 8; nt++) {
                    uint32_t b0 = __float_as_uint(vs[(kk * 8 + tg    ) * AP + nt * 8 + g]);
                    uint32_t b1 = __float_as_uint(vs[(kk * 8 + tg + 4) * AP + nt * 8 + g]);
                    mma8(o[nt], pa[0], pa[1], pa[2], pa[3], b0, b1);
                }
            }
        }

        // normalize and write this tile's output
        const float inv0 = __frcp_rn(l0);
        const float inv1 = __frcp_rn(l1);
        #pragma unroll
        for (int nt = 0; nt < 8; nt++) {
            int col = nt * 8 + 2 * tg;
            *reinterpret_cast<float2*>(
                &out[((size_t)b * SEQ + tile * 64 + qr + g    ) * HEAD + col]) =
                make_float2(o[nt].x * inv0, o[nt].y * inv0);
            *reinterpret_cast<float2*>(
                &out[((size_t)b * SEQ + tile * 64 + qr + g + 8) * HEAD + col]) =
                make_float2(o[nt].z * inv1, o[nt].w * inv1);
        }
    }
}

// ---------------------------------------------------------------------------
extern "C" void kernel_launch(void* const* d_in, const int* in_sizes, int n_in,
                              void* d_out, int out_size)
{
    const float* x  = (const float*)d_in[0];
    const float* Wq = (const float*)d_in[1];
    const float* Wk = (const float*)d_in[2];
    const float* Wv = (const float*)d_in[3];
    float* out = (float*)d_out;

    (void)in_sizes; (void)n_in; (void)out_size;

    cudaFuncSetAttribute(attn_kernel,
                         cudaFuncAttributeMaxDynamicSharedMemorySize,
                         ATTN_SMEM_FLOATS * (int)sizeof(float));

    proj_kernel<<<dim3(MROWS / 128, 3), 256>>>(x, Wq, Wk, Wv);
    attn_kernel<<<dim3(16, BATCH), 128,
                  ATTN_SMEM_FLOATS * (int)sizeof(float)>>>(out);
}

// round 4
// speedup vs baseline: 2.4697x; 1.6075x over previous
#include <cuda_runtime.h>
#include <cuda_bf16.h>
#include <math_constants.h>
#include <cstdint>

#define N_EMBED 1024
#define HEAD    64
#define BATCH   8
#define SEQ     2048
#define MROWS   (BATCH * SEQ)   // 16384

// ---------------------------------------------------------------------------
// Global scratch (no allocation allowed)
// ---------------------------------------------------------------------------
__device__ uint16_t g_qh[MROWS * HEAD], g_ql[MROWS * HEAD];   // Q bf16 hi/lo [row][head]
__device__ uint16_t g_kh[MROWS * HEAD], g_kl[MROWS * HEAD];   // K bf16 hi/lo [row][head]
__device__ uint16_t g_vth[MROWS * HEAD], g_vtl[MROWS * HEAD]; // V^T bf16 hi/lo [b][head][seq]
__device__ float    g_v[MROWS * HEAD];                        // V fp32 (for transpose kernel)
__device__ uint16_t g_wth[3 * HEAD * N_EMBED], g_wtl[3 * HEAD * N_EMBED]; // W^T [which][n][k]

// ---------------------------------------------------------------------------
// helpers
// ---------------------------------------------------------------------------
__device__ __forceinline__ uint32_t packbf(float lo, float hi) {
    uint32_t r;
    asm("cvt.rn.bf16x2.f32 %0, %1, %2;" : "=r"(r) : "f"(hi), "f"(lo));
    return r;
}
// x0 -> low half, x1 -> high half; l = bf16 residuals
__device__ __forceinline__ void hilo2(float x0, float x1, uint32_t& h, uint32_t& l) {
    h = packbf(x0, x1);
    float r0 = x0 - __uint_as_float(h << 16);
    float r1 = x1 - __uint_as_float(h & 0xFFFF0000u);
    l = packbf(r0, r1);
}

__device__ __forceinline__ void mma16(float4& c,
                                      uint32_t a0, uint32_t a1, uint32_t a2, uint32_t a3,
                                      uint32_t b0, uint32_t b1) {
    asm volatile(
        "mma.sync.aligned.m16n8k16.row.col.f32.bf16.bf16.f32 "
        "{%0,%1,%2,%3}, {%4,%5,%6,%7}, {%8,%9}, {%0,%1,%2,%3};"
        : "+f"(c.x), "+f"(c.y), "+f"(c.z), "+f"(c.w)
        : "r"(a0), "r"(a1), "r"(a2), "r"(a3), "r"(b0), "r"(b1));
}

__device__ __forceinline__ void cp16(uint32_t dst, const void* src) {
    asm volatile("cp.async.cg.shared.global [%0], [%1], 16;" :: "r"(dst), "l"(src));
}
__device__ __forceinline__ void cp_commit() {
    asm volatile("cp.async.commit_group;");
}
template <int N>
__device__ __forceinline__ void cp_wait() {
    asm volatile("cp.async.wait_group %0;" :: "n"(N));
}

// ---------------------------------------------------------------------------
// wprep: W [k][n] fp32 -> W^T [n][k] bf16 hi/lo.  grid (16, 3), 256 thr.
// ---------------------------------------------------------------------------
__global__ __launch_bounds__(256) void wprep_kernel(
    const float* __restrict__ Wq, const float* __restrict__ Wk,
    const float* __restrict__ Wv)
{
    const int which = blockIdx.y;
    const float* __restrict__ W = (which == 0) ? Wq : (which == 1) ? Wk : Wv;
    const int k0 = blockIdx.x * 64;

    __shared__ float sw[64][68];
    const int t = threadIdx.x;
    const int r = t >> 2, c16 = (t & 3) * 16;
    #pragma unroll
    for (int rep = 0; rep < 4; rep++) {
        float4 v = *reinterpret_cast<const float4*>(
            &W[(size_t)(k0 + r) * HEAD + c16 + rep * 4]);
        sw[r][c16 + rep * 4 + 0] = v.x; sw[r][c16 + rep * 4 + 1] = v.y;
        sw[r][c16 + rep * 4 + 2] = v.z; sw[r][c16 + rep * 4 + 3] = v.w;
    }
    __syncthreads();
    // write transposed: n = r, k slab cols c16..c16+15
    uint32_t hp[8], lp[8];
    #pragma unroll
    for (int i = 0; i < 8; i++)
        hilo2(sw[c16 + 2 * i][r], sw[c16 + 2 * i + 1][r], hp[i], lp[i]);
    size_t off = ((size_t)(which * HEAD + r)) * N_EMBED + k0 + c16;
    *reinterpret_cast<uint4*>(&g_wth[off    ]) = make_uint4(hp[0], hp[1], hp[2], hp[3]);
    *reinterpret_cast<uint4*>(&g_wth[off + 8]) = make_uint4(hp[4], hp[5], hp[6], hp[7]);
    *reinterpret_cast<uint4*>(&g_wtl[off    ]) = make_uint4(lp[0], lp[1], lp[2], lp[3]);
    *reinterpret_cast<uint4*>(&g_wtl[off + 8]) = make_uint4(lp[4], lp[5], lp[6], lp[7]);
}

// ---------------------------------------------------------------------------
// proj: x [16384][1024] @ W -> q/k as bf16 hi/lo, v as fp32.
// grid (3, 128), 256 thr (8 warps: 4 m-groups x 2 n-groups).
// block tile 128x64; warp tile 32x32; bf16 3-term, K chunk 32 (2 x k16).
// ---------------------------------------------------------------------------
#define XP  40   // bf16 pitch (word pitch 20 -> conflict-free fragments)
#define XPW 20

__global__ __launch_bounds__(256) void proj_kernel(const float* __restrict__ x)
{
    const int which = blockIdx.x;
    const int m0 = blockIdx.y * 128;
    const int t = threadIdx.x;
    const int warp = t >> 5, lane = t & 31;
    const int g = lane >> 2, tg = lane & 3;
    const int wm = warp >> 1, wn = warp & 1;

    __shared__ __align__(16) uint16_t xh[128 * XP], xl[128 * XP];
    __shared__ __align__(16) uint16_t wts_h[64 * XP], wts_l[64 * XP];

    const uint16_t* __restrict__ gwh = g_wth + (size_t)which * HEAD * N_EMBED;
    const uint16_t* __restrict__ gwl = g_wtl + (size_t)which * HEAD * N_EMBED;

    float4 acc[2][4] = {};

    const int xr = t >> 1, xc = (t & 1) * 16;
    const int wr = t >> 2, wc = (t & 3) * 8;

    uint32_t* xh32w = reinterpret_cast<uint32_t*>(xh);
    uint32_t* xl32w = reinterpret_cast<uint32_t*>(xl);

    for (int ch = 0; ch < N_EMBED / 32; ch++) {
        const int kc0 = ch * 32;
        // stage x 128x32 as bf16 hi/lo
        #pragma unroll
        for (int rep = 0; rep < 4; rep++) {
            float4 v = *reinterpret_cast<const float4*>(
                &x[(size_t)(m0 + xr) * N_EMBED + kc0 + xc + rep * 4]);
            uint32_t h0, l0, h1, l1;
            hilo2(v.x, v.y, h0, l0);
            hilo2(v.z, v.w, h1, l1);
            int wb = xr * XPW + ((xc + rep * 4) >> 1);
            xh32w[wb] = h0; xh32w[wb + 1] = h1;
            xl32w[wb] = l0; xl32w[wb + 1] = l1;
        }
        // stage W^T 64x32 (simple 16B copies)
        *reinterpret_cast<uint4*>(&wts_h[wr * XP + wc]) =
            *reinterpret_cast<const uint4*>(&gwh[(size_t)wr * N_EMBED + kc0 + wc]);
        *reinterpret_cast<uint4*>(&wts_l[wr * XP + wc]) =
            *reinterpret_cast<const uint4*>(&gwl[(size_t)wr * N_EMBED + kc0 + wc]);
        __syncthreads();

        const uint32_t* xh32 = reinterpret_cast<const uint32_t*>(xh);
        const uint32_t* xl32 = reinterpret_cast<const uint32_t*>(xl);
        const uint32_t* wh32 = reinterpret_cast<const uint32_t*>(wts_h);
        const uint32_t* wl32 = reinterpret_cast<const uint32_t*>(wts_l);

        #pragma unroll
        for (int kk = 0; kk < 2; kk++) {
            uint32_t ah[2][4], al[2][4];
            #pragma unroll
            for (int mt = 0; mt < 2; mt++) {
                int base = (wm * 32 + mt * 16 + g) * XPW + kk * 8 + tg;
                ah[mt][0] = xh32[base];
                ah[mt][1] = xh32[base + 8 * XPW];
                ah[mt][2] = xh32[base + 4];
                ah[mt][3] = xh32[base + 8 * XPW + 4];
                al[mt][0] = xl32[base];
                al[mt][1] = xl32[base + 8 * XPW];
                al[mt][2] = xl32[base + 4];
                al[mt][3] = xl32[base + 8 * XPW + 4];
            }
            #pragma unroll
            for (int nt = 0; nt < 4; nt++) {
                int bb = (wn * 32 + nt * 8 + g) * XPW + kk * 8 + tg;
                uint32_t bh0 = wh32[bb], bh1 = wh32[bb + 4];
                uint32_t bl0 = wl32[bb], bl1 = wl32[bb + 4];
                #pragma unroll
                for (int mt = 0; mt < 2; mt++) {
                    mma16(acc[mt][nt], ah[mt][0], ah[mt][1], ah[mt][2], ah[mt][3], bh0, bh1);
                    mma16(acc[mt][nt], ah[mt][0], ah[mt][1], ah[mt][2], ah[mt][3], bl0, bl1);
                    mma16(acc[mt][nt], al[mt][0], al[mt][1], al[mt][2], al[mt][3], bh0, bh1);
                }
            }
        }
        __syncthreads();
    }

    if (which < 2) {
        uint16_t* oh = which ? g_kh : g_qh;
        uint16_t* ol = which ? g_kl : g_ql;
        #pragma unroll
        for (int mt = 0; mt < 2; mt++)
        #pragma unroll
        for (int nt = 0; nt < 4; nt++) {
            int m   = m0 + wm * 32 + mt * 16 + g;
            int col = wn * 32 + nt * 8 + 2 * tg;
            uint32_t h, l;
            hilo2(acc[mt][nt].x, acc[mt][nt].y, h, l);
            reinterpret_cast<uint32_t*>(oh)[((size_t)m * HEAD + col) >> 1] = h;
            reinterpret_cast<uint32_t*>(ol)[((size_t)m * HEAD + col) >> 1] = l;
            hilo2(acc[mt][nt].z, acc[mt][nt].w, h, l);
            reinterpret_cast<uint32_t*>(oh)[((size_t)(m + 8) * HEAD + col) >> 1] = h;
            reinterpret_cast<uint32_t*>(ol)[((size_t)(m + 8) * HEAD + col) >> 1] = l;
        }
    } else {
        #pragma unroll
        for (int mt = 0; mt < 2; mt++)
        #pragma unroll
        for (int nt = 0; nt < 4; nt++) {
            int m   = m0 + wm * 32 + mt * 16 + g;
            int col = wn * 32 + nt * 8 + 2 * tg;
            *reinterpret_cast<float2*>(&g_v[(size_t)m * HEAD + col]) =
                make_float2(acc[mt][nt].x, acc[mt][nt].y);
            *reinterpret_cast<float2*>(&g_v[(size_t)(m + 8) * HEAD + col]) =
                make_float2(acc[mt][nt].z, acc[mt][nt].w);
        }
    }
}

// ---------------------------------------------------------------------------
// vtrans: g_v [row][head] fp32 -> V^T [b][head][seq] bf16 hi/lo. grid(32,8).
// ---------------------------------------------------------------------------
__global__ __launch_bounds__(256) void vtrans_kernel()
{
    const int tile = blockIdx.x, b = blockIdx.y;
    __shared__ float sv[64][68];
    const int t = threadIdx.x;
    const int r = t >> 2, c16 = (t & 3) * 16;
    #pragma unroll
    for (int rep = 0; rep < 4; rep++) {
        float4 v = *reinterpret_cast<const float4*>(
            &g_v[((size_t)(b * SEQ + tile * 64 + r)) * HEAD + c16 + rep * 4]);
        sv[r][c16 + rep * 4 + 0] = v.x; sv[r][c16 + rep * 4 + 1] = v.y;
        sv[r][c16 + rep * 4 + 2] = v.z; sv[r][c16 + rep * 4 + 3] = v.w;
    }
    __syncthreads();
    uint32_t hp[8], lp[8];
    #pragma unroll
    for (int i = 0; i < 8; i++)
        hilo2(sv[c16 + 2 * i][r], sv[c16 + 2 * i + 1][r], hp[i], lp[i]);
    size_t off = ((size_t)(b * HEAD + r)) * SEQ + tile * 64 + c16;
    *reinterpret_cast<uint4*>(&g_vth[off    ]) = make_uint4(hp[0], hp[1], hp[2], hp[3]);
    *reinterpret_cast<uint4*>(&g_vth[off + 8]) = make_uint4(hp[4], hp[5], hp[6], hp[7]);
    *reinterpret_cast<uint4*>(&g_vtl[off    ]) = make_uint4(lp[0], lp[1], lp[2], lp[3]);
    *reinterpret_cast<uint4*>(&g_vtl[off + 8]) = make_uint4(lp[4], lp[5], lp[6], lp[7]);
}

// ---------------------------------------------------------------------------
// attn: causal flash attention, bf16 3-term, cp.async double buffering.
// grid (32, 8), 128 thr (4 warps). tile = 31 - bx (longest first).
// smem: qh,ql,ph,pl + 2 x (kh,kl,vh,vl), each 64x72 bf16 = 9216 B.
// ---------------------------------------------------------------------------
#define APE 72
#define APW 36
#define APB (64 * APE * 2)               // 9216 bytes per tile
#define ATTN_SMEM (12 * APB)             // 110592 bytes

__device__ __forceinline__ void stage_kv(char* smbuf,
    const uint16_t* __restrict__ gkh, const uint16_t* __restrict__ gkl,
    const uint16_t* __restrict__ gvh, const uint16_t* __restrict__ gvl,
    int j, int tid)
{
    #pragma unroll
    for (int i = 0; i < 4; i++) {
        int u = tid + i * 128;
        int r = u >> 3, c8 = (u & 7) * 8;
        uint32_t d = (uint32_t)__cvta_generic_to_shared(smbuf + (r * APE + c8) * 2);
        size_t koff = (size_t)(j * 64 + r) * HEAD + c8;
        size_t voff = (size_t)r * SEQ + j * 64 + c8;
        cp16(d,           gkh + koff);
        cp16(d + APB,     gkl + koff);
        cp16(d + 2 * APB, gvh + voff);
        cp16(d + 3 * APB, gvl + voff);
    }
    cp_commit();
}

__global__ __launch_bounds__(128) void attn_kernel(float* __restrict__ out)
{
    extern __shared__ char sm[];
    const int bx = blockIdx.x, b = blockIdx.y;
    const int tile = 31 - bx;
    const int tid = threadIdx.x;
    const int warp = tid >> 5, lane = tid & 31;
    const int g = lane >> 2, tg = lane & 3;
    const int qr = warp * 16;

    uint16_t* qh = reinterpret_cast<uint16_t*>(sm);
    uint16_t* ql = reinterpret_cast<uint16_t*>(sm + APB);
    uint16_t* ph = reinterpret_cast<uint16_t*>(sm + 2 * APB);
    uint16_t* pl = reinterpret_cast<uint16_t*>(sm + 3 * APB);

    const uint16_t* __restrict__ gqh = g_qh + (size_t)b * SEQ * HEAD;
    const uint16_t* __restrict__ gql = g_ql + (size_t)b * SEQ * HEAD;
    const uint16_t* __restrict__ gkh = g_kh + (size_t)b * SEQ * HEAD;
    const uint16_t* __restrict__ gkl = g_kl + (size_t)b * SEQ * HEAD;
    const uint16_t* __restrict__ gvh = g_vth + (size_t)b * HEAD * SEQ;
    const uint16_t* __restrict__ gvl = g_vtl + (size_t)b * HEAD * SEQ;

    // prefetch chunk 0 (and 1) into the double buffers
    stage_kv(sm + 4 * APB, gkh, gkl, gvh, gvl, 0, tid);
    if (tile >= 1) stage_kv(sm + 8 * APB, gkh, gkl, gvh, gvl, 1, tid);

    // load Q tile (regular copies; covered by the first syncthreads)
    #pragma unroll
    for (int i = 0; i < 4; i++) {
        int u = tid + i * 128;
        int r = u >> 3, c8 = (u & 7) * 8;
        *reinterpret_cast<uint4*>(&qh[r * APE + c8]) =
            *reinterpret_cast<const uint4*>(&gqh[(size_t)(tile * 64 + r) * HEAD + c8]);
        *reinterpret_cast<uint4*>(&ql[r * APE + c8]) =
            *reinterpret_cast<const uint4*>(&gql[(size_t)(tile * 64 + r) * HEAD + c8]);
    }

    const uint32_t* qh32 = reinterpret_cast<const uint32_t*>(qh);
    const uint32_t* ql32 = reinterpret_cast<const uint32_t*>(ql);
    uint32_t* ph32 = reinterpret_cast<uint32_t*>(ph);
    uint32_t* pl32 = reinterpret_cast<uint32_t*>(pl);

    const float SC = 0.125f;
    float mx0 = -CUDART_INF_F, mx1 = -CUDART_INF_F;
    float l0 = 0.f, l1 = 0.f;
    float4 o[8] = {};

    for (int j = 0; j <= tile; j++) {
        if (j == tile) cp_wait<0>(); else cp_wait<1>();
        __syncthreads();

        char* buf = sm + (4 + (j & 1) * 4) * APB;
        const uint32_t* kh32 = reinterpret_cast<const uint32_t*>(buf);
        const uint32_t* kl32 = reinterpret_cast<const uint32_t*>(buf + APB);
        const uint32_t* vh32 = reinterpret_cast<const uint32_t*>(buf + 2 * APB);
        const uint32_t* vl32 = reinterpret_cast<const uint32_t*>(buf + 3 * APB);

        // ---- S = Q K^T (bf16 3-term) ----
        float4 s[8] = {};
        #pragma unroll
        for (int kk = 0; kk < 4; kk++) {
            const int ab = (qr + g) * APW + kk * 8 + tg;
            uint32_t ah0 = qh32[ab],               ah1 = qh32[ab + 8 * APW];
            uint32_t ah2 = qh32[ab + 4],           ah3 = qh32[ab + 8 * APW + 4];
            uint32_t al0 = ql32[ab],               al1 = ql32[ab + 8 * APW];
            uint32_t al2 = ql32[ab + 4],           al3 = ql32[ab + 8 * APW + 4];
            #pragma unroll
            for (int nt = 0; nt < 8; nt++) {
                const int bb = (nt * 8 + g) * APW + kk * 8 + tg;
                uint32_t bh0 = kh32[bb], bh1 = kh32[bb + 4];
                uint32_t bl0 = kl32[bb], bl1 = kl32[bb + 4];
                mma16(s[nt], ah0, ah1, ah2, ah3, bh0, bh1);
                mma16(s[nt], ah0, ah1, ah2, ah3, bl0, bl1);
                mma16(s[nt], al0, al1, al2, al3, bh0, bh1);
            }
        }

        // ---- scale + causal mask ----
        if (j == tile) {
            const int rg0 = tile * 64 + qr + g;
            const int rg1 = rg0 + 8;
            #pragma unroll
            for (int nt = 0; nt < 8; nt++) {
                const int cg = j * 64 + nt * 8 + 2 * tg;
                s[nt].x = (cg     > rg0) ? -CUDART_INF_F : s[nt].x * SC;
                s[nt].y = (cg + 1 > rg0) ? -CUDART_INF_F : s[nt].y * SC;
                s[nt].z = (cg     > rg1) ? -CUDART_INF_F : s[nt].z * SC;
                s[nt].w = (cg + 1 > rg1) ? -CUDART_INF_F : s[nt].w * SC;
            }
        } else {
            #pragma unroll
            for (int nt = 0; nt < 8; nt++) {
                s[nt].x *= SC; s[nt].y *= SC; s[nt].z *= SC; s[nt].w *= SC;
            }
        }

        // ---- online softmax (rows qr+g, qr+g+8) ----
        float rm0 = -CUDART_INF_F, rm1 = -CUDART_INF_F;
        #pragma unroll
        for (int nt = 0; nt < 8; nt++) {
            rm0 = fmaxf(rm0, fmaxf(s[nt].x, s[nt].y));
            rm1 = fmaxf(rm1, fmaxf(s[nt].z, s[nt].w));
        }
        rm0 = fmaxf(rm0, __shfl_xor_sync(0xffffffffu, rm0, 1));
        rm0 = fmaxf(rm0, __shfl_xor_sync(0xffffffffu, rm0, 2));
        rm1 = fmaxf(rm1, __shfl_xor_sync(0xffffffffu, rm1, 1));
        rm1 = fmaxf(rm1, __shfl_xor_sync(0xffffffffu, rm1, 2));
        const float nm0 = fmaxf(mx0, rm0);
        const float nm1 = fmaxf(mx1, rm1);
        const float a0 = __expf(mx0 - nm0);
        const float a1 = __expf(mx1 - nm1);

        float rs0 = 0.f, rs1 = 0.f;
        #pragma unroll
        for (int nt = 0; nt < 8; nt++) {
            float px = __expf(s[nt].x - nm0);
            float py = __expf(s[nt].y - nm0);
            float pz = __expf(s[nt].z - nm1);
            float pw = __expf(s[nt].w - nm1);
            rs0 += px + py;
            rs1 += pz + pw;
            uint32_t h, l;
            hilo2(px, py, h, l);
            ph32[(qr + g) * APW + nt * 4 + tg] = h;
            pl32[(qr + g) * APW + nt * 4 + tg] = l;
            hilo2(pz, pw, h, l);
            ph32[(qr + g + 8) * APW + nt * 4 + tg] = h;
            pl32[(qr + g + 8) * APW + nt * 4 + tg] = l;
        }
        rs0 += __shfl_xor_sync(0xffffffffu, rs0, 1);
        rs0 += __shfl_xor_sync(0xffffffffu, rs0, 2);
        rs1 += __shfl_xor_sync(0xffffffffu, rs1, 1);
        rs1 += __shfl_xor_sync(0xffffffffu, rs1, 2);
        l0 = l0 * a0 + rs0;
        l1 = l1 * a1 + rs1;
        mx0 = nm0; mx1 = nm1;
        #pragma unroll
        for (int nt = 0; nt < 8; nt++) {
            o[nt].x *= a0; o[nt].y *= a0;
            o[nt].z *= a1; o[nt].w *= a1;
        }
        __syncwarp();   // ph/pl are warp-local (rows qr..qr+15)

        // ---- O += P V (bf16 3-term, B = V^T tiles) ----
        #pragma unroll
        for (int kk = 0; kk < 4; kk++) {
            const int ab = (qr + g) * APW + kk * 8 + tg;
            uint32_t pa0 = ph32[ab],     pa1 = ph32[ab + 8 * APW];
            uint32_t pa2 = ph32[ab + 4], pa3 = ph32[ab + 8 * APW + 4];
            uint32_t pb0 = pl32[ab],     pb1 = pl32[ab + 8 * APW];
            uint32_t pb2 = pl32[ab + 4], pb3 = pl32[ab + 8 * APW + 4];
            #pragma unroll
            for (int nt = 0; nt < 8; nt++) {
                const int bb = (nt * 8 + g) * APW + kk * 8 + tg;
                uint32_t vh0 = vh32[bb], vh1 = vh32[bb + 4];
                uint32_t vl0 = vl32[bb], vl1 = vl32[bb + 4];
                mma16(o[nt], pa0, pa1, pa2, pa3, vh0, vh1);
                mma16(o[nt], pa0, pa1, pa2, pa3, vl0, vl1);
                mma16(o[nt], pb0, pb1, pb2, pb3, vh0, vh1);
            }
        }
        __syncthreads();   // all warps done with buffer (j&1) before restage
        if (j + 2 <= tile)
            stage_kv(sm + (4 + (j & 1) * 4) * APB, gkh, gkl, gvh, gvl, j + 2, tid);
    }

    // normalize and write
    const float inv0 = __frcp_rn(l0);
    const float inv1 = __frcp_rn(l1);
    #pragma unroll
    for (int nt = 0; nt < 8; nt++) {
        int col = nt * 8 + 2 * tg;
        *reinterpret_cast<float2*>(
            &out[((size_t)b * SEQ + tile * 64 + qr + g    ) * HEAD + col]) =
            make_float2(o[nt].x * inv0, o[nt].y * inv0);
        *reinterpret_cast<float2*>(
            &out[((size_t)b * SEQ + tile * 64 + qr + g + 8) * HEAD + col]) =
            make_float2(o[nt].z * inv1, o[nt].w * inv1);
    }
}

// ---------------------------------------------------------------------------
extern "C" void kernel_launch(void* const* d_in, const int* in_sizes, int n_in,
                              void* d_out, int out_size)
{
    const float* x  = (const float*)d_in[0];
    const float* Wq = (const float*)d_in[1];
    const float* Wk = (const float*)d_in[2];
    const float* Wv = (const float*)d_in[3];
    float* out = (float*)d_out;

    (void)in_sizes; (void)n_in; (void)out_size;

    cudaFuncSetAttribute(attn_kernel,
                         cudaFuncAttributeMaxDynamicSharedMemorySize, ATTN_SMEM);

    wprep_kernel<<<dim3(16, 3), 256>>>(Wq, Wk, Wv);
    proj_kernel<<<dim3(3, 128), 256>>>(x);
    vtrans_kernel<<<dim3(32, 8), 256>>>();
    attn_kernel<<<dim3(32, 8), 128, ATTN_SMEM>>>(out);
}

// round 5
// speedup vs baseline: 2.5139x; 1.0179x over previous
#include <cuda_runtime.h>
#include <cuda_bf16.h>
#include <math_constants.h>
#include <cstdint>

#define N_EMBED 1024
#define HEAD    64
#define BATCH   8
#define SEQ     2048
#define MROWS   (BATCH * SEQ)   // 16384

// ---------------------------------------------------------------------------
// Global scratch
// ---------------------------------------------------------------------------
__device__ uint16_t g_xh[MROWS * N_EMBED], g_xl[MROWS * N_EMBED];  // x bf16 hi/lo
__device__ uint16_t g_qh[MROWS * HEAD], g_ql[MROWS * HEAD];        // Q hi/lo [row][head]
__device__ uint16_t g_kh[MROWS * HEAD], g_kl[MROWS * HEAD];        // K hi/lo [row][head]
__device__ uint16_t g_vth[MROWS * HEAD], g_vtl[MROWS * HEAD];      // V^T hi/lo [b][head][seq]
__device__ float    g_v[MROWS * HEAD];                             // V fp32
__device__ uint16_t g_wth[3 * HEAD * N_EMBED], g_wtl[3 * HEAD * N_EMBED]; // W^T [which][n][k]

// ---------------------------------------------------------------------------
// helpers
// ---------------------------------------------------------------------------
__device__ __forceinline__ uint32_t packbf(float lo, float hi) {
    uint32_t r;
    asm("cvt.rn.bf16x2.f32 %0, %1, %2;" : "=r"(r) : "f"(hi), "f"(lo));
    return r;
}
__device__ __forceinline__ void hilo2(float x0, float x1, uint32_t& h, uint32_t& l) {
    h = packbf(x0, x1);
    float r0 = x0 - __uint_as_float(h << 16);
    float r1 = x1 - __uint_as_float(h & 0xFFFF0000u);
    l = packbf(r0, r1);
}
__device__ __forceinline__ void mma16(float4& c,
                                      uint32_t a0, uint32_t a1, uint32_t a2, uint32_t a3,
                                      uint32_t b0, uint32_t b1) {
    asm volatile(
        "mma.sync.aligned.m16n8k16.row.col.f32.bf16.bf16.f32 "
        "{%0,%1,%2,%3}, {%4,%5,%6,%7}, {%8,%9}, {%0,%1,%2,%3};"
        : "+f"(c.x), "+f"(c.y), "+f"(c.z), "+f"(c.w)
        : "r"(a0), "r"(a1), "r"(a2), "r"(a3), "r"(b0), "r"(b1));
}
__device__ __forceinline__ void cp16(uint32_t dst, const void* src) {
    asm volatile("cp.async.cg.shared.global [%0], [%1], 16;" :: "r"(dst), "l"(src));
}
__device__ __forceinline__ void cp_commit() {
    asm volatile("cp.async.commit_group;");
}
template <int N>
__device__ __forceinline__ void cp_wait() {
    asm volatile("cp.async.wait_group %0;" :: "n"(N));
}

// ---------------------------------------------------------------------------
// xprep: x fp32 -> bf16 hi/lo. grid 8192 x 256, 8 elts/thread.
// ---------------------------------------------------------------------------
__global__ __launch_bounds__(256) void xprep_kernel(const float* __restrict__ x)
{
    size_t i = ((size_t)blockIdx.x * 256 + threadIdx.x) * 8;
    float4 v0 = *reinterpret_cast<const float4*>(x + i);
    float4 v1 = *reinterpret_cast<const float4*>(x + i + 4);
    uint32_t h0, l0, h1, l1, h2, l2, h3, l3;
    hilo2(v0.x, v0.y, h0, l0);
    hilo2(v0.z, v0.w, h1, l1);
    hilo2(v1.x, v1.y, h2, l2);
    hilo2(v1.z, v1.w, h3, l3);
    *reinterpret_cast<uint4*>(&g_xh[i]) = make_uint4(h0, h1, h2, h3);
    *reinterpret_cast<uint4*>(&g_xl[i]) = make_uint4(l0, l1, l2, l3);
}

// ---------------------------------------------------------------------------
// wprep: W [k][n] fp32 -> W^T [n][k] bf16 hi/lo.  grid (16, 3), 256 thr.
// ---------------------------------------------------------------------------
__global__ __launch_bounds__(256) void wprep_kernel(
    const float* __restrict__ Wq, const float* __restrict__ Wk,
    const float* __restrict__ Wv)
{
    const int which = blockIdx.y;
    const float* __restrict__ W = (which == 0) ? Wq : (which == 1) ? Wk : Wv;
    const int k0 = blockIdx.x * 64;

    __shared__ float sw[64][68];
    const int t = threadIdx.x;
    const int r = t >> 2, c16 = (t & 3) * 16;
    #pragma unroll
    for (int rep = 0; rep < 4; rep++) {
        float4 v = *reinterpret_cast<const float4*>(
            &W[(size_t)(k0 + r) * HEAD + c16 + rep * 4]);
        sw[r][c16 + rep * 4 + 0] = v.x; sw[r][c16 + rep * 4 + 1] = v.y;
        sw[r][c16 + rep * 4 + 2] = v.z; sw[r][c16 + rep * 4 + 3] = v.w;
    }
    __syncthreads();
    uint32_t hp[8], lp[8];
    #pragma unroll
    for (int i = 0; i < 8; i++)
        hilo2(sw[c16 + 2 * i][r], sw[c16 + 2 * i + 1][r], hp[i], lp[i]);
    size_t off = ((size_t)(which * HEAD + r)) * N_EMBED + k0 + c16;
    *reinterpret_cast<uint4*>(&g_wth[off    ]) = make_uint4(hp[0], hp[1], hp[2], hp[3]);
    *reinterpret_cast<uint4*>(&g_wth[off + 8]) = make_uint4(hp[4], hp[5], hp[6], hp[7]);
    *reinterpret_cast<uint4*>(&g_wtl[off    ]) = make_uint4(lp[0], lp[1], lp[2], lp[3]);
    *reinterpret_cast<uint4*>(&g_wtl[off + 8]) = make_uint4(lp[4], lp[5], lp[6], lp[7]);
}

// ---------------------------------------------------------------------------
// proj: bf16 hi/lo 3-term GEMM, cp.async double-buffered, no conversion.
// grid (3, 128): which, m-tile of 128 rows. 256 thr (8 warps: wm 0..3 x wn 0..1).
// Warp tile 32x32. K-chunk 32 (2 x k16).
// ---------------------------------------------------------------------------
#define PW 20                              // words per 32-elt row (pad 8 elts)
// dynamic smem word offsets
#define P_XH(b) ((b) * 2560)               // 128 rows * PW
#define P_XL(b) (5120 + (b) * 2560)
#define P_WH(b) (10240 + (b) * 1280)       // 64 rows * PW
#define P_WL(b) (12800 + (b) * 1280)
#define PROJ_SMEM_WORDS 15360              // 61440 bytes

__device__ __forceinline__ void proj_stage(uint32_t* smw, int which, int m0,
                                           int ch, int tid)
{
    const int buf = ch & 1;
    const int kc0 = ch * 32;
    // x: 128 rows x (hi,lo) x 4 quarters = 1024 cp16
    #pragma unroll
    for (int i = 0; i < 4; i++) {
        int u = tid + i * 256;
        int row = u >> 3, rem = u & 7;
        int arr = rem >> 2, q = rem & 3;
        const uint16_t* src = (arr ? g_xl : g_xh) +
                              (size_t)(m0 + row) * N_EMBED + kc0 + q * 8;
        uint32_t d = (uint32_t)__cvta_generic_to_shared(
            smw + (arr ? P_XL(buf) : P_XH(buf)) + row * PW + q * 4);
        cp16(d, src);
    }
    // W: 64 rows x (hi,lo) x 4 quarters = 512 cp16
    #pragma unroll
    for (int i = 0; i < 2; i++) {
        int u = tid + i * 256;
        int row = u >> 3, rem = u & 7;
        int arr = rem >> 2, q = rem & 3;
        const uint16_t* src = (arr ? g_wtl : g_wth) +
                              (size_t)(which * HEAD + row) * N_EMBED + kc0 + q * 8;
        uint32_t d = (uint32_t)__cvta_generic_to_shared(
            smw + (arr ? P_WL(buf) : P_WH(buf)) + row * PW + q * 4);
        cp16(d, src);
    }
    cp_commit();
}

__global__ __launch_bounds__(256) void proj_kernel()
{
    extern __shared__ uint32_t smw[];
    const int which = blockIdx.x;
    const int m0 = blockIdx.y * 128;
    const int t = threadIdx.x;
    const int warp = t >> 5, lane = t & 31;
    const int g = lane >> 2, tg = lane & 3;
    const int wm = warp >> 1, wn = warp & 1;

    float4 acc[2][4] = {};

    proj_stage(smw, which, m0, 0, t);
    proj_stage(smw, which, m0, 1, t);

    for (int ch = 0; ch < 32; ch++) {
        if (ch == 31) cp_wait<0>(); else cp_wait<1>();
        __syncthreads();
        const int buf = ch & 1;
        const uint32_t* xh32 = smw + P_XH(buf);
        const uint32_t* xl32 = smw + P_XL(buf);
        const uint32_t* wh32 = smw + P_WH(buf);
        const uint32_t* wl32 = smw + P_WL(buf);

        #pragma unroll
        for (int kk = 0; kk < 2; kk++) {
            uint32_t ah[2][4], al[2][4];
            #pragma unroll
            for (int mt = 0; mt < 2; mt++) {
                int base = (wm * 32 + mt * 16 + g) * PW + kk * 8 + tg;
                ah[mt][0] = xh32[base];
                ah[mt][1] = xh32[base + 8 * PW];
                ah[mt][2] = xh32[base + 4];
                ah[mt][3] = xh32[base + 8 * PW + 4];
                al[mt][0] = xl32[base];
                al[mt][1] = xl32[base + 8 * PW];
                al[mt][2] = xl32[base + 4];
                al[mt][3] = xl32[base + 8 * PW + 4];
            }
            #pragma unroll
            for (int nt = 0; nt < 4; nt++) {
                int bb = (wn * 32 + nt * 8 + g) * PW + kk * 8 + tg;
                uint32_t bh0 = wh32[bb], bh1 = wh32[bb + 4];
                uint32_t bl0 = wl32[bb], bl1 = wl32[bb + 4];
                #pragma unroll
                for (int mt = 0; mt < 2; mt++) {
                    mma16(acc[mt][nt], ah[mt][0], ah[mt][1], ah[mt][2], ah[mt][3], bh0, bh1);
                    mma16(acc[mt][nt], ah[mt][0], ah[mt][1], ah[mt][2], ah[mt][3], bl0, bl1);
                    mma16(acc[mt][nt], al[mt][0], al[mt][1], al[mt][2], al[mt][3], bh0, bh1);
                }
            }
        }
        __syncthreads();
        if (ch + 2 < 32) proj_stage(smw, which, m0, ch + 2, t);
    }

    if (which < 2) {
        uint16_t* oh = which ? g_kh : g_qh;
        uint16_t* ol = which ? g_kl : g_ql;
        #pragma unroll
        for (int mt = 0; mt < 2; mt++)
        #pragma unroll
        for (int nt = 0; nt < 4; nt++) {
            int m   = m0 + wm * 32 + mt * 16 + g;
            int col = wn * 32 + nt * 8 + 2 * tg;
            uint32_t h, l;
            hilo2(acc[mt][nt].x, acc[mt][nt].y, h, l);
            reinterpret_cast<uint32_t*>(oh)[((size_t)m * HEAD + col) >> 1] = h;
            reinterpret_cast<uint32_t*>(ol)[((size_t)m * HEAD + col) >> 1] = l;
            hilo2(acc[mt][nt].z, acc[mt][nt].w, h, l);
            reinterpret_cast<uint32_t*>(oh)[((size_t)(m + 8) * HEAD + col) >> 1] = h;
            reinterpret_cast<uint32_t*>(ol)[((size_t)(m + 8) * HEAD + col) >> 1] = l;
        }
    } else {
        #pragma unroll
        for (int mt = 0; mt < 2; mt++)
        #pragma unroll
        for (int nt = 0; nt < 4; nt++) {
            int m   = m0 + wm * 32 + mt * 16 + g;
            int col = wn * 32 + nt * 8 + 2 * tg;
            *reinterpret_cast<float2*>(&g_v[(size_t)m * HEAD + col]) =
                make_float2(acc[mt][nt].x, acc[mt][nt].y);
            *reinterpret_cast<float2*>(&g_v[(size_t)(m + 8) * HEAD + col]) =
                make_float2(acc[mt][nt].z, acc[mt][nt].w);
        }
    }
}

// ---------------------------------------------------------------------------
// vtrans: g_v [row][head] fp32 -> V^T [b][head][seq] bf16 hi/lo. grid(32,8).
// ---------------------------------------------------------------------------
__global__ __launch_bounds__(256) void vtrans_kernel()
{
    const int tile = blockIdx.x, b = blockIdx.y;
    __shared__ float sv[64][68];
    const int t = threadIdx.x;
    const int r = t >> 2, c16 = (t & 3) * 16;
    #pragma unroll
    for (int rep = 0; rep < 4; rep++) {
        float4 v = *reinterpret_cast<const float4*>(
            &g_v[((size_t)(b * SEQ + tile * 64 + r)) * HEAD + c16 + rep * 4]);
        sv[r][c16 + rep * 4 + 0] = v.x; sv[r][c16 + rep * 4 + 1] = v.y;
        sv[r][c16 + rep * 4 + 2] = v.z; sv[r][c16 + rep * 4 + 3] = v.w;
    }
    __syncthreads();
    uint32_t hp[8], lp[8];
    #pragma unroll
    for (int i = 0; i < 8; i++)
        hilo2(sv[c16 + 2 * i][r], sv[c16 + 2 * i + 1][r], hp[i], lp[i]);
    size_t off = ((size_t)(b * HEAD + r)) * SEQ + tile * 64 + c16;
    *reinterpret_cast<uint4*>(&g_vth[off    ]) = make_uint4(hp[0], hp[1], hp[2], hp[3]);
    *reinterpret_cast<uint4*>(&g_vth[off + 8]) = make_uint4(hp[4], hp[5], hp[6], hp[7]);
    *reinterpret_cast<uint4*>(&g_vtl[off    ]) = make_uint4(lp[0], lp[1], lp[2], lp[3]);
    *reinterpret_cast<uint4*>(&g_vtl[off + 8]) = make_uint4(lp[4], lp[5], lp[6], lp[7]);
}

// ---------------------------------------------------------------------------
// attn: causal flash attention, bf16 3-term, cp.async double buffering,
// P kept in registers (S C-fragment == PV A-fragment layout).
// grid (32, 8), 128 thr (4 warps). tile = 31 - bx.
// smem: qh,ql + 2 x (kh,kl,vh,vl) @ 64x72 bf16 each = 92160 B -> 2 CTA/SM.
// ---------------------------------------------------------------------------
#define APE 72
#define APW 36
#define APB (64 * APE * 2)               // 9216 bytes per tile
#define ATTN_SMEM (10 * APB)             // 92160 bytes

__device__ __forceinline__ void stage_kv(char* smbuf,
    const uint16_t* __restrict__ gkh, const uint16_t* __restrict__ gkl,
    const uint16_t* __restrict__ gvh, const uint16_t* __restrict__ gvl,
    int j, int tid)
{
    #pragma unroll
    for (int i = 0; i < 4; i++) {
        int u = tid + i * 128;
        int r = u >> 3, c8 = (u & 7) * 8;
        uint32_t d = (uint32_t)__cvta_generic_to_shared(smbuf + (r * APE + c8) * 2);
        size_t koff = (size_t)(j * 64 + r) * HEAD + c8;
        size_t voff = (size_t)r * SEQ + j * 64 + c8;
        cp16(d,           gkh + koff);
        cp16(d + APB,     gkl + koff);
        cp16(d + 2 * APB, gvh + voff);
        cp16(d + 3 * APB, gvl + voff);
    }
    cp_commit();
}

__global__ __launch_bounds__(128) void attn_kernel(float* __restrict__ out)
{
    extern __shared__ char sm[];
    const int bx = blockIdx.x, b = blockIdx.y;
    const int tile = 31 - bx;
    const int tid = threadIdx.x;
    const int warp = tid >> 5, lane = tid & 31;
    const int g = lane >> 2, tg = lane & 3;
    const int qr = warp * 16;

    uint16_t* qh = reinterpret_cast<uint16_t*>(sm);
    uint16_t* ql = reinterpret_cast<uint16_t*>(sm + APB);

    const uint16_t* __restrict__ gqh = g_qh + (size_t)b * SEQ * HEAD;
    const uint16_t* __restrict__ gql = g_ql + (size_t)b * SEQ * HEAD;
    const uint16_t* __restrict__ gkh = g_kh + (size_t)b * SEQ * HEAD;
    const uint16_t* __restrict__ gkl = g_kl + (size_t)b * SEQ * HEAD;
    const uint16_t* __restrict__ gvh = g_vth + (size_t)b * HEAD * SEQ;
    const uint16_t* __restrict__ gvl = g_vtl + (size_t)b * HEAD * SEQ;

    stage_kv(sm + 2 * APB, gkh, gkl, gvh, gvl, 0, tid);
    if (tile >= 1) stage_kv(sm + 6 * APB, gkh, gkl, gvh, gvl, 1, tid);

    // load Q tile (regular loads; covered by the loop's first syncthreads)
    #pragma unroll
    for (int i = 0; i < 4; i++) {
        int u = tid + i * 128;
        int r = u >> 3, c8 = (u & 7) * 8;
        *reinterpret_cast<uint4*>(&qh[r * APE + c8]) =
            *reinterpret_cast<const uint4*>(&gqh[(size_t)(tile * 64 + r) * HEAD + c8]);
        *reinterpret_cast<uint4*>(&ql[r * APE + c8]) =
            *reinterpret_cast<const uint4*>(&gql[(size_t)(tile * 64 + r) * HEAD + c8]);
    }

    const uint32_t* qh32 = reinterpret_cast<const uint32_t*>(qh);
    const uint32_t* ql32 = reinterpret_cast<const uint32_t*>(ql);

    const float SC = 0.125f;
    float mx0 = -CUDART_INF_F, mx1 = -CUDART_INF_F;
    float l0 = 0.f, l1 = 0.f;
    float4 o[8] = {};

    for (int j = 0; j <= tile; j++) {
        if (j == tile) cp_wait<0>(); else cp_wait<1>();
        __syncthreads();

        char* buf = sm + (2 + (j & 1) * 4) * APB;
        const uint32_t* kh32 = reinterpret_cast<const uint32_t*>(buf);
        const uint32_t* kl32 = reinterpret_cast<const uint32_t*>(buf + APB);
        const uint32_t* vh32 = reinterpret_cast<const uint32_t*>(buf + 2 * APB);
        const uint32_t* vl32 = reinterpret_cast<const uint32_t*>(buf + 3 * APB);

        // ---- S = Q K^T (bf16 3-term) ----
        float4 s[8] = {};
        #pragma unroll
        for (int kk = 0; kk < 4; kk++) {
            const int ab = (qr + g) * APW + kk * 8 + tg;
            uint32_t ah0 = qh32[ab],     ah1 = qh32[ab + 8 * APW];
            uint32_t ah2 = qh32[ab + 4], ah3 = qh32[ab + 8 * APW + 4];
            uint32_t al0 = ql32[ab],     al1 = ql32[ab + 8 * APW];
            uint32_t al2 = ql32[ab + 4], al3 = ql32[ab + 8 * APW + 4];
            #pragma unroll
            for (int nt = 0; nt < 8; nt++) {
                const int bb = (nt * 8 + g) * APW + kk * 8 + tg;
                uint32_t bh0 = kh32[bb], bh1 = kh32[bb + 4];
                uint32_t bl0 = kl32[bb], bl1 = kl32[bb + 4];
                mma16(s[nt], ah0, ah1, ah2, ah3, bh0, bh1);
                mma16(s[nt], ah0, ah1, ah2, ah3, bl0, bl1);
                mma16(s[nt], al0, al1, al2, al3, bh0, bh1);
            }
        }

        // ---- scale + causal mask ----
        if (j == tile) {
            const int rg0 = tile * 64 + qr + g;
            const int rg1 = rg0 + 8;
            #pragma unroll
            for (int nt = 0; nt < 8; nt++) {
                const int cg = j * 64 + nt * 8 + 2 * tg;
                s[nt].x = (cg     > rg0) ? -CUDART_INF_F : s[nt].x * SC;
                s[nt].y = (cg + 1 > rg0) ? -CUDART_INF_F : s[nt].y * SC;
                s[nt].z = (cg     > rg1) ? -CUDART_INF_F : s[nt].z * SC;
                s[nt].w = (cg + 1 > rg1) ? -CUDART_INF_F : s[nt].w * SC;
            }
        } else {
            #pragma unroll
            for (int nt = 0; nt < 8; nt++) {
                s[nt].x *= SC; s[nt].y *= SC; s[nt].z *= SC; s[nt].w *= SC;
            }
        }

        // ---- online softmax (rows qr+g, qr+g+8) ----
        float rm0 = -CUDART_INF_F, rm1 = -CUDART_INF_F;
        #pragma unroll
        for (int nt = 0; nt < 8; nt++) {
            rm0 = fmaxf(rm0, fmaxf(s[nt].x, s[nt].y));
            rm1 = fmaxf(rm1, fmaxf(s[nt].z, s[nt].w));
        }
        rm0 = fmaxf(rm0, __shfl_xor_sync(0xffffffffu, rm0, 1));
        rm0 = fmaxf(rm0, __shfl_xor_sync(0xffffffffu, rm0, 2));
        rm1 = fmaxf(rm1, __shfl_xor_sync(0xffffffffu, rm1, 1));
        rm1 = fmaxf(rm1, __shfl_xor_sync(0xffffffffu, rm1, 2));
        const float nm0 = fmaxf(mx0, rm0);
        const float nm1 = fmaxf(mx1, rm1);
        const float a0 = __expf(mx0 - nm0);
        const float a1 = __expf(mx1 - nm1);

        // P packed directly into PV A-fragments (hi/lo), no smem round-trip
        uint32_t pah[8], pal[8], pbh[8], pbl[8];
        float rs0 = 0.f, rs1 = 0.f;
        #pragma unroll
        for (int nt = 0; nt < 8; nt++) {
            float px = __expf(s[nt].x - nm0);
            float py = __expf(s[nt].y - nm0);
            float pz = __expf(s[nt].z - nm1);
            float pw = __expf(s[nt].w - nm1);
            rs0 += px + py;
            rs1 += pz + pw;
            hilo2(px, py, pah[nt], pal[nt]);   // row g
            hilo2(pz, pw, pbh[nt], pbl[nt]);   // row g+8
        }
        rs0 += __shfl_xor_sync(0xffffffffu, rs0, 1);
        rs0 += __shfl_xor_sync(0xffffffffu, rs0, 2);
        rs1 += __shfl_xor_sync(0xffffffffu, rs1, 1);
        rs1 += __shfl_xor_sync(0xffffffffu, rs1, 2);
        l0 = l0 * a0 + rs0;
        l1 = l1 * a1 + rs1;
        mx0 = nm0; mx1 = nm1;
        #pragma unroll
        for (int nt = 0; nt < 8; nt++) {
            o[nt].x *= a0; o[nt].y *= a0;
            o[nt].z *= a1; o[nt].w *= a1;
        }

        // ---- O += P V (bf16 3-term, B = V^T tiles) ----
        #pragma unroll
        for (int kk = 0; kk < 4; kk++) {
            uint32_t a0h = pah[2 * kk],     a1h = pbh[2 * kk];
            uint32_t a2h = pah[2 * kk + 1], a3h = pbh[2 * kk + 1];
            uint32_t a0l = pal[2 * kk],     a1l = pbl[2 * kk];
            uint32_t a2l = pal[2 * kk + 1], a3l = pbl[2 * kk + 1];
            #pragma unroll
            for (int nt = 0; nt < 8; nt++) {
                const int bb = (nt * 8 + g) * APW + kk * 8 + tg;
                uint32_t vh0 = vh32[bb], vh1 = vh32[bb + 4];
                uint32_t vl0 = vl32[bb], vl1 = vl32[bb + 4];
                mma16(o[nt], a0h, a1h, a2h, a3h, vh0, vh1);
                mma16(o[nt], a0h, a1h, a2h, a3h, vl0, vl1);
                mma16(o[nt], a0l, a1l, a2l, a3l, vh0, vh1);
            }
        }
        __syncthreads();   // all warps done with buffer (j&1) before restage
        if (j + 2 <= tile)
            stage_kv(sm + (2 + (j & 1) * 4) * APB, gkh, gkl, gvh, gvl, j + 2, tid);
    }

    const float inv0 = __frcp_rn(l0);
    const float inv1 = __frcp_rn(l1);
    #pragma unroll
    for (int nt = 0; nt < 8; nt++) {
        int col = nt * 8 + 2 * tg;
        *reinterpret_cast<float2*>(
            &out[((size_t)b * SEQ + tile * 64 + qr + g    ) * HEAD + col]) =
            make_float2(o[nt].x * inv0, o[nt].y * inv0);
        *reinterpret_cast<float2*>(
            &out[((size_t)b * SEQ + tile * 64 + qr + g + 8) * HEAD + col]) =
            make_float2(o[nt].z * inv1, o[nt].w * inv1);
    }
}

// ---------------------------------------------------------------------------
extern "C" void kernel_launch(void* const* d_in, const int* in_sizes, int n_in,
                              void* d_out, int out_size)
{
    const float* x  = (const float*)d_in[0];
    const float* Wq = (const float*)d_in[1];
    const float* Wk = (const float*)d_in[2];
    const float* Wv = (const float*)d_in[3];
    float* out = (float*)d_out;

    (void)in_sizes; (void)n_in; (void)out_size;

    cudaFuncSetAttribute(proj_kernel,
                         cudaFuncAttributeMaxDynamicSharedMemorySize,
                         PROJ_SMEM_WORDS * (int)sizeof(uint32_t));
    cudaFuncSetAttribute(attn_kernel,
                         cudaFuncAttributeMaxDynamicSharedMemorySize, ATTN_SMEM);

    xprep_kernel<<<8192, 256>>>(x);
    wprep_kernel<<<dim3(16, 3), 256>>>(Wq, Wk, Wv);
    proj_kernel<<<dim3(3, 128), 256,
                  PROJ_SMEM_WORDS * (int)sizeof(uint32_t)>>>();
    vtrans_kernel<<<dim3(32, 8), 256>>>();
    attn_kernel<<<dim3(32, 8), 128, ATTN_SMEM>>>(out);
}

// round 6
// speedup vs baseline: 3.4498x; 1.3723x over previous
#include <cuda_runtime.h>
#include <cuda_bf16.h>
#include <math_constants.h>
#include <cstdint>

#define N_EMBED 1024
#define HEAD    64
#define BATCH   8
#define SEQ     2048
#define MROWS   (BATCH * SEQ)   // 16384

// ---------------------------------------------------------------------------
// Global scratch
// ---------------------------------------------------------------------------
__device__ uint16_t g_qh[MROWS * HEAD], g_ql[MROWS * HEAD];        // Q hi/lo [row][head]
__device__ uint16_t g_kh[MROWS * HEAD], g_kl[MROWS * HEAD];        // K hi/lo [row][head]
__device__ uint16_t g_vth[MROWS * HEAD], g_vtl[MROWS * HEAD];      // V^T hi/lo [b][head][seq]
__device__ float    g_v[MROWS * HEAD];                             // V fp32
__device__ uint16_t g_wth[3 * HEAD * N_EMBED], g_wtl[3 * HEAD * N_EMBED]; // W^T [which][n][k]
// split-KV partials: [b][tile][slot]
__device__ float g_po[BATCH * 32 * 2 * 64 * 64];                   // 8.4 MB
__device__ float g_pm[BATCH * 32 * 2 * 64];
__device__ float g_pl[BATCH * 32 * 2 * 64];

// ---------------------------------------------------------------------------
// helpers
// ---------------------------------------------------------------------------
__device__ __forceinline__ uint32_t packbf(float lo, float hi) {
    uint32_t r;
    asm("cvt.rn.bf16x2.f32 %0, %1, %2;" : "=r"(r) : "f"(hi), "f"(lo));
    return r;
}
__device__ __forceinline__ void hilo2(float x0, float x1, uint32_t& h, uint32_t& l) {
    h = packbf(x0, x1);
    float r0 = x0 - __uint_as_float(h << 16);
    float r1 = x1 - __uint_as_float(h & 0xFFFF0000u);
    l = packbf(r0, r1);
}
__device__ __forceinline__ void mma16(float4& c,
                                      uint32_t a0, uint32_t a1, uint32_t a2, uint32_t a3,
                                      uint32_t b0, uint32_t b1) {
    asm volatile(
        "mma.sync.aligned.m16n8k16.row.col.f32.bf16.bf16.f32 "
        "{%0,%1,%2,%3}, {%4,%5,%6,%7}, {%8,%9}, {%0,%1,%2,%3};"
        : "+f"(c.x), "+f"(c.y), "+f"(c.z), "+f"(c.w)
        : "r"(a0), "r"(a1), "r"(a2), "r"(a3), "r"(b0), "r"(b1));
}
__device__ __forceinline__ void cp16(uint32_t dst, const void* src) {
    asm volatile("cp.async.cg.shared.global [%0], [%1], 16;" :: "r"(dst), "l"(src));
}
__device__ __forceinline__ void cp_commit() {
    asm volatile("cp.async.commit_group;");
}
template <int N>
__device__ __forceinline__ void cp_wait() {
    asm volatile("cp.async.wait_group %0;" :: "n"(N));
}

// ---------------------------------------------------------------------------
// wprep: W [k][n] fp32 -> W^T [n][k] bf16 hi/lo.  grid (16, 3), 256 thr.
// ---------------------------------------------------------------------------
__global__ __launch_bounds__(256) void wprep_kernel(
    const float* __restrict__ Wq, const float* __restrict__ Wk,
    const float* __restrict__ Wv)
{
    const int which = blockIdx.y;
    const float* __restrict__ W = (which == 0) ? Wq : (which == 1) ? Wk : Wv;
    const int k0 = blockIdx.x * 64;

    __shared__ float sw[64][68];
    const int t = threadIdx.x;
    const int r = t >> 2, c16 = (t & 3) * 16;
    #pragma unroll
    for (int rep = 0; rep < 4; rep++) {
        float4 v = *reinterpret_cast<const float4*>(
            &W[(size_t)(k0 + r) * HEAD + c16 + rep * 4]);
        sw[r][c16 + rep * 4 + 0] = v.x; sw[r][c16 + rep * 4 + 1] = v.y;
        sw[r][c16 + rep * 4 + 2] = v.z; sw[r][c16 + rep * 4 + 3] = v.w;
    }
    __syncthreads();
    uint32_t hp[8], lp[8];
    #pragma unroll
    for (int i = 0; i < 8; i++)
        hilo2(sw[c16 + 2 * i][r], sw[c16 + 2 * i + 1][r], hp[i], lp[i]);
    size_t off = ((size_t)(which * HEAD + r)) * N_EMBED + k0 + c16;
    *reinterpret_cast<uint4*>(&g_wth[off    ]) = make_uint4(hp[0], hp[1], hp[2], hp[3]);
    *reinterpret_cast<uint4*>(&g_wth[off + 8]) = make_uint4(hp[4], hp[5], hp[6], hp[7]);
    *reinterpret_cast<uint4*>(&g_wtl[off    ]) = make_uint4(lp[0], lp[1], lp[2], lp[3]);
    *reinterpret_cast<uint4*>(&g_wtl[off + 8]) = make_uint4(lp[4], lp[5], lp[6], lp[7]);
}

// ---------------------------------------------------------------------------
// Fused proj: one pass over x computes Q, K, V for a 128-row tile.
// grid 128, 256 thr (8 warps: wm 0..3 x wn 0..1). Warp tile 32x32 per which.
// x staged fp32 via cp.async; converted to bf16 hi/lo in the fragment loads.
// ---------------------------------------------------------------------------
#define XFP 36                              // fp32 words per 32-col row
#define PJW 20                              // bf16 words per 32-elt row (W)
#define PX(buf)              ((buf) * 4608)                      // 128*36
#define PWOFF(buf, arr, wch) (9216 + (((buf) * 2 + (arr)) * 3 + (wch)) * 1280)
#define PROJ_WORDS 24576                    // 98304 bytes

__device__ __forceinline__ void proj_stage(uint32_t* smw, const float* __restrict__ x,
                                           int m0, int ch, int tid)
{
    const int buf = ch & 1;
    const int kc0 = ch * 32;
    // x: 128 rows x 32 fp32 = 1024 x 16B
    #pragma unroll
    for (int i = 0; i < 4; i++) {
        int u = tid + i * 256;
        int row = u >> 3, q = u & 7;
        const float* src = x + (size_t)(m0 + row) * N_EMBED + kc0 + q * 4;
        uint32_t d = (uint32_t)__cvta_generic_to_shared(smw + PX(buf) + row * XFP + q * 4);
        cp16(d, src);
    }
    // W: 3 which x 64 rows x (hi,lo) x 4 x 16B = 1536
    #pragma unroll
    for (int i = 0; i < 6; i++) {
        int u = tid + i * 256;
        int wch = u >> 9, rem = u & 511;
        int row = rem >> 3, rem2 = rem & 7;
        int arr = rem2 >> 2, q = rem2 & 3;
        const uint16_t* src = (arr ? g_wtl : g_wth) +
                              (size_t)(wch * HEAD + row) * N_EMBED + kc0 + q * 8;
        uint32_t d = (uint32_t)__cvta_generic_to_shared(
            smw + PWOFF(buf, arr, wch) + row * PJW + q * 4);
        cp16(d, src);
    }
    cp_commit();
}

__global__ __launch_bounds__(256) void proj_kernel(const float* __restrict__ x)
{
    extern __shared__ uint32_t smw[];
    const int m0 = blockIdx.x * 128;
    const int t = threadIdx.x;
    const int warp = t >> 5, lane = t & 31;
    const int g = lane >> 2, tg = lane & 3;
    const int wm = warp >> 1, wn = warp & 1;

    float4 acc[3][2][4] = {};

    proj_stage(smw, x, m0, 0, t);
    proj_stage(smw, x, m0, 1, t);

    for (int ch = 0; ch < 32; ch++) {
        if (ch == 31) cp_wait<0>(); else cp_wait<1>();
        __syncthreads();
        const int buf = ch & 1;
        const float* xf = reinterpret_cast<const float*>(smw + PX(buf));

        #pragma unroll
        for (int kk = 0; kk < 2; kk++) {
            uint32_t ah[2][4], al[2][4];
            #pragma unroll
            for (int mt = 0; mt < 2; mt++) {
                const int r0 = wm * 32 + mt * 16 + g;
                const int c0 = kk * 16 + 2 * tg;
                float2 e0 = *reinterpret_cast<const float2*>(&xf[r0 * XFP + c0]);
                float2 e1 = *reinterpret_cast<const float2*>(&xf[(r0 + 8) * XFP + c0]);
                float2 e2 = *reinterpret_cast<const float2*>(&xf[r0 * XFP + c0 + 8]);
                float2 e3 = *reinterpret_cast<const float2*>(&xf[(r0 + 8) * XFP + c0 + 8]);
                hilo2(e0.x, e0.y, ah[mt][0], al[mt][0]);
                hilo2(e1.x, e1.y, ah[mt][1], al[mt][1]);
                hilo2(e2.x, e2.y, ah[mt][2], al[mt][2]);
                hilo2(e3.x, e3.y, ah[mt][3], al[mt][3]);
            }
            #pragma unroll
            for (int wch = 0; wch < 3; wch++) {
                const uint32_t* wh32 = smw + PWOFF(buf, 0, wch);
                const uint32_t* wl32 = smw + PWOFF(buf, 1, wch);
                #pragma unroll
                for (int nt = 0; nt < 4; nt++) {
                    int bb = (wn * 32 + nt * 8 + g) * PJW + kk * 8 + tg;
                    uint32_t bh0 = wh32[bb], bh1 = wh32[bb + 4];
                    uint32_t bl0 = wl32[bb], bl1 = wl32[bb + 4];
                    #pragma unroll
                    for (int mt = 0; mt < 2; mt++) {
                        mma16(acc[wch][mt][nt], ah[mt][0], ah[mt][1], ah[mt][2], ah[mt][3], bh0, bh1);
                        mma16(acc[wch][mt][nt], ah[mt][0], ah[mt][1], ah[mt][2], ah[mt][3], bl0, bl1);
                        mma16(acc[wch][mt][nt], al[mt][0], al[mt][1], al[mt][2], al[mt][3], bh0, bh1);
                    }
                }
            }
        }
        __syncthreads();
        if (ch + 2 < 32) proj_stage(smw, x, m0, ch + 2, t);
    }

    // epilogue
    #pragma unroll
    for (int wch = 0; wch < 3; wch++) {
        if (wch < 2) {
            uint16_t* oh = wch ? g_kh : g_qh;
            uint16_t* ol = wch ? g_kl : g_ql;
            #pragma unroll
            for (int mt = 0; mt < 2; mt++)
            #pragma unroll
            for (int nt = 0; nt < 4; nt++) {
                int m   = m0 + wm * 32 + mt * 16 + g;
                int col = wn * 32 + nt * 8 + 2 * tg;
                uint32_t h, l;
                hilo2(acc[wch][mt][nt].x, acc[wch][mt][nt].y, h, l);
                reinterpret_cast<uint32_t*>(oh)[((size_t)m * HEAD + col) >> 1] = h;
                reinterpret_cast<uint32_t*>(ol)[((size_t)m * HEAD + col) >> 1] = l;
                hilo2(acc[wch][mt][nt].z, acc[wch][mt][nt].w, h, l);
                reinterpret_cast<uint32_t*>(oh)[((size_t)(m + 8) * HEAD + col) >> 1] = h;
                reinterpret_cast<uint32_t*>(ol)[((size_t)(m + 8) * HEAD + col) >> 1] = l;
            }
        } else {
            #pragma unroll
            for (int mt = 0; mt < 2; mt++)
            #pragma unroll
            for (int nt = 0; nt < 4; nt++) {
                int m   = m0 + wm * 32 + mt * 16 + g;
                int col = wn * 32 + nt * 8 + 2 * tg;
                *reinterpret_cast<float2*>(&g_v[(size_t)m * HEAD + col]) =
                    make_float2(acc[wch][mt][nt].x, acc[wch][mt][nt].y);
                *reinterpret_cast<float2*>(&g_v[(size_t)(m + 8) * HEAD + col]) =
                    make_float2(acc[wch][mt][nt].z, acc[wch][mt][nt].w);
            }
        }
    }
}

// ---------------------------------------------------------------------------
// vtrans: g_v [row][head] fp32 -> V^T [b][head][seq] bf16 hi/lo. grid(32,8).
// ---------------------------------------------------------------------------
__global__ __launch_bounds__(256) void vtrans_kernel()
{
    const int tile = blockIdx.x, b = blockIdx.y;
    __shared__ float sv[64][68];
    const int t = threadIdx.x;
    const int r = t >> 2, c16 = (t & 3) * 16;
    #pragma unroll
    for (int rep = 0; rep < 4; rep++) {
        float4 v = *reinterpret_cast<const float4*>(
            &g_v[((size_t)(b * SEQ + tile * 64 + r)) * HEAD + c16 + rep * 4]);
        sv[r][c16 + rep * 4 + 0] = v.x; sv[r][c16 + rep * 4 + 1] = v.y;
        sv[r][c16 + rep * 4 + 2] = v.z; sv[r][c16 + rep * 4 + 3] = v.w;
    }
    __syncthreads();
    uint32_t hp[8], lp[8];
    #pragma unroll
    for (int i = 0; i < 8; i++)
        hilo2(sv[c16 + 2 * i][r], sv[c16 + 2 * i + 1][r], hp[i], lp[i]);
    size_t off = ((size_t)(b * HEAD + r)) * SEQ + tile * 64 + c16;
    *reinterpret_cast<uint4*>(&g_vth[off    ]) = make_uint4(hp[0], hp[1], hp[2], hp[3]);
    *reinterpret_cast<uint4*>(&g_vth[off + 8]) = make_uint4(hp[4], hp[5], hp[6], hp[7]);
    *reinterpret_cast<uint4*>(&g_vtl[off    ]) = make_uint4(lp[0], lp[1], lp[2], lp[3]);
    *reinterpret_cast<uint4*>(&g_vtl[off + 8]) = make_uint4(lp[4], lp[5], lp[6], lp[7]);
}

// ---------------------------------------------------------------------------
// attn: split-KV causal flash attention, bf16 3-term, register P,
// cp.async double buffering, partial (m,l,O) outputs.
// grid (49, 8), 128 thr. Unit table: longest-first, max 16 chunks.
// ---------------------------------------------------------------------------
#define APE 72
#define APW 36
#define APB (64 * APE * 2)               // 9216 bytes per tile
#define ATTN_SMEM (10 * APB)             // 92160 bytes

// {tile, chunk_begin, chunk_end, slot} sorted by length desc
__constant__ uchar4 c_units[49] = {
    {31,0,16,0},{31,16,32,1},{30,0,16,0},
    {30,16,31,1},{29,0,15,0},{29,15,30,1},{28,0,15,0},{14,0,15,0},
    {28,15,29,1},{27,0,14,0},{27,14,28,1},{26,0,14,0},{13,0,14,0},
    {26,14,27,1},{25,0,13,0},{25,13,26,1},{24,0,13,0},{12,0,13,0},
    {24,13,25,1},{23,0,12,0},{23,12,24,1},{22,0,12,0},{11,0,12,0},
    {22,12,23,1},{21,0,11,0},{21,11,22,1},{20,0,11,0},{10,0,11,0},
    {20,11,21,1},{19,0,10,0},{19,10,20,1},{18,0,10,0},{9,0,10,0},
    {18,10,19,1},{17,0,9,0},{17,9,18,1},{16,0,9,0},{8,0,9,0},
    {16,9,17,1},{15,0,8,0},{15,8,16,1},{7,0,8,0},
    {6,0,7,0},{5,0,6,0},{4,0,5,0},{3,0,4,0},{2,0,3,0},{1,0,2,0},{0,0,1,0}
};

__device__ __forceinline__ void stage_kv(char* smbuf,
    const uint16_t* __restrict__ gkh, const uint16_t* __restrict__ gkl,
    const uint16_t* __restrict__ gvh, const uint16_t* __restrict__ gvl,
    int j, int tid)
{
    #pragma unroll
    for (int i = 0; i < 4; i++) {
        int u = tid + i * 128;
        int r = u >> 3, c8 = (u & 7) * 8;
        uint32_t d = (uint32_t)__cvta_generic_to_shared(smbuf + (r * APE + c8) * 2);
        size_t koff = (size_t)(j * 64 + r) * HEAD + c8;
        size_t voff = (size_t)r * SEQ + j * 64 + c8;
        cp16(d,           gkh + koff);
        cp16(d + APB,     gkl + koff);
        cp16(d + 2 * APB, gvh + voff);
        cp16(d + 3 * APB, gvl + voff);
    }
    cp_commit();
}

__global__ __launch_bounds__(128) void attn_kernel()
{
    extern __shared__ char sm[];
    const uchar4 u = c_units[blockIdx.x];
    const int tile = u.x, c0 = u.y, c1 = u.z, slot = u.w;
    const int b = blockIdx.y;
    const int tid = threadIdx.x;
    const int warp = tid >> 5, lane = tid & 31;
    const int g = lane >> 2, tg = lane & 3;
    const int qr = warp * 16;

    uint16_t* qh = reinterpret_cast<uint16_t*>(sm);
    uint16_t* ql = reinterpret_cast<uint16_t*>(sm + APB);

    const uint16_t* __restrict__ gqh = g_qh + (size_t)b * SEQ * HEAD;
    const uint16_t* __restrict__ gql = g_ql + (size_t)b * SEQ * HEAD;
    const uint16_t* __restrict__ gkh = g_kh + (size_t)b * SEQ * HEAD;
    const uint16_t* __restrict__ gkl = g_kl + (size_t)b * SEQ * HEAD;
    const uint16_t* __restrict__ gvh = g_vth + (size_t)b * HEAD * SEQ;
    const uint16_t* __restrict__ gvl = g_vtl + (size_t)b * HEAD * SEQ;

    stage_kv(sm + (2 + (c0 & 1) * 4) * APB, gkh, gkl, gvh, gvl, c0, tid);
    if (c0 + 1 < c1)
        stage_kv(sm + (2 + ((c0 + 1) & 1) * 4) * APB, gkh, gkl, gvh, gvl, c0 + 1, tid);

    #pragma unroll
    for (int i = 0; i < 4; i++) {
        int uu = tid + i * 128;
        int r = uu >> 3, c8 = (uu & 7) * 8;
        *reinterpret_cast<uint4*>(&qh[r * APE + c8]) =
            *reinterpret_cast<const uint4*>(&gqh[(size_t)(tile * 64 + r) * HEAD + c8]);
        *reinterpret_cast<uint4*>(&ql[r * APE + c8]) =
            *reinterpret_cast<const uint4*>(&gql[(size_t)(tile * 64 + r) * HEAD + c8]);
    }

    const uint32_t* qh32 = reinterpret_cast<const uint32_t*>(qh);
    const uint32_t* ql32 = reinterpret_cast<const uint32_t*>(ql);

    const float SC = 0.125f;
    float mx0 = -CUDART_INF_F, mx1 = -CUDART_INF_F;
    float l0 = 0.f, l1 = 0.f;
    float4 o[8] = {};

    for (int j = c0; j < c1; j++) {
        if (j == c1 - 1) cp_wait<0>(); else cp_wait<1>();
        __syncthreads();

        char* buf = sm + (2 + (j & 1) * 4) * APB;
        const uint32_t* kh32 = reinterpret_cast<const uint32_t*>(buf);
        const uint32_t* kl32 = reinterpret_cast<const uint32_t*>(buf + APB);
        const uint32_t* vh32 = reinterpret_cast<const uint32_t*>(buf + 2 * APB);
        const uint32_t* vl32 = reinterpret_cast<const uint32_t*>(buf + 3 * APB);

        // ---- S = Q K^T ----
        float4 s[8] = {};
        #pragma unroll
        for (int kk = 0; kk < 4; kk++) {
            const int ab = (qr + g) * APW + kk * 8 + tg;
            uint32_t ah0 = qh32[ab],     ah1 = qh32[ab + 8 * APW];
            uint32_t ah2 = qh32[ab + 4], ah3 = qh32[ab + 8 * APW + 4];
            uint32_t al0 = ql32[ab],     al1 = ql32[ab + 8 * APW];
            uint32_t al2 = ql32[ab + 4], al3 = ql32[ab + 8 * APW + 4];
            #pragma unroll
            for (int nt = 0; nt < 8; nt++) {
                const int bb = (nt * 8 + g) * APW + kk * 8 + tg;
                uint32_t bh0 = kh32[bb], bh1 = kh32[bb + 4];
                uint32_t bl0 = kl32[bb], bl1 = kl32[bb + 4];
                mma16(s[nt], ah0, ah1, ah2, ah3, bh0, bh1);
                mma16(s[nt], ah0, ah1, ah2, ah3, bl0, bl1);
                mma16(s[nt], al0, al1, al2, al3, bh0, bh1);
            }
        }

        // ---- scale + causal mask (diagonal chunk only) ----
        if (j == tile) {
            const int rg0 = tile * 64 + qr + g;
            const int rg1 = rg0 + 8;
            #pragma unroll
            for (int nt = 0; nt < 8; nt++) {
                const int cg = j * 64 + nt * 8 + 2 * tg;
                s[nt].x = (cg     > rg0) ? -CUDART_INF_F : s[nt].x * SC;
                s[nt].y = (cg + 1 > rg0) ? -CUDART_INF_F : s[nt].y * SC;
                s[nt].z = (cg     > rg1) ? -CUDART_INF_F : s[nt].z * SC;
                s[nt].w = (cg + 1 > rg1) ? -CUDART_INF_F : s[nt].w * SC;
            }
        } else {
            #pragma unroll
            for (int nt = 0; nt < 8; nt++) {
                s[nt].x *= SC; s[nt].y *= SC; s[nt].z *= SC; s[nt].w *= SC;
            }
        }

        // ---- online softmax ----
        float rm0 = -CUDART_INF_F, rm1 = -CUDART_INF_F;
        #pragma unroll
        for (int nt = 0; nt < 8; nt++) {
            rm0 = fmaxf(rm0, fmaxf(s[nt].x, s[nt].y));
            rm1 = fmaxf(rm1, fmaxf(s[nt].z, s[nt].w));
        }
        rm0 = fmaxf(rm0, __shfl_xor_sync(0xffffffffu, rm0, 1));
        rm0 = fmaxf(rm0, __shfl_xor_sync(0xffffffffu, rm0, 2));
        rm1 = fmaxf(rm1, __shfl_xor_sync(0xffffffffu, rm1, 1));
        rm1 = fmaxf(rm1, __shfl_xor_sync(0xffffffffu, rm1, 2));
        const float nm0 = fmaxf(mx0, rm0);
        const float nm1 = fmaxf(mx1, rm1);
        const float a0 = __expf(mx0 - nm0);
        const float a1 = __expf(mx1 - nm1);

        uint32_t pah[8], pal[8], pbh[8], pbl[8];
        float rs0 = 0.f, rs1 = 0.f;
        #pragma unroll
        for (int nt = 0; nt < 8; nt++) {
            float px = __expf(s[nt].x - nm0);
            float py = __expf(s[nt].y - nm0);
            float pz = __expf(s[nt].z - nm1);
            float pw = __expf(s[nt].w - nm1);
            rs0 += px + py;
            rs1 += pz + pw;
            hilo2(px, py, pah[nt], pal[nt]);
            hilo2(pz, pw, pbh[nt], pbl[nt]);
        }
        rs0 += __shfl_xor_sync(0xffffffffu, rs0, 1);
        rs0 += __shfl_xor_sync(0xffffffffu, rs0, 2);
        rs1 += __shfl_xor_sync(0xffffffffu, rs1, 1);
        rs1 += __shfl_xor_sync(0xffffffffu, rs1, 2);
        l0 = l0 * a0 + rs0;
        l1 = l1 * a1 + rs1;
        mx0 = nm0; mx1 = nm1;
        #pragma unroll
        for (int nt = 0; nt < 8; nt++) {
            o[nt].x *= a0; o[nt].y *= a0;
            o[nt].z *= a1; o[nt].w *= a1;
        }

        // ---- O += P V ----
        #pragma unroll
        for (int kk = 0; kk < 4; kk++) {
            uint32_t a0h = pah[2 * kk],     a1h = pbh[2 * kk];
            uint32_t a2h = pah[2 * kk + 1], a3h = pbh[2 * kk + 1];
            uint32_t a0l = pal[2 * kk],     a1l = pbl[2 * kk];
            uint32_t a2l = pal[2 * kk + 1], a3l = pbl[2 * kk + 1];
            #pragma unroll
            for (int nt = 0; nt < 8; nt++) {
                const int bb = (nt * 8 + g) * APW + kk * 8 + tg;
                uint32_t vh0 = vh32[bb], vh1 = vh32[bb + 4];
                uint32_t vl0 = vl32[bb], vl1 = vl32[bb + 4];
                mma16(o[nt], a0h, a1h, a2h, a3h, vh0, vh1);
                mma16(o[nt], a0h, a1h, a2h, a3h, vl0, vl1);
                mma16(o[nt], a0l, a1l, a2l, a3l, vh0, vh1);
            }
        }
        __syncthreads();
        if (j + 2 < c1)
            stage_kv(sm + (2 + (j & 1) * 4) * APB, gkh, gkl, gvh, gvl, j + 2, tid);
    }

    // write partials (unnormalized O, running m and l)
    const int sidx = ((b * 32 + tile) * 2 + slot);
    float* po = g_po + (size_t)sidx * 64 * 64;
    #pragma unroll
    for (int nt = 0; nt < 8; nt++) {
        int col = nt * 8 + 2 * tg;
        *reinterpret_cast<float2*>(&po[(qr + g    ) * 64 + col]) = make_float2(o[nt].x, o[nt].y);
        *reinterpret_cast<float2*>(&po[(qr + g + 8) * 64 + col]) = make_float2(o[nt].z, o[nt].w);
    }
    if (tg == 0) {
        g_pm[sidx * 64 + qr + g    ] = mx0;
        g_pm[sidx * 64 + qr + g + 8] = mx1;
        g_pl[sidx * 64 + qr + g    ] = l0;
        g_pl[sidx * 64 + qr + g + 8] = l1;
    }
}

// ---------------------------------------------------------------------------
// combine: merge split-KV partials, normalize, write out. grid (32,8), 64 thr.
// ---------------------------------------------------------------------------
__global__ __launch_bounds__(64) void combine_kernel(float* __restrict__ out)
{
    const int tile = blockIdx.x, b = blockIdx.y;
    const int r = threadIdx.x;
    const int s0 = (b * 32 + tile) * 2;
    const float4* O1 = reinterpret_cast<const float4*>(g_po + ((size_t)s0 * 64 + r) * 64);
    float4* dst = reinterpret_cast<float4*>(out + ((size_t)b * SEQ + tile * 64 + r) * HEAD);

    if (tile < 15) {
        const float inv = __frcp_rn(g_pl[s0 * 64 + r]);
        #pragma unroll
        for (int i = 0; i < 16; i++) {
            float4 v = O1[i];
            dst[i] = make_float4(v.x * inv, v.y * inv, v.z * inv, v.w * inv);
        }
    } else {
        const float4* O2 = reinterpret_cast<const float4*>(g_po + ((size_t)(s0 + 1) * 64 + r) * 64);
        const float m1 = g_pm[s0 * 64 + r],     m2 = g_pm[(s0 + 1) * 64 + r];
        const float L1 = g_pl[s0 * 64 + r],     L2 = g_pl[(s0 + 1) * 64 + r];
        const float m  = fmaxf(m1, m2);
        const float w1 = __expf(m1 - m), w2 = __expf(m2 - m);
        const float invL = __frcp_rn(w1 * L1 + w2 * L2);
        const float a = w1 * invL, bb = w2 * invL;
        #pragma unroll
        for (int i = 0; i < 16; i++) {
            float4 v1 = O1[i], v2 = O2[i];
            dst[i] = make_float4(v1.x * a + v2.x * bb, v1.y * a + v2.y * bb,
                                 v1.z * a + v2.z * bb, v1.w * a + v2.w * bb);
        }
    }
}

// ---------------------------------------------------------------------------
extern "C" void kernel_launch(void* const* d_in, const int* in_sizes, int n_in,
                              void* d_out, int out_size)
{
    const float* x  = (const float*)d_in[0];
    const float* Wq = (const float*)d_in[1];
    const float* Wk = (const float*)d_in[2];
    const float* Wv = (const float*)d_in[3];
    float* out = (float*)d_out;

    (void)in_sizes; (void)n_in; (void)out_size;

    cudaFuncSetAttribute(proj_kernel,
                         cudaFuncAttributeMaxDynamicSharedMemorySize,
                         PROJ_WORDS * (int)sizeof(uint32_t));
    cudaFuncSetAttribute(attn_kernel,
                         cudaFuncAttributeMaxDynamicSharedMemorySize, ATTN_SMEM);

    wprep_kernel<<<dim3(16, 3), 256>>>(Wq, Wk, Wv);
    proj_kernel<<<128, 256, PROJ_WORDS * (int)sizeof(uint32_t)>>>(x);
    vtrans_kernel<<<dim3(32, 8), 256>>>();
    attn_kernel<<<dim3(49, 8), 128, ATTN_SMEM>>>();
    combine_kernel<<<dim3(32, 8), 64>>>(out);
}

// round 7
// speedup vs baseline: 3.6769x; 1.0658x over previous
#include <cuda_runtime.h>
#include <cuda_bf16.h>
#include <math_constants.h>
#include <cstdint>

#define N_EMBED 1024
#define HEAD    64
#define BATCH   8
#define SEQ     2048
#define MROWS   (BATCH * SEQ)   // 16384

// ---------------------------------------------------------------------------
// Global scratch
// ---------------------------------------------------------------------------
__device__ uint16_t g_qh[MROWS * HEAD], g_ql[MROWS * HEAD];        // Q hi/lo [row][head]
__device__ uint16_t g_kh[MROWS * HEAD], g_kl[MROWS * HEAD];        // K hi/lo [row][head]
__device__ uint16_t g_vth[MROWS * HEAD], g_vtl[MROWS * HEAD];      // V^T hi/lo [b][head][seq]
__device__ uint16_t g_wth[3 * HEAD * N_EMBED], g_wtl[3 * HEAD * N_EMBED]; // W^T [which][n][k]
// split-KV partials: [b][tile][slot]
__device__ float g_po[BATCH * 32 * 2 * 64 * 64];
__device__ float g_pm[BATCH * 32 * 2 * 64];
__device__ float g_pl[BATCH * 32 * 2 * 64];

// ---------------------------------------------------------------------------
// helpers
// ---------------------------------------------------------------------------
__device__ __forceinline__ uint32_t packbf(float lo, float hi) {
    uint32_t r;
    asm("cvt.rn.bf16x2.f32 %0, %1, %2;" : "=r"(r) : "f"(hi), "f"(lo));
    return r;
}
__device__ __forceinline__ void hilo2(float x0, float x1, uint32_t& h, uint32_t& l) {
    h = packbf(x0, x1);
    float r0 = x0 - __uint_as_float(h << 16);
    float r1 = x1 - __uint_as_float(h & 0xFFFF0000u);
    l = packbf(r0, r1);
}
__device__ __forceinline__ void mma16(float4& c,
                                      uint32_t a0, uint32_t a1, uint32_t a2, uint32_t a3,
                                      uint32_t b0, uint32_t b1) {
    asm volatile(
        "mma.sync.aligned.m16n8k16.row.col.f32.bf16.bf16.f32 "
        "{%0,%1,%2,%3}, {%4,%5,%6,%7}, {%8,%9}, {%0,%1,%2,%3};"
        : "+f"(c.x), "+f"(c.y), "+f"(c.z), "+f"(c.w)
        : "r"(a0), "r"(a1), "r"(a2), "r"(a3), "r"(b0), "r"(b1));
}
__device__ __forceinline__ void ldsm4(uint32_t& r0, uint32_t& r1, uint32_t& r2,
                                      uint32_t& r3, uint32_t addr) {
    asm volatile("ldmatrix.sync.aligned.m8n8.x4.shared.b16 {%0,%1,%2,%3}, [%4];"
                 : "=r"(r0), "=r"(r1), "=r"(r2), "=r"(r3) : "r"(addr));
}
__device__ __forceinline__ void cp16(uint32_t dst, const void* src) {
    asm volatile("cp.async.cg.shared.global [%0], [%1], 16;" :: "r"(dst), "l"(src));
}
__device__ __forceinline__ void cp_commit() {
    asm volatile("cp.async.commit_group;");
}
template <int N>
__device__ __forceinline__ void cp_wait() {
    asm volatile("cp.async.wait_group %0;" :: "n"(N));
}

// ---------------------------------------------------------------------------
// wprep: W [k][n] fp32 -> W^T [n][k] bf16 hi/lo.  grid (16, 3), 256 thr.
// ---------------------------------------------------------------------------
__global__ __launch_bounds__(256) void wprep_kernel(
    const float* __restrict__ Wq, const float* __restrict__ Wk,
    const float* __restrict__ Wv)
{
    const int which = blockIdx.y;
    const float* __restrict__ W = (which == 0) ? Wq : (which == 1) ? Wk : Wv;
    const int k0 = blockIdx.x * 64;

    __shared__ float sw[64][68];
    const int t = threadIdx.x;
    const int r = t >> 2, c16 = (t & 3) * 16;
    #pragma unroll
    for (int rep = 0; rep < 4; rep++) {
        float4 v = *reinterpret_cast<const float4*>(
            &W[(size_t)(k0 + r) * HEAD + c16 + rep * 4]);
        sw[r][c16 + rep * 4 + 0] = v.x; sw[r][c16 + rep * 4 + 1] = v.y;
        sw[r][c16 + rep * 4 + 2] = v.z; sw[r][c16 + rep * 4 + 3] = v.w;
    }
    __syncthreads();
    uint32_t hp[8], lp[8];
    #pragma unroll
    for (int i = 0; i < 8; i++)
        hilo2(sw[c16 + 2 * i][r], sw[c16 + 2 * i + 1][r], hp[i], lp[i]);
    size_t off = ((size_t)(which * HEAD + r)) * N_EMBED + k0 + c16;
    *reinterpret_cast<uint4*>(&g_wth[off    ]) = make_uint4(hp[0], hp[1], hp[2], hp[3]);
    *reinterpret_cast<uint4*>(&g_wth[off + 8]) = make_uint4(hp[4], hp[5], hp[6], hp[7]);
    *reinterpret_cast<uint4*>(&g_wtl[off    ]) = make_uint4(lp[0], lp[1], lp[2], lp[3]);
    *reinterpret_cast<uint4*>(&g_wtl[off + 8]) = make_uint4(lp[4], lp[5], lp[6], lp[7]);
}

// ---------------------------------------------------------------------------
// Fused proj: 64-row tiles, 256 CTAs. x converted at staging, ldmatrix frags,
// W via cp.async double-buffer, V^T emitted directly (fused transpose).
// 256 thr = 8 warps: wm = warp>>1 (16-row groups), wn = warp&1 (32-col groups).
// ---------------------------------------------------------------------------
#define WP     40                       // halves pitch for 32-half rows
#define XTILE  (64 * WP * 2)            // 5120 bytes per 64-row tile
#define PBUF   (8 * XTILE)              // xh,xl,w0h,w0l,w1h,w1l,w2h,w2l
#define PROJ_SMEM (2 * PBUF)            // 81920 bytes

__device__ __forceinline__ void proj_stage_w(char* sm, int buf, int ch, int t)
{
    const int kc0 = ch * 32;
    #pragma unroll
    for (int i = 0; i < 6; i++) {
        int u = t + i * 256;
        int w = u >> 9, rem = u & 511;
        int row = rem >> 3, rem2 = rem & 7;
        int arr = rem2 >> 2, q = rem2 & 3;
        const uint16_t* src = (arr ? g_wtl : g_wth) +
                              (size_t)(w * HEAD + row) * N_EMBED + kc0 + q * 8;
        uint32_t d = (uint32_t)__cvta_generic_to_shared(
            sm + buf * PBUF + (2 + w * 2 + arr) * XTILE + (row * WP + q * 8) * 2);
        cp16(d, src);
    }
    cp_commit();
}

__global__ __launch_bounds__(256) void proj_kernel(const float* __restrict__ x)
{
    extern __shared__ char sm[];
    const int m0 = blockIdx.x * 64;
    const int t = threadIdx.x;
    const int warp = t >> 5, lane = t & 31;
    const int g = lane >> 2, tg = lane & 3;
    const int wm = warp >> 1, wn = warp & 1;
    const int l8 = lane & 7, mi = lane >> 3;

    const uint32_t smu = (uint32_t)__cvta_generic_to_shared(sm);
    // ldmatrix base addresses (per-lane)
    const uint32_t aX = smu + ((wm * 16 + ((mi & 1) << 3) + l8) * WP + ((mi >> 1) << 3)) * 2;
    const uint32_t bW = smu + 2 * XTILE +
                        ((wn * 32 + ((mi >> 1) << 3) + l8) * WP + ((mi & 1) << 3)) * 2;

    // x staging: thread -> row t>>2, cols (t&3)*8 .. +7
    const int xrow = t >> 2, xc8 = (t & 3) * 8;

    float4 acc[3][4] = {};
    float4 xr0, xr1;

    // prologue: stage chunk 0, prefetch chunk 1
    {
        const float* src = x + (size_t)(m0 + xrow) * N_EMBED + xc8;
        xr0 = *reinterpret_cast<const float4*>(src);
        xr1 = *reinterpret_cast<const float4*>(src + 4);
        uint32_t h0, l0, h1, l1, h2, l2, h3, l3;
        hilo2(xr0.x, xr0.y, h0, l0); hilo2(xr0.z, xr0.w, h1, l1);
        hilo2(xr1.x, xr1.y, h2, l2); hilo2(xr1.z, xr1.w, h3, l3);
        *reinterpret_cast<uint4*>(sm + (xrow * WP + xc8) * 2) = make_uint4(h0, h1, h2, h3);
        *reinterpret_cast<uint4*>(sm + XTILE + (xrow * WP + xc8) * 2) = make_uint4(l0, l1, l2, l3);
        proj_stage_w(sm, 0, 0, t);
        // prefetch chunk 1
        xr0 = *reinterpret_cast<const float4*>(src + 32);
        xr1 = *reinterpret_cast<const float4*>(src + 36);
    }

    for (int ch = 0; ch < 32; ch++) {
        cp_wait<0>();
        __syncthreads();
        const int buf = ch & 1;

        if (ch + 1 < 32) {
            const int nbuf = (ch + 1) & 1;
            uint32_t h0, l0, h1, l1, h2, l2, h3, l3;
            hilo2(xr0.x, xr0.y, h0, l0); hilo2(xr0.z, xr0.w, h1, l1);
            hilo2(xr1.x, xr1.y, h2, l2); hilo2(xr1.z, xr1.w, h3, l3);
            *reinterpret_cast<uint4*>(sm + nbuf * PBUF + (xrow * WP + xc8) * 2) =
                make_uint4(h0, h1, h2, h3);
            *reinterpret_cast<uint4*>(sm + nbuf * PBUF + XTILE + (xrow * WP + xc8) * 2) =
                make_uint4(l0, l1, l2, l3);
            proj_stage_w(sm, nbuf, ch + 1, t);
            if (ch + 2 < 32) {
                const float* src = x + (size_t)(m0 + xrow) * N_EMBED + (ch + 2) * 32 + xc8;
                xr0 = *reinterpret_cast<const float4*>(src);
                xr1 = *reinterpret_cast<const float4*>(src + 4);
            }
        }

        // compute on buf
        const uint32_t ax = aX + buf * PBUF;
        const uint32_t bw = bW + buf * PBUF;
        #pragma unroll
        for (int kk = 0; kk < 2; kk++) {
            uint32_t ah0, ah1, ah2, ah3, al0, al1, al2, al3;
            ldsm4(ah0, ah1, ah2, ah3, ax + kk * 32);
            ldsm4(al0, al1, al2, al3, ax + XTILE + kk * 32);
            #pragma unroll
            for (int w = 0; w < 3; w++) {
                #pragma unroll
                for (int ntp = 0; ntp < 2; ntp++) {
                    uint32_t ba = bw + w * 2 * XTILE + ntp * (16 * WP * 2) + kk * 32;
                    uint32_t bh0, bh1, bh2, bh3, bl0, bl1, bl2, bl3;
                    ldsm4(bh0, bh1, bh2, bh3, ba);
                    ldsm4(bl0, bl1, bl2, bl3, ba + XTILE);
                    mma16(acc[w][2*ntp],   ah0, ah1, ah2, ah3, bh0, bh1);
                    mma16(acc[w][2*ntp],   ah0, ah1, ah2, ah3, bl0, bl1);
                    mma16(acc[w][2*ntp],   al0, al1, al2, al3, bh0, bh1);
                    mma16(acc[w][2*ntp+1], ah0, ah1, ah2, ah3, bh2, bh3);
                    mma16(acc[w][2*ntp+1], ah0, ah1, ah2, ah3, bl2, bl3);
                    mma16(acc[w][2*ntp+1], al0, al1, al2, al3, bh2, bh3);
                }
            }
        }
        __syncthreads();
    }

    // ---- epilogue: Q, K as bf16 hi/lo ----
    #pragma unroll
    for (int w = 0; w < 2; w++) {
        uint16_t* oh = w ? g_kh : g_qh;
        uint16_t* ol = w ? g_kl : g_ql;
        #pragma unroll
        for (int nt = 0; nt < 4; nt++) {
            int m   = m0 + wm * 16 + g;
            int col = wn * 32 + nt * 8 + 2 * tg;
            uint32_t h, l;
            hilo2(acc[w][nt].x, acc[w][nt].y, h, l);
            reinterpret_cast<uint32_t*>(oh)[((size_t)m * HEAD + col) >> 1] = h;
            reinterpret_cast<uint32_t*>(ol)[((size_t)m * HEAD + col) >> 1] = l;
            hilo2(acc[w][nt].z, acc[w][nt].w, h, l);
            reinterpret_cast<uint32_t*>(oh)[((size_t)(m + 8) * HEAD + col) >> 1] = h;
            reinterpret_cast<uint32_t*>(ol)[((size_t)(m + 8) * HEAD + col) >> 1] = l;
        }
    }

    // ---- epilogue: V -> V^T bf16 hi/lo (fused transpose via smem) ----
    float* sv = reinterpret_cast<float*>(sm);   // [64][68]
    #pragma unroll
    for (int nt = 0; nt < 4; nt++) {
        int r0 = wm * 16 + g;
        int col = wn * 32 + nt * 8 + 2 * tg;
        sv[r0 * 68 + col] = acc[2][nt].x; sv[r0 * 68 + col + 1] = acc[2][nt].y;
        sv[(r0 + 8) * 68 + col] = acc[2][nt].z; sv[(r0 + 8) * 68 + col + 1] = acc[2][nt].w;
    }
    __syncthreads();
    {
        const int r = t >> 2, c16 = (t & 3) * 16;
        uint32_t hp[8], lp[8];
        #pragma unroll
        for (int i = 0; i < 8; i++)
            hilo2(sv[(c16 + 2 * i) * 68 + r], sv[(c16 + 2 * i + 1) * 68 + r], hp[i], lp[i]);
        const int b = m0 >> 11;            // batch
        const int seq0 = m0 & 2047;        // seq offset within batch
        size_t off = ((size_t)(b * HEAD + r)) * SEQ + seq0 + c16;
        *reinterpret_cast<uint4*>(&g_vth[off    ]) = make_uint4(hp[0], hp[1], hp[2], hp[3]);
        *reinterpret_cast<uint4*>(&g_vth[off + 8]) = make_uint4(hp[4], hp[5], hp[6], hp[7]);
        *reinterpret_cast<uint4*>(&g_vtl[off    ]) = make_uint4(lp[0], lp[1], lp[2], lp[3]);
        *reinterpret_cast<uint4*>(&g_vtl[off + 8]) = make_uint4(lp[4], lp[5], lp[6], lp[7]);
    }
}

// ---------------------------------------------------------------------------
// attn: split-KV causal flash attention, bf16 3-term, ldmatrix fragments,
// register P, cp.async double buffering. Full-tile units write out directly.
// grid (49, 8), 128 thr.
// ---------------------------------------------------------------------------
#define APE 72
#define APB (64 * APE * 2)               // 9216 bytes per tile
#define ATTN_SMEM (10 * APB)             // 92160 bytes

__constant__ uchar4 c_units[49] = {
    {31,0,16,0},{31,16,32,1},{30,0,16,0},
    {30,16,31,1},{29,0,15,0},{29,15,30,1},{28,0,15,0},{14,0,15,0},
    {28,15,29,1},{27,0,14,0},{27,14,28,1},{26,0,14,0},{13,0,14,0},
    {26,14,27,1},{25,0,13,0},{25,13,26,1},{24,0,13,0},{12,0,13,0},
    {24,13,25,1},{23,0,12,0},{23,12,24,1},{22,0,12,0},{11,0,12,0},
    {22,12,23,1},{21,0,11,0},{21,11,22,1},{20,0,11,0},{10,0,11,0},
    {20,11,21,1},{19,0,10,0},{19,10,20,1},{18,0,10,0},{9,0,10,0},
    {18,10,19,1},{17,0,9,0},{17,9,18,1},{16,0,9,0},{8,0,9,0},
    {16,9,17,1},{15,0,8,0},{15,8,16,1},{7,0,8,0},
    {6,0,7,0},{5,0,6,0},{4,0,5,0},{3,0,4,0},{2,0,3,0},{1,0,2,0},{0,0,1,0}
};

__device__ __forceinline__ void stage_kv(char* smbuf,
    const uint16_t* __restrict__ gkh, const uint16_t* __restrict__ gkl,
    const uint16_t* __restrict__ gvh, const uint16_t* __restrict__ gvl,
    int j, int tid)
{
    #pragma unroll
    for (int i = 0; i < 4; i++) {
        int u = tid + i * 128;
        int r = u >> 3, c8 = (u & 7) * 8;
        uint32_t d = (uint32_t)__cvta_generic_to_shared(smbuf + (r * APE + c8) * 2);
        size_t koff = (size_t)(j * 64 + r) * HEAD + c8;
        size_t voff = (size_t)r * SEQ + j * 64 + c8;
        cp16(d,           gkh + koff);
        cp16(d + APB,     gkl + koff);
        cp16(d + 2 * APB, gvh + voff);
        cp16(d + 3 * APB, gvl + voff);
    }
    cp_commit();
}

__global__ __launch_bounds__(128) void attn_kernel(float* __restrict__ out)
{
    extern __shared__ char sm[];
    const uchar4 u = c_units[blockIdx.x];
    const int tile = u.x, c0 = u.y, c1 = u.z, slot = u.w;
    const int b = blockIdx.y;
    const int tid = threadIdx.x;
    const int warp = tid >> 5, lane = tid & 31;
    const int g = lane >> 2, tg = lane & 3;
    const int qr = warp * 16;
    const int l8 = lane & 7, mi = lane >> 3;

    const uint32_t smu = (uint32_t)__cvta_generic_to_shared(sm);
    // A-frag (Q) ldmatrix address: qh tile at byte 0, ql at +APB
    const uint32_t aQ = smu + ((qr + ((mi & 1) << 3) + l8) * APE + ((mi >> 1) << 3)) * 2;
    // B-frag local offset within a tile
    const uint32_t bloc = ((((mi >> 1) << 3) + l8) * APE + ((mi & 1) << 3)) * 2;

    uint16_t* qh = reinterpret_cast<uint16_t*>(sm);
    uint16_t* ql = reinterpret_cast<uint16_t*>(sm + APB);

    const uint16_t* __restrict__ gqh = g_qh + (size_t)b * SEQ * HEAD;
    const uint16_t* __restrict__ gql = g_ql + (size_t)b * SEQ * HEAD;
    const uint16_t* __restrict__ gkh = g_kh + (size_t)b * SEQ * HEAD;
    const uint16_t* __restrict__ gkl = g_kl + (size_t)b * SEQ * HEAD;
    const uint16_t* __restrict__ gvh = g_vth + (size_t)b * HEAD * SEQ;
    const uint16_t* __restrict__ gvl = g_vtl + (size_t)b * HEAD * SEQ;

    stage_kv(sm + (2 + (c0 & 1) * 4) * APB, gkh, gkl, gvh, gvl, c0, tid);
    if (c0 + 1 < c1)
        stage_kv(sm + (2 + ((c0 + 1) & 1) * 4) * APB, gkh, gkl, gvh, gvl, c0 + 1, tid);

    #pragma unroll
    for (int i = 0; i < 4; i++) {
        int uu = tid + i * 128;
        int r = uu >> 3, c8 = (uu & 7) * 8;
        *reinterpret_cast<uint4*>(&qh[r * APE + c8]) =
            *reinterpret_cast<const uint4*>(&gqh[(size_t)(tile * 64 + r) * HEAD + c8]);
        *reinterpret_cast<uint4*>(&ql[r * APE + c8]) =
            *reinterpret_cast<const uint4*>(&gql[(size_t)(tile * 64 + r) * HEAD + c8]);
    }

    const float SC = 0.125f;
    float mx0 = -CUDART_INF_F, mx1 = -CUDART_INF_F;
    float l0 = 0.f, l1 = 0.f;
    float4 o[8] = {};

    for (int j = c0; j < c1; j++) {
        if (j == c1 - 1) cp_wait<0>(); else cp_wait<1>();
        __syncthreads();

        const uint32_t kb = smu + (2 + (j & 1) * 4) * APB + bloc;
        const uint32_t vb = kb + 2 * APB;

        // ---- S = Q K^T (bf16 3-term) ----
        float4 s[8] = {};
        #pragma unroll
        for (int kk = 0; kk < 4; kk++) {
            uint32_t ah0, ah1, ah2, ah3, al0, al1, al2, al3;
            ldsm4(ah0, ah1, ah2, ah3, aQ + kk * 32);
            ldsm4(al0, al1, al2, al3, aQ + APB + kk * 32);
            #pragma unroll
            for (int ntp = 0; ntp < 4; ntp++) {
                uint32_t ba = kb + ntp * (16 * APE * 2) + kk * 32;
                uint32_t bh0, bh1, bh2, bh3, bl0, bl1, bl2, bl3;
                ldsm4(bh0, bh1, bh2, bh3, ba);
                ldsm4(bl0, bl1, bl2, bl3, ba + APB);
                mma16(s[2*ntp],   ah0, ah1, ah2, ah3, bh0, bh1);
                mma16(s[2*ntp],   ah0, ah1, ah2, ah3, bl0, bl1);
                mma16(s[2*ntp],   al0, al1, al2, al3, bh0, bh1);
                mma16(s[2*ntp+1], ah0, ah1, ah2, ah3, bh2, bh3);
                mma16(s[2*ntp+1], ah0, ah1, ah2, ah3, bl2, bl3);
                mma16(s[2*ntp+1], al0, al1, al2, al3, bh2, bh3);
            }
        }

        // ---- scale + causal mask ----
        if (j == tile) {
            const int rg0 = tile * 64 + qr + g;
            const int rg1 = rg0 + 8;
            #pragma unroll
            for (int nt = 0; nt < 8; nt++) {
                const int cg = j * 64 + nt * 8 + 2 * tg;
                s[nt].x = (cg     > rg0) ? -CUDART_INF_F : s[nt].x * SC;
                s[nt].y = (cg + 1 > rg0) ? -CUDART_INF_F : s[nt].y * SC;
                s[nt].z = (cg     > rg1) ? -CUDART_INF_F : s[nt].z * SC;
                s[nt].w = (cg + 1 > rg1) ? -CUDART_INF_F : s[nt].w * SC;
            }
        } else {
            #pragma unroll
            for (int nt = 0; nt < 8; nt++) {
                s[nt].x *= SC; s[nt].y *= SC; s[nt].z *= SC; s[nt].w *= SC;
            }
        }

        // ---- online softmax ----
        float rm0 = -CUDART_INF_F, rm1 = -CUDART_INF_F;
        #pragma unroll
        for (int nt = 0; nt < 8; nt++) {
            rm0 = fmaxf(rm0, fmaxf(s[nt].x, s[nt].y));
            rm1 = fmaxf(rm1, fmaxf(s[nt].z, s[nt].w));
        }
        rm0 = fmaxf(rm0, __shfl_xor_sync(0xffffffffu, rm0, 1));
        rm0 = fmaxf(rm0, __shfl_xor_sync(0xffffffffu, rm0, 2));
        rm1 = fmaxf(rm1, __shfl_xor_sync(0xffffffffu, rm1, 1));
        rm1 = fmaxf(rm1, __shfl_xor_sync(0xffffffffu, rm1, 2));
        const float nm0 = fmaxf(mx0, rm0);
        const float nm1 = fmaxf(mx1, rm1);
        const float a0 = __expf(mx0 - nm0);
        const float a1 = __expf(mx1 - nm1);

        uint32_t pah[8], pal[8], pbh[8], pbl[8];
        float rs0 = 0.f, rs1 = 0.f;
        #pragma unroll
        for (int nt = 0; nt < 8; nt++) {
            float px = __expf(s[nt].x - nm0);
            float py = __expf(s[nt].y - nm0);
            float pz = __expf(s[nt].z - nm1);
            float pw = __expf(s[nt].w - nm1);
            rs0 += px + py;
            rs1 += pz + pw;
            hilo2(px, py, pah[nt], pal[nt]);
            hilo2(pz, pw, pbh[nt], pbl[nt]);
        }
        rs0 += __shfl_xor_sync(0xffffffffu, rs0, 1);
        rs0 += __shfl_xor_sync(0xffffffffu, rs0, 2);
        rs1 += __shfl_xor_sync(0xffffffffu, rs1, 1);
        rs1 += __shfl_xor_sync(0xffffffffu, rs1, 2);
        l0 = l0 * a0 + rs0;
        l1 = l1 * a1 + rs1;
        mx0 = nm0; mx1 = nm1;
        #pragma unroll
        for (int nt = 0; nt < 8; nt++) {
            o[nt].x *= a0; o[nt].y *= a0;
            o[nt].z *= a1; o[nt].w *= a1;
        }

        // ---- O += P V (bf16 3-term, B = V^T tiles) ----
        #pragma unroll
        for (int kk = 0; kk < 4; kk++) {
            uint32_t a0h = pah[2 * kk],     a1h = pbh[2 * kk];
            uint32_t a2h = pah[2 * kk + 1], a3h = pbh[2 * kk + 1];
            uint32_t a0l = pal[2 * kk],     a1l = pbl[2 * kk];
            uint32_t a2l = pal[2 * kk + 1], a3l = pbl[2 * kk + 1];
            #pragma unroll
            for (int ntp = 0; ntp < 4; ntp++) {
                uint32_t ba = vb + ntp * (16 * APE * 2) + kk * 32;
                uint32_t vh0, vh1, vh2, vh3, vl0, vl1, vl2, vl3;
                ldsm4(vh0, vh1, vh2, vh3, ba);
                ldsm4(vl0, vl1, vl2, vl3, ba + APB);
                mma16(o[2*ntp],   a0h, a1h, a2h, a3h, vh0, vh1);
                mma16(o[2*ntp],   a0h, a1h, a2h, a3h, vl0, vl1);
                mma16(o[2*ntp],   a0l, a1l, a2l, a3l, vh0, vh1);
                mma16(o[2*ntp+1], a0h, a1h, a2h, a3h, vh2, vh3);
                mma16(o[2*ntp+1], a0h, a1h, a2h, a3h, vl2, vl3);
                mma16(o[2*ntp+1], a0l, a1l, a2l, a3l, vh2, vh3);
            }
        }
        __syncthreads();
        if (j + 2 < c1)
            stage_kv(sm + (2 + (j & 1) * 4) * APB, gkh, gkl, gvh, gvl, j + 2, tid);
    }

    if (c0 == 0 && c1 == tile + 1) {
        // full tile: normalize and write output directly
        const float inv0 = __frcp_rn(l0);
        const float inv1 = __frcp_rn(l1);
        #pragma unroll
        for (int nt = 0; nt < 8; nt++) {
            int col = nt * 8 + 2 * tg;
            *reinterpret_cast<float2*>(
                &out[((size_t)b * SEQ + tile * 64 + qr + g    ) * HEAD + col]) =
                make_float2(o[nt].x * inv0, o[nt].y * inv0);
            *reinterpret_cast<float2*>(
                &out[((size_t)b * SEQ + tile * 64 + qr + g + 8) * HEAD + col]) =
                make_float2(o[nt].z * inv1, o[nt].w * inv1);
        }
    } else {
        const int sidx = ((b * 32 + tile) * 2 + slot);
        float* po = g_po + (size_t)sidx * 64 * 64;
        #pragma unroll
        for (int nt = 0; nt < 8; nt++) {
            int col = nt * 8 + 2 * tg;
            *reinterpret_cast<float2*>(&po[(qr + g    ) * 64 + col]) = make_float2(o[nt].x, o[nt].y);
            *reinterpret_cast<float2*>(&po[(qr + g + 8) * 64 + col]) = make_float2(o[nt].z, o[nt].w);
        }
        if (tg == 0) {
            g_pm[sidx * 64 + qr + g    ] = mx0;
            g_pm[sidx * 64 + qr + g + 8] = mx1;
            g_pl[sidx * 64 + qr + g    ] = l0;
            g_pl[sidx * 64 + qr + g + 8] = l1;
        }
    }
}

// ---------------------------------------------------------------------------
// combine: merge the two split-KV partials for tiles 15..31. grid (17,8).
// ---------------------------------------------------------------------------
__global__ __launch_bounds__(64) void combine_kernel(float* __restrict__ out)
{
    const int tile = blockIdx.x + 15, b = blockIdx.y;
    const int r = threadIdx.x;
    const int s0 = (b * 32 + tile) * 2;
    const float4* O1 = reinterpret_cast<const float4*>(g_po + ((size_t)s0 * 64 + r) * 64);
    const float4* O2 = reinterpret_cast<const float4*>(g_po + ((size_t)(s0 + 1) * 64 + r) * 64);
    float4* dst = reinterpret_cast<float4*>(out + ((size_t)b * SEQ + tile * 64 + r) * HEAD);

    const float m1 = g_pm[s0 * 64 + r],     m2 = g_pm[(s0 + 1) * 64 + r];
    const float L1 = g_pl[s0 * 64 + r],     L2 = g_pl[(s0 + 1) * 64 + r];
    const float m  = fmaxf(m1, m2);
    const float w1 = __expf(m1 - m), w2 = __expf(m2 - m);
    const float invL = __frcp_rn(w1 * L1 + w2 * L2);
    const float a = w1 * invL, bb = w2 * invL;
    #pragma unroll
    for (int i = 0; i < 16; i++) {
        float4 v1 = O1[i], v2 = O2[i];
        dst[i] = make_float4(v1.x * a + v2.x * bb, v1.y * a + v2.y * bb,
                             v1.z * a + v2.z * bb, v1.w * a + v2.w * bb);
    }
}

// ---------------------------------------------------------------------------
extern "C" void kernel_launch(void* const* d_in, const int* in_sizes, int n_in,
                              void* d_out, int out_size)
{
    const float* x  = (const float*)d_in[0];
    const float* Wq = (const float*)d_in[1];
    const float* Wk = (const float*)d_in[2];
    const float* Wv = (const float*)d_in[3];
    float* out = (float*)d_out;

    (void)in_sizes; (void)n_in; (void)out_size;

    cudaFuncSetAttribute(proj_kernel,
                         cudaFuncAttributeMaxDynamicSharedMemorySize, PROJ_SMEM);
    cudaFuncSetAttribute(attn_kernel,
                         cudaFuncAttributeMaxDynamicSharedMemorySize, ATTN_SMEM);

    wprep_kernel<<<dim3(16, 3), 256>>>(Wq, Wk, Wv);
    proj_kernel<<<256, 256, PROJ_SMEM>>>(x);
    attn_kernel<<<dim3(49, 8), 128, ATTN_SMEM>>>(out);
    combine_kernel<<<dim3(17, 8), 64>>>(out);
}

// round 9
// speedup vs baseline: 4.1890x; 1.1393x over previous
#include <cuda_runtime.h>
#include <cuda_fp16.h>
#include <math_constants.h>
#include <cstdint>

#define N_EMBED 1024
#define HEAD    64
#define BATCH   8
#define SEQ     2048
#define MROWS   (BATCH * SEQ)   // 16384

// ---------------------------------------------------------------------------
// Global scratch (fp16)
// ---------------------------------------------------------------------------
__device__ uint16_t g_qh[MROWS * HEAD];                            // Q fp16 [row][head]
__device__ uint16_t g_kh[MROWS * HEAD], g_kl[MROWS * HEAD];        // K hi/lo [row][head]
__device__ uint16_t g_vth[MROWS * HEAD], g_vtl[MROWS * HEAD];      // V^T hi/lo [b][head][seq]
__device__ uint16_t g_wth[3 * HEAD * N_EMBED], g_wtl[3 * HEAD * N_EMBED]; // W^T [which][n][k]
// split-KV partials
__device__ float g_po[BATCH * 32 * 2 * 64 * 64];
__device__ float g_pm[BATCH * 32 * 2 * 64];
__device__ float g_pl[BATCH * 32 * 2 * 64];

// ---------------------------------------------------------------------------
// helpers
// ---------------------------------------------------------------------------
__device__ __forceinline__ uint32_t packhf(float x0, float x1) {
    __half2 h = __floats2half2_rn(x0, x1);
    return *reinterpret_cast<uint32_t*>(&h);
}
__device__ __forceinline__ void hilo2h(float x0, float x1, uint32_t& h, uint32_t& l) {
    __half2 hv = __floats2half2_rn(x0, x1);
    h = *reinterpret_cast<uint32_t*>(&hv);
    float2 d = __half22float2(hv);
    __half2 lv = __floats2half2_rn(x0 - d.x, x1 - d.y);
    l = *reinterpret_cast<uint32_t*>(&lv);
}
__device__ __forceinline__ void mma16(float4& c,
                                      uint32_t a0, uint32_t a1, uint32_t a2, uint32_t a3,
                                      uint32_t b0, uint32_t b1) {
    asm volatile(
        "mma.sync.aligned.m16n8k16.row.col.f32.f16.f16.f32 "
        "{%0,%1,%2,%3}, {%4,%5,%6,%7}, {%8,%9}, {%0,%1,%2,%3};"
        : "+f"(c.x), "+f"(c.y), "+f"(c.z), "+f"(c.w)
        : "r"(a0), "r"(a1), "r"(a2), "r"(a3), "r"(b0), "r"(b1));
}
__device__ __forceinline__ void ldsm4(uint32_t& r0, uint32_t& r1, uint32_t& r2,
                                      uint32_t& r3, uint32_t addr) {
    asm volatile("ldmatrix.sync.aligned.m8n8.x4.shared.b16 {%0,%1,%2,%3}, [%4];"
                 : "=r"(r0), "=r"(r1), "=r"(r2), "=r"(r3) : "r"(addr));
}
__device__ __forceinline__ void cp16(uint32_t dst, const void* src) {
    asm volatile("cp.async.cg.shared.global [%0], [%1], 16;" :: "r"(dst), "l"(src));
}
__device__ __forceinline__ void cp_commit() {
    asm volatile("cp.async.commit_group;");
}
template <int N>
__device__ __forceinline__ void cp_wait() {
    asm volatile("cp.async.wait_group %0;" :: "n"(N));
}
__device__ __forceinline__ uint32_t smem_u32(const void* p) {
    return (uint32_t)__cvta_generic_to_shared(p);
}

// ---------------------------------------------------------------------------
// wprep: W [k][n] fp32 -> W^T [n][k] fp16 hi/lo.  grid (16, 3), 256 thr.
// ---------------------------------------------------------------------------
__global__ __launch_bounds__(256) void wprep_kernel(
    const float* __restrict__ Wq, const float* __restrict__ Wk,
    const float* __restrict__ Wv)
{
    const int which = blockIdx.y;
    const float* __restrict__ W = (which == 0) ? Wq : (which == 1) ? Wk : Wv;
    const int k0 = blockIdx.x * 64;

    __shared__ float sw[64][68];
    const int t = threadIdx.x;
    const int r = t >> 2, c16 = (t & 3) * 16;
    #pragma unroll
    for (int rep = 0; rep < 4; rep++) {
        float4 v = *reinterpret_cast<const float4*>(
            &W[(size_t)(k0 + r) * HEAD + c16 + rep * 4]);
        sw[r][c16 + rep * 4 + 0] = v.x; sw[r][c16 + rep * 4 + 1] = v.y;
        sw[r][c16 + rep * 4 + 2] = v.z; sw[r][c16 + rep * 4 + 3] = v.w;
    }
    __syncthreads();
    uint32_t hp[8], lp[8];
    #pragma unroll
    for (int i = 0; i < 8; i++)
        hilo2h(sw[c16 + 2 * i][r], sw[c16 + 2 * i + 1][r], hp[i], lp[i]);
    size_t off = ((size_t)(which * HEAD + r)) * N_EMBED + k0 + c16;
    *reinterpret_cast<uint4*>(&g_wth[off    ]) = make_uint4(hp[0], hp[1], hp[2], hp[3]);
    *reinterpret_cast<uint4*>(&g_wth[off + 8]) = make_uint4(hp[4], hp[5], hp[6], hp[7]);
    *reinterpret_cast<uint4*>(&g_wtl[off    ]) = make_uint4(lp[0], lp[1], lp[2], lp[3]);
    *reinterpret_cast<uint4*>(&g_wtl[off + 8]) = make_uint4(lp[4], lp[5], lp[6], lp[7]);
}

// ---------------------------------------------------------------------------
// Fused proj: 64-row tiles, 256 CTAs, fp16 3-term, ldmatrix fragments.
// ---------------------------------------------------------------------------
#define WP     40                       // halves pitch for 32-half rows
#define XTILE  (64 * WP * 2)            // 5120 bytes per 64-row tile
#define PBUF   (8 * XTILE)              // xh,xl,w0h,w0l,w1h,w1l,w2h,w2l
#define PROJ_SMEM (2 * PBUF)            // 81920 bytes

__device__ __forceinline__ void proj_stage_w(char* sm, int buf, int ch, int t)
{
    const int kc0 = ch * 32;
    #pragma unroll
    for (int i = 0; i < 6; i++) {
        int u = t + i * 256;
        int w = u >> 9, rem = u & 511;
        int row = rem >> 3, rem2 = rem & 7;
        int arr = rem2 >> 2, q = rem2 & 3;
        const uint16_t* src = (arr ? g_wtl : g_wth) +
                              (size_t)(w * HEAD + row) * N_EMBED + kc0 + q * 8;
        uint32_t d = smem_u32(sm + buf * PBUF + (2 + w * 2 + arr) * XTILE +
                              (row * WP + q * 8) * 2);
        cp16(d, src);
    }
    cp_commit();
}

__global__ __launch_bounds__(256) void proj_kernel(const float* __restrict__ x)
{
    extern __shared__ char sm[];
    const int m0 = blockIdx.x * 64;
    const int t = threadIdx.x;
    const int warp = t >> 5, lane = t & 31;
    const int g = lane >> 2, tg = lane & 3;
    const int wm = warp >> 1, wn = warp & 1;
    const int l8 = lane & 7, mi = lane >> 3;

    const uint32_t smu = smem_u32(sm);
    const uint32_t aX = smu + ((wm * 16 + ((mi & 1) << 3) + l8) * WP + ((mi >> 1) << 3)) * 2;
    const uint32_t bW = smu + 2 * XTILE +
                        ((wn * 32 + ((mi >> 1) << 3) + l8) * WP + ((mi & 1) << 3)) * 2;

    const int xrow = t >> 2, xc8 = (t & 3) * 8;

    float4 acc[3][4] = {};
    float4 xr0, xr1;

    {
        const float* src = x + (size_t)(m0 + xrow) * N_EMBED + xc8;
        xr0 = *reinterpret_cast<const float4*>(src);
        xr1 = *reinterpret_cast<const float4*>(src + 4);
        uint32_t h0, l0, h1, l1, h2, l2, h3, l3;
        hilo2h(xr0.x, xr0.y, h0, l0); hilo2h(xr0.z, xr0.w, h1, l1);
        hilo2h(xr1.x, xr1.y, h2, l2); hilo2h(xr1.z, xr1.w, h3, l3);
        *reinterpret_cast<uint4*>(sm + (xrow * WP + xc8) * 2) = make_uint4(h0, h1, h2, h3);
        *reinterpret_cast<uint4*>(sm + XTILE + (xrow * WP + xc8) * 2) = make_uint4(l0, l1, l2, l3);
        proj_stage_w(sm, 0, 0, t);
        xr0 = *reinterpret_cast<const float4*>(src + 32);
        xr1 = *reinterpret_cast<const float4*>(src + 36);
    }

    for (int ch = 0; ch < 32; ch++) {
        cp_wait<0>();
        __syncthreads();
        const int buf = ch & 1;

        if (ch + 1 < 32) {
            const int nbuf = (ch + 1) & 1;
            uint32_t h0, l0, h1, l1, h2, l2, h3, l3;
            hilo2h(xr0.x, xr0.y, h0, l0); hilo2h(xr0.z, xr0.w, h1, l1);
            hilo2h(xr1.x, xr1.y, h2, l2); hilo2h(xr1.z, xr1.w, h3, l3);
            *reinterpret_cast<uint4*>(sm + nbuf * PBUF + (xrow * WP + xc8) * 2) =
                make_uint4(h0, h1, h2, h3);
            *reinterpret_cast<uint4*>(sm + nbuf * PBUF + XTILE + (xrow * WP + xc8) * 2) =
                make_uint4(l0, l1, l2, l3);
            proj_stage_w(sm, nbuf, ch + 1, t);
            if (ch + 2 < 32) {
                const float* src = x + (size_t)(m0 + xrow) * N_EMBED + (ch + 2) * 32 + xc8;
                xr0 = *reinterpret_cast<const float4*>(src);
                xr1 = *reinterpret_cast<const float4*>(src + 4);
            }
        }

        const uint32_t ax = aX + buf * PBUF;
        const uint32_t bw = bW + buf * PBUF;
        #pragma unroll
        for (int kk = 0; kk < 2; kk++) {
            uint32_t ah0, ah1, ah2, ah3, al0, al1, al2, al3;
            ldsm4(ah0, ah1, ah2, ah3, ax + kk * 32);
            ldsm4(al0, al1, al2, al3, ax + XTILE + kk * 32);
            #pragma unroll
            for (int w = 0; w < 3; w++) {
                #pragma unroll
                for (int ntp = 0; ntp < 2; ntp++) {
                    uint32_t ba = bw + w * 2 * XTILE + ntp * (16 * WP * 2) + kk * 32;
                    uint32_t bh0, bh1, bh2, bh3, bl0, bl1, bl2, bl3;
                    ldsm4(bh0, bh1, bh2, bh3, ba);
                    ldsm4(bl0, bl1, bl2, bl3, ba + XTILE);
                    mma16(acc[w][2*ntp],   ah0, ah1, ah2, ah3, bh0, bh1);
                    mma16(acc[w][2*ntp],   ah0, ah1, ah2, ah3, bl0, bl1);
                    mma16(acc[w][2*ntp],   al0, al1, al2, al3, bh0, bh1);
                    mma16(acc[w][2*ntp+1], ah0, ah1, ah2, ah3, bh2, bh3);
                    mma16(acc[w][2*ntp+1], ah0, ah1, ah2, ah3, bl2, bl3);
                    mma16(acc[w][2*ntp+1], al0, al1, al2, al3, bh2, bh3);
                }
            }
        }
        __syncthreads();
    }

    // ---- epilogue: Q plain fp16; K fp16 hi/lo ----
    #pragma unroll
    for (int nt = 0; nt < 4; nt++) {
        int m   = m0 + wm * 16 + g;
        int col = wn * 32 + nt * 8 + 2 * tg;
        // Q
        reinterpret_cast<uint32_t*>(g_qh)[((size_t)m * HEAD + col) >> 1] =
            packhf(acc[0][nt].x, acc[0][nt].y);
        reinterpret_cast<uint32_t*>(g_qh)[((size_t)(m + 8) * HEAD + col) >> 1] =
            packhf(acc[0][nt].z, acc[0][nt].w);
        // K
        uint32_t h, l;
        hilo2h(acc[1][nt].x, acc[1][nt].y, h, l);
        reinterpret_cast<uint32_t*>(g_kh)[((size_t)m * HEAD + col) >> 1] = h;
        reinterpret_cast<uint32_t*>(g_kl)[((size_t)m * HEAD + col) >> 1] = l;
        hilo2h(acc[1][nt].z, acc[1][nt].w, h, l);
        reinterpret_cast<uint32_t*>(g_kh)[((size_t)(m + 8) * HEAD + col) >> 1] = h;
        reinterpret_cast<uint32_t*>(g_kl)[((size_t)(m + 8) * HEAD + col) >> 1] = l;
    }

    // ---- epilogue: V -> V^T fp16 hi/lo (fused transpose via smem) ----
    float* sv = reinterpret_cast<float*>(sm);   // [64][68]
    #pragma unroll
    for (int nt = 0; nt < 4; nt++) {
        int r0 = wm * 16 + g;
        int col = wn * 32 + nt * 8 + 2 * tg;
        sv[r0 * 68 + col] = acc[2][nt].x; sv[r0 * 68 + col + 1] = acc[2][nt].y;
        sv[(r0 + 8) * 68 + col] = acc[2][nt].z; sv[(r0 + 8) * 68 + col + 1] = acc[2][nt].w;
    }
    __syncthreads();
    {
        const int r = t >> 2, c16 = (t & 3) * 16;
        uint32_t hp[8], lp[8];
        #pragma unroll
        for (int i = 0; i < 8; i++)
            hilo2h(sv[(c16 + 2 * i) * 68 + r], sv[(c16 + 2 * i + 1) * 68 + r], hp[i], lp[i]);
        const int b = m0 >> 11;
        const int seq0 = m0 & 2047;
        size_t off = ((size_t)(b * HEAD + r)) * SEQ + seq0 + c16;
        *reinterpret_cast<uint4*>(&g_vth[off    ]) = make_uint4(hp[0], hp[1], hp[2], hp[3]);
        *reinterpret_cast<uint4*>(&g_vth[off + 8]) = make_uint4(hp[4], hp[5], hp[6], hp[7]);
        *reinterpret_cast<uint4*>(&g_vtl[off    ]) = make_uint4(lp[0], lp[1], lp[2], lp[3]);
        *reinterpret_cast<uint4*>(&g_vtl[off + 8]) = make_uint4(lp[4], lp[5], lp[6], lp[7]);
    }
}

// ---------------------------------------------------------------------------
// attn: split-KV causal flash attention, fp16 2-term S / 2-term PV,
// ldmatrix fragments, register P, cp.async double buffering.
// grid (49, 8), 128 thr. smem: qh + 2 x (kh,kl,vh,vl) = 9 tiles.
// ---------------------------------------------------------------------------
#define APE 72
#define APB (64 * APE * 2)
#define ATTN_SMEM (9 * APB)              // 82944 bytes

__constant__ uchar4 c_units[49] = {
    {31,0,16,0},{31,16,32,1},{30,0,16,0},
    {30,16,31,1},{29,0,15,0},{29,15,30,1},{28,0,15,0},{14,0,15,0},
    {28,15,29,1},{27,0,14,0},{27,14,28,1},{26,0,14,0},{13,0,14,0},
    {26,14,27,1},{25,0,13,0},{25,13,26,1},{24,0,13,0},{12,0,13,0},
    {24,13,25,1},{23,0,12,0},{23,12,24,1},{22,0,12,0},{11,0,12,0},
    {22,12,23,1},{21,0,11,0},{21,11,22,1},{20,0,11,0},{10,0,11,0},
    {20,11,21,1},{19,0,10,0},{19,10,20,1},{18,0,10,0},{9,0,10,0},
    {18,10,19,1},{17,0,9,0},{17,9,18,1},{16,0,9,0},{8,0,9,0},
    {16,9,17,1},{15,0,8,0},{15,8,16,1},{7,0,8,0},
    {6,0,7,0},{5,0,6,0},{4,0,5,0},{3,0,4,0},{2,0,3,0},{1,0,2,0},{0,0,1,0}
};

__device__ __forceinline__ void stage_kv(char* smbuf,
    const uint16_t* __restrict__ gkh, const uint16_t* __restrict__ gkl,
    const uint16_t* __restrict__ gvh, const uint16_t* __restrict__ gvl,
    int j, int tid)
{
    #pragma unroll
    for (int i = 0; i < 4; i++) {
        int u = tid + i * 128;
        int r = u >> 3, c8 = (u & 7) * 8;
        uint32_t d = smem_u32(smbuf + (r * APE + c8) * 2);
        size_t koff = (size_t)(j * 64 + r) * HEAD + c8;
        size_t voff = (size_t)r * SEQ + j * 64 + c8;
        cp16(d,           gkh + koff);
        cp16(d + APB,     gkl + koff);
        cp16(d + 2 * APB, gvh + voff);
        cp16(d + 3 * APB, gvl + voff);
    }
    cp_commit();
}

__global__ __launch_bounds__(128) void attn_kernel(float* __restrict__ out)
{
    extern __shared__ char sm[];
    const uchar4 u = c_units[blockIdx.x];
    const int tile = u.x, c0 = u.y, c1 = u.z, slot = u.w;
    const int b = blockIdx.y;
    const int tid = threadIdx.x;
    const int warp = tid >> 5, lane = tid & 31;
    const int g = lane >> 2, tg = lane & 3;
    const int qr = warp * 16;
    const int l8 = lane & 7, mi = lane >> 3;

    const uint32_t smu = smem_u32(sm);
    const uint32_t aQ = smu + ((qr + ((mi & 1) << 3) + l8) * APE + ((mi >> 1) << 3)) * 2;
    const uint32_t bloc = ((((mi >> 1) << 3) + l8) * APE + ((mi & 1) << 3)) * 2;

    uint16_t* qh = reinterpret_cast<uint16_t*>(sm);

    const uint16_t* __restrict__ gqh = g_qh + (size_t)b * SEQ * HEAD;
    const uint16_t* __restrict__ gkh = g_kh + (size_t)b * SEQ * HEAD;
    const uint16_t* __restrict__ gkl = g_kl + (size_t)b * SEQ * HEAD;
    const uint16_t* __restrict__ gvh = g_vth + (size_t)b * HEAD * SEQ;
    const uint16_t* __restrict__ gvl = g_vtl + (size_t)b * HEAD * SEQ;

    stage_kv(sm + (1 + (c0 & 1) * 4) * APB, gkh, gkl, gvh, gvl, c0, tid);
    if (c0 + 1 < c1)
        stage_kv(sm + (1 + ((c0 + 1) & 1) * 4) * APB, gkh, gkl, gvh, gvl, c0 + 1, tid);

    #pragma unroll
    for (int i = 0; i < 4; i++) {
        int uu = tid + i * 128;
        int r = uu >> 3, c8 = (uu & 7) * 8;
        *reinterpret_cast<uint4*>(&qh[r * APE + c8]) =
            *reinterpret_cast<const uint4*>(&gqh[(size_t)(tile * 64 + r) * HEAD + c8]);
    }

    const float SC = 0.125f;
    float mx0 = -CUDART_INF_F, mx1 = -CUDART_INF_F;
    float l0 = 0.f, l1 = 0.f;
    float4 o[8] = {};

    for (int j = c0; j < c1; j++) {
        if (j == c1 - 1) cp_wait<0>(); else cp_wait<1>();
        __syncthreads();

        const uint32_t kb = smu + (1 + (j & 1) * 4) * APB + bloc;
        const uint32_t vb = kb + 2 * APB;

        // ---- S = Qh·Kh + Qh·Kl ----
        float4 s[8] = {};
        #pragma unroll
        for (int kk = 0; kk < 4; kk++) {
            uint32_t ah0, ah1, ah2, ah3;
            ldsm4(ah0, ah1, ah2, ah3, aQ + kk * 32);
            #pragma unroll
            for (int ntp = 0; ntp < 4; ntp++) {
                uint32_t ba = kb + ntp * (16 * APE * 2) + kk * 32;
                uint32_t bh0, bh1, bh2, bh3, bl0, bl1, bl2, bl3;
                ldsm4(bh0, bh1, bh2, bh3, ba);
                ldsm4(bl0, bl1, bl2, bl3, ba + APB);
                mma16(s[2*ntp],   ah0, ah1, ah2, ah3, bh0, bh1);
                mma16(s[2*ntp],   ah0, ah1, ah2, ah3, bl0, bl1);
                mma16(s[2*ntp+1], ah0, ah1, ah2, ah3, bh2, bh3);
                mma16(s[2*ntp+1], ah0, ah1, ah2, ah3, bl2, bl3);
            }
        }

        // ---- scale + causal mask ----
        if (j == tile) {
            const int rg0 = tile * 64 + qr + g;
            const int rg1 = rg0 + 8;
            #pragma unroll
            for (int nt = 0; nt < 8; nt++) {
                const int cg = j * 64 + nt * 8 + 2 * tg;
                s[nt].x = (cg     > rg0) ? -CUDART_INF_F : s[nt].x * SC;
                s[nt].y = (cg + 1 > rg0) ? -CUDART_INF_F : s[nt].y * SC;
                s[nt].z = (cg     > rg1) ? -CUDART_INF_F : s[nt].z * SC;
                s[nt].w = (cg + 1 > rg1) ? -CUDART_INF_F : s[nt].w * SC;
            }
        } else {
            #pragma unroll
            for (int nt = 0; nt < 8; nt++) {
                s[nt].x *= SC; s[nt].y *= SC; s[nt].z *= SC; s[nt].w *= SC;
            }
        }

        // ---- online softmax ----
        float rm0 = -CUDART_INF_F, rm1 = -CUDART_INF_F;
        #pragma unroll
        for (int nt = 0; nt < 8; nt++) {
            rm0 = fmaxf(rm0, fmaxf(s[nt].x, s[nt].y));
            rm1 = fmaxf(rm1, fmaxf(s[nt].z, s[nt].w));
        }
        rm0 = fmaxf(rm0, __shfl_xor_sync(0xffffffffu, rm0, 1));
        rm0 = fmaxf(rm0, __shfl_xor_sync(0xffffffffu, rm0, 2));
        rm1 = fmaxf(rm1, __shfl_xor_sync(0xffffffffu, rm1, 1));
        rm1 = fmaxf(rm1, __shfl_xor_sync(0xffffffffu, rm1, 2));
        const float nm0 = fmaxf(mx0, rm0);
        const float nm1 = fmaxf(mx1, rm1);
        const float a0 = __expf(mx0 - nm0);
        const float a1 = __expf(mx1 - nm1);

        // P packed directly as plain fp16 A-fragments
        uint32_t pa[8], pb[8];
        float rs0 = 0.f, rs1 = 0.f;
        #pragma unroll
        for (int nt = 0; nt < 8; nt++) {
            float px = __expf(s[nt].x - nm0);
            float py = __expf(s[nt].y - nm0);
            float pz = __expf(s[nt].z - nm1);
            float pw = __expf(s[nt].w - nm1);
            rs0 += px + py;
            rs1 += pz + pw;
            pa[nt] = packhf(px, py);
            pb[nt] = packhf(pz, pw);
        }
        rs0 += __shfl_xor_sync(0xffffffffu, rs0, 1);
        rs0 += __shfl_xor_sync(0xffffffffu, rs0, 2);
        rs1 += __shfl_xor_sync(0xffffffffu, rs1, 1);
        rs1 += __shfl_xor_sync(0xffffffffu, rs1, 2);
        l0 = l0 * a0 + rs0;
        l1 = l1 * a1 + rs1;
        mx0 = nm0; mx1 = nm1;
        #pragma unroll
        for (int nt = 0; nt < 8; nt++) {
            o[nt].x *= a0; o[nt].y *= a0;
            o[nt].z *= a1; o[nt].w *= a1;
        }

        // ---- O += P·Vh + P·Vl ----
        #pragma unroll
        for (int kk = 0; kk < 4; kk++) {
            uint32_t a0f = pa[2 * kk],     a1f = pb[2 * kk];
            uint32_t a2f = pa[2 * kk + 1], a3f = pb[2 * kk + 1];
            #pragma unroll
            for (int ntp = 0; ntp < 4; ntp++) {
                uint32_t ba = vb + ntp * (16 * APE * 2) + kk * 32;
                uint32_t vh0, vh1, vh2, vh3, vl0, vl1, vl2, vl3;
                ldsm4(vh0, vh1, vh2, vh3, ba);
                ldsm4(vl0, vl1, vl2, vl3, ba + APB);
                mma16(o[2*ntp],   a0f, a1f, a2f, a3f, vh0, vh1);
                mma16(o[2*ntp],   a0f, a1f, a2f, a3f, vl0, vl1);
                mma16(o[2*ntp+1], a0f, a1f, a2f, a3f, vh2, vh3);
                mma16(o[2*ntp+1], a0f, a1f, a2f, a3f, vl2, vl3);
            }
        }
        __syncthreads();
        if (j + 2 < c1)
            stage_kv(sm + (1 + (j & 1) * 4) * APB, gkh, gkl, gvh, gvl, j + 2, tid);
    }

    if (c0 == 0 && c1 == tile + 1) {
        const float inv0 = __frcp_rn(l0);
        const float inv1 = __frcp_rn(l1);
        #pragma unroll
        for (int nt = 0; nt < 8; nt++) {
            int col = nt * 8 + 2 * tg;
            *reinterpret_cast<float2*>(
                &out[((size_t)b * SEQ + tile * 64 + qr + g    ) * HEAD + col]) =
                make_float2(o[nt].x * inv0, o[nt].y * inv0);
            *reinterpret_cast<float2*>(
                &out[((size_t)b * SEQ + tile * 64 + qr + g + 8) * HEAD + col]) =
                make_float2(o[nt].z * inv1, o[nt].w * inv1);
        }
    } else {
        const int sidx = ((b * 32 + tile) * 2 + slot);
        float* po = g_po + (size_t)sidx * 64 * 64;
        #pragma unroll
        for (int nt = 0; nt < 8; nt++) {
            int col = nt * 8 + 2 * tg;
            *reinterpret_cast<float2*>(&po[(qr + g    ) * 64 + col]) = make_float2(o[nt].x, o[nt].y);
            *reinterpret_cast<float2*>(&po[(qr + g + 8) * 64 + col]) = make_float2(o[nt].z, o[nt].w);
        }
        if (tg == 0) {
            g_pm[sidx * 64 + qr + g    ] = mx0;
            g_pm[sidx * 64 + qr + g + 8] = mx1;
            g_pl[sidx * 64 + qr + g    ] = l0;
            g_pl[sidx * 64 + qr + g + 8] = l1;
        }
    }
}

// ---------------------------------------------------------------------------
// combine: merge split-KV partials for tiles 15..31. grid (17,8), 256 thr.
// ---------------------------------------------------------------------------
__global__ __launch_bounds__(256) void combine_kernel(float* __restrict__ out)
{
    const int tile = blockIdx.x + 15, b = blockIdx.y;
    const int t = threadIdx.x;
    const int r = t >> 2, qd = (t & 3) * 4;
    const int s0 = (b * 32 + tile) * 2;
    const float4* O1 = reinterpret_cast<const float4*>(g_po + ((size_t)s0 * 64 + r) * 64);
    const float4* O2 = reinterpret_cast<const float4*>(g_po + ((size_t)(s0 + 1) * 64 + r) * 64);
    float4* dst = reinterpret_cast<float4*>(out + ((size_t)b * SEQ + tile * 64 + r) * HEAD);

    const float m1 = g_pm[s0 * 64 + r],     m2 = g_pm[(s0 + 1) * 64 + r];
    const float L1 = g_pl[s0 * 64 + r],     L2 = g_pl[(s0 + 1) * 64 + r];
    const float m  = fmaxf(m1, m2);
    const float w1 = __expf(m1 - m), w2 = __expf(m2 - m);
    const float invL = __frcp_rn(w1 * L1 + w2 * L2);
    const float a = w1 * invL, bb = w2 * invL;
    #pragma unroll
    for (int i = 0; i < 4; i++) {
        float4 v1 = O1[qd + i], v2 = O2[qd + i];
        dst[qd + i] = make_float4(v1.x * a + v2.x * bb, v1.y * a + v2.y * bb,
                                  v1.z * a + v2.z * bb, v1.w * a + v2.w * bb);
    }
}

// ---------------------------------------------------------------------------
extern "C" void kernel_launch(void* const* d_in, const int* in_sizes, int n_in,
                              void* d_out, int out_size)
{
    const float* x  = (const float*)d_in[0];
    const float* Wq = (const float*)d_in[1];
    const float* Wk = (const float*)d_in[2];
    const float* Wv = (const float*)d_in[3];
    float* out = (float*)d_out;

    (void)in_sizes; (void)n_in; (void)out_size;

    cudaFuncSetAttribute(proj_kernel,
                         cudaFuncAttributeMaxDynamicSharedMemorySize, PROJ_SMEM);
    cudaFuncSetAttribute(attn_kernel,
                         cudaFuncAttributeMaxDynamicSharedMemorySize, ATTN_SMEM);

    wprep_kernel<<<dim3(16, 3), 256>>>(Wq, Wk, Wv);
    proj_kernel<<<256, 256, PROJ_SMEM>>>(x);
    attn_kernel<<<dim3(49, 8), 128, ATTN_SMEM>>>(out);
    combine_kernel<<<dim3(17, 8), 256>>>(out);
}

// round 10
// speedup vs baseline: 4.8184x; 1.1502x over previous
#include <cuda_runtime.h>
#include <cuda_fp16.h>
#include <math_constants.h>
#include <cstdint>

#define N_EMBED 1024
#define HEAD    64
#define BATCH   8
#define SEQ     2048
#define MROWS   (BATCH * SEQ)   // 16384

// ---------------------------------------------------------------------------
// Global scratch (fp16)
// ---------------------------------------------------------------------------
__device__ uint16_t g_qh[MROWS * HEAD];                            // Q*0.125*log2e fp16
__device__ uint16_t g_kh[MROWS * HEAD];                            // K fp16 [row][head]
__device__ uint16_t g_vth[MROWS * HEAD];                           // V^T fp16 [b][head][seq]
__device__ uint16_t g_wth[3 * HEAD * N_EMBED], g_wtl[3 * HEAD * N_EMBED]; // W^T hi/lo
// split-KV partials + completion counters
__device__ float g_po[BATCH * 32 * 2 * 64 * 64];
__device__ float g_pm[BATCH * 32 * 2 * 64];
__device__ float g_pl[BATCH * 32 * 2 * 64];
__device__ int   g_cnt[BATCH * 32];     // zero-init; +2 per replay per split tile

// ---------------------------------------------------------------------------
// helpers
// ---------------------------------------------------------------------------
__device__ __forceinline__ uint32_t packhf(float x0, float x1) {
    __half2 h = __floats2half2_rn(x0, x1);
    return *reinterpret_cast<uint32_t*>(&h);
}
__device__ __forceinline__ void hilo2h(float x0, float x1, uint32_t& h, uint32_t& l) {
    __half2 hv = __floats2half2_rn(x0, x1);
    h = *reinterpret_cast<uint32_t*>(&hv);
    float2 d = __half22float2(hv);
    __half2 lv = __floats2half2_rn(x0 - d.x, x1 - d.y);
    l = *reinterpret_cast<uint32_t*>(&lv);
}
__device__ __forceinline__ void mma16(float4& c,
                                      uint32_t a0, uint32_t a1, uint32_t a2, uint32_t a3,
                                      uint32_t b0, uint32_t b1) {
    asm volatile(
        "mma.sync.aligned.m16n8k16.row.col.f32.f16.f16.f32 "
        "{%0,%1,%2,%3}, {%4,%5,%6,%7}, {%8,%9}, {%0,%1,%2,%3};"
        : "+f"(c.x), "+f"(c.y), "+f"(c.z), "+f"(c.w)
        : "r"(a0), "r"(a1), "r"(a2), "r"(a3), "r"(b0), "r"(b1));
}
__device__ __forceinline__ void ldsm4(uint32_t& r0, uint32_t& r1, uint32_t& r2,
                                      uint32_t& r3, uint32_t addr) {
    asm volatile("ldmatrix.sync.aligned.m8n8.x4.shared.b16 {%0,%1,%2,%3}, [%4];"
                 : "=r"(r0), "=r"(r1), "=r"(r2), "=r"(r3) : "r"(addr));
}
__device__ __forceinline__ void cp16(uint32_t dst, const void* src) {
    asm volatile("cp.async.cg.shared.global [%0], [%1], 16;" :: "r"(dst), "l"(src));
}
__device__ __forceinline__ void cp_commit() {
    asm volatile("cp.async.commit_group;");
}
template <int N>
__device__ __forceinline__ void cp_wait() {
    asm volatile("cp.async.wait_group %0;" :: "n"(N));
}
__device__ __forceinline__ uint32_t smem_u32(const void* p) {
    return (uint32_t)__cvta_generic_to_shared(p);
}

// 0.125 * log2(e): folded into Q so softmax uses exp2 directly
#define QSCALE 0.18033688011112042f

// ---------------------------------------------------------------------------
// wprep: W [k][n] fp32 -> W^T [n][k] fp16 hi/lo.  grid (16, 3), 256 thr.
// ---------------------------------------------------------------------------
__global__ __launch_bounds__(256) void wprep_kernel(
    const float* __restrict__ Wq, const float* __restrict__ Wk,
    const float* __restrict__ Wv)
{
    const int which = blockIdx.y;
    const float* __restrict__ W = (which == 0) ? Wq : (which == 1) ? Wk : Wv;
    const int k0 = blockIdx.x * 64;

    __shared__ float sw[64][68];
    const int t = threadIdx.x;
    const int r = t >> 2, c16 = (t & 3) * 16;
    #pragma unroll
    for (int rep = 0; rep < 4; rep++) {
        float4 v = *reinterpret_cast<const float4*>(
            &W[(size_t)(k0 + r) * HEAD + c16 + rep * 4]);
        sw[r][c16 + rep * 4 + 0] = v.x; sw[r][c16 + rep * 4 + 1] = v.y;
        sw[r][c16 + rep * 4 + 2] = v.z; sw[r][c16 + rep * 4 + 3] = v.w;
    }
    __syncthreads();
    uint32_t hp[8], lp[8];
    #pragma unroll
    for (int i = 0; i < 8; i++)
        hilo2h(sw[c16 + 2 * i][r], sw[c16 + 2 * i + 1][r], hp[i], lp[i]);
    size_t off = ((size_t)(which * HEAD + r)) * N_EMBED + k0 + c16;
    *reinterpret_cast<uint4*>(&g_wth[off    ]) = make_uint4(hp[0], hp[1], hp[2], hp[3]);
    *reinterpret_cast<uint4*>(&g_wth[off + 8]) = make_uint4(hp[4], hp[5], hp[6], hp[7]);
    *reinterpret_cast<uint4*>(&g_wtl[off    ]) = make_uint4(lp[0], lp[1], lp[2], lp[3]);
    *reinterpret_cast<uint4*>(&g_wtl[off + 8]) = make_uint4(lp[4], lp[5], lp[6], lp[7]);
}

// ---------------------------------------------------------------------------
// Fused proj: 64-row tiles, 256 CTAs, fp16 3-term, ldmatrix fragments.
// Outputs: Q (scaled, fp16), K (fp16), V^T (fp16).
// ---------------------------------------------------------------------------
#define WP     40
#define XTILE  (64 * WP * 2)
#define PBUF   (8 * XTILE)
#define PROJ_SMEM (2 * PBUF)            // 81920 bytes

__device__ __forceinline__ void proj_stage_w(char* sm, int buf, int ch, int t)
{
    const int kc0 = ch * 32;
    #pragma unroll
    for (int i = 0; i < 6; i++) {
        int u = t + i * 256;
        int w = u >> 9, rem = u & 511;
        int row = rem >> 3, rem2 = rem & 7;
        int arr = rem2 >> 2, q = rem2 & 3;
        const uint16_t* src = (arr ? g_wtl : g_wth) +
                              (size_t)(w * HEAD + row) * N_EMBED + kc0 + q * 8;
        uint32_t d = smem_u32(sm + buf * PBUF + (2 + w * 2 + arr) * XTILE +
                              (row * WP + q * 8) * 2);
        cp16(d, src);
    }
    cp_commit();
}

__global__ __launch_bounds__(256) void proj_kernel(const float* __restrict__ x)
{
    extern __shared__ char sm[];
    const int m0 = blockIdx.x * 64;
    const int t = threadIdx.x;
    const int warp = t >> 5, lane = t & 31;
    const int g = lane >> 2, tg = lane & 3;
    const int wm = warp >> 1, wn = warp & 1;
    const int l8 = lane & 7, mi = lane >> 3;

    const uint32_t smu = smem_u32(sm);
    const uint32_t aX = smu + ((wm * 16 + ((mi & 1) << 3) + l8) * WP + ((mi >> 1) << 3)) * 2;
    const uint32_t bW = smu + 2 * XTILE +
                        ((wn * 32 + ((mi >> 1) << 3) + l8) * WP + ((mi & 1) << 3)) * 2;

    const int xrow = t >> 2, xc8 = (t & 3) * 8;

    float4 acc[3][4] = {};
    float4 xr0, xr1;

    {
        const float* src = x + (size_t)(m0 + xrow) * N_EMBED + xc8;
        xr0 = *reinterpret_cast<const float4*>(src);
        xr1 = *reinterpret_cast<const float4*>(src + 4);
        uint32_t h0, l0, h1, l1, h2, l2, h3, l3;
        hilo2h(xr0.x, xr0.y, h0, l0); hilo2h(xr0.z, xr0.w, h1, l1);
        hilo2h(xr1.x, xr1.y, h2, l2); hilo2h(xr1.z, xr1.w, h3, l3);
        *reinterpret_cast<uint4*>(sm + (xrow * WP + xc8) * 2) = make_uint4(h0, h1, h2, h3);
        *reinterpret_cast<uint4*>(sm + XTILE + (xrow * WP + xc8) * 2) = make_uint4(l0, l1, l2, l3);
        proj_stage_w(sm, 0, 0, t);
        xr0 = *reinterpret_cast<const float4*>(src + 32);
        xr1 = *reinterpret_cast<const float4*>(src + 36);
    }

    for (int ch = 0; ch < 32; ch++) {
        cp_wait<0>();
        __syncthreads();
        const int buf = ch & 1;

        if (ch + 1 < 32) {
            const int nbuf = (ch + 1) & 1;
            uint32_t h0, l0, h1, l1, h2, l2, h3, l3;
            hilo2h(xr0.x, xr0.y, h0, l0); hilo2h(xr0.z, xr0.w, h1, l1);
            hilo2h(xr1.x, xr1.y, h2, l2); hilo2h(xr1.z, xr1.w, h3, l3);
            *reinterpret_cast<uint4*>(sm + nbuf * PBUF + (xrow * WP + xc8) * 2) =
                make_uint4(h0, h1, h2, h3);
            *reinterpret_cast<uint4*>(sm + nbuf * PBUF + XTILE + (xrow * WP + xc8) * 2) =
                make_uint4(l0, l1, l2, l3);
            proj_stage_w(sm, nbuf, ch + 1, t);
            if (ch + 2 < 32) {
                const float* src = x + (size_t)(m0 + xrow) * N_EMBED + (ch + 2) * 32 + xc8;
                xr0 = *reinterpret_cast<const float4*>(src);
                xr1 = *reinterpret_cast<const float4*>(src + 4);
            }
        }

        const uint32_t ax = aX + buf * PBUF;
        const uint32_t bw = bW + buf * PBUF;
        #pragma unroll
        for (int kk = 0; kk < 2; kk++) {
            uint32_t ah0, ah1, ah2, ah3, al0, al1, al2, al3;
            ldsm4(ah0, ah1, ah2, ah3, ax + kk * 32);
            ldsm4(al0, al1, al2, al3, ax + XTILE + kk * 32);
            #pragma unroll
            for (int w = 0; w < 3; w++) {
                #pragma unroll
                for (int ntp = 0; ntp < 2; ntp++) {
                    uint32_t ba = bw + w * 2 * XTILE + ntp * (16 * WP * 2) + kk * 32;
                    uint32_t bh0, bh1, bh2, bh3, bl0, bl1, bl2, bl3;
                    ldsm4(bh0, bh1, bh2, bh3, ba);
                    ldsm4(bl0, bl1, bl2, bl3, ba + XTILE);
                    mma16(acc[w][2*ntp],   ah0, ah1, ah2, ah3, bh0, bh1);
                    mma16(acc[w][2*ntp],   ah0, ah1, ah2, ah3, bl0, bl1);
                    mma16(acc[w][2*ntp],   al0, al1, al2, al3, bh0, bh1);
                    mma16(acc[w][2*ntp+1], ah0, ah1, ah2, ah3, bh2, bh3);
                    mma16(acc[w][2*ntp+1], ah0, ah1, ah2, ah3, bl2, bl3);
                    mma16(acc[w][2*ntp+1], al0, al1, al2, al3, bh2, bh3);
                }
            }
        }
        __syncthreads();
    }

    // ---- epilogue: Q scaled fp16; K plain fp16 ----
    #pragma unroll
    for (int nt = 0; nt < 4; nt++) {
        int m   = m0 + wm * 16 + g;
        int col = wn * 32 + nt * 8 + 2 * tg;
        reinterpret_cast<uint32_t*>(g_qh)[((size_t)m * HEAD + col) >> 1] =
            packhf(acc[0][nt].x * QSCALE, acc[0][nt].y * QSCALE);
        reinterpret_cast<uint32_t*>(g_qh)[((size_t)(m + 8) * HEAD + col) >> 1] =
            packhf(acc[0][nt].z * QSCALE, acc[0][nt].w * QSCALE);
        reinterpret_cast<uint32_t*>(g_kh)[((size_t)m * HEAD + col) >> 1] =
            packhf(acc[1][nt].x, acc[1][nt].y);
        reinterpret_cast<uint32_t*>(g_kh)[((size_t)(m + 8) * HEAD + col) >> 1] =
            packhf(acc[1][nt].z, acc[1][nt].w);
    }

    // ---- epilogue: V -> V^T fp16 (fused transpose via smem) ----
    float* sv = reinterpret_cast<float*>(sm);   // [64][68]
    #pragma unroll
    for (int nt = 0; nt < 4; nt++) {
        int r0 = wm * 16 + g;
        int col = wn * 32 + nt * 8 + 2 * tg;
        sv[r0 * 68 + col] = acc[2][nt].x; sv[r0 * 68 + col + 1] = acc[2][nt].y;
        sv[(r0 + 8) * 68 + col] = acc[2][nt].z; sv[(r0 + 8) * 68 + col + 1] = acc[2][nt].w;
    }
    __syncthreads();
    {
        const int r = t >> 2, c16 = (t & 3) * 16;
        uint32_t hp[8];
        #pragma unroll
        for (int i = 0; i < 8; i++)
            hp[i] = packhf(sv[(c16 + 2 * i) * 68 + r], sv[(c16 + 2 * i + 1) * 68 + r]);
        const int b = m0 >> 11;
        const int seq0 = m0 & 2047;
        size_t off = ((size_t)(b * HEAD + r)) * SEQ + seq0 + c16;
        *reinterpret_cast<uint4*>(&g_vth[off    ]) = make_uint4(hp[0], hp[1], hp[2], hp[3]);
        *reinterpret_cast<uint4*>(&g_vth[off + 8]) = make_uint4(hp[4], hp[5], hp[6], hp[7]);
    }
}

// ---------------------------------------------------------------------------
// attn: split-KV causal flash attention, fp16 single-term S and PV,
// exp2 softmax, inline split merge (second finisher merges).
// grid (49, 8), 128 thr. smem: q + 2 x (k, v) = 5 tiles = 46 KB.
// ---------------------------------------------------------------------------
#define APE 72
#define APB (64 * APE * 2)
#define ATTN_SMEM (5 * APB)              // 46080 bytes

__constant__ uchar4 c_units[49] = {
    {31,0,16,0},{31,16,32,1},{30,0,16,0},
    {30,16,31,1},{29,0,15,0},{29,15,30,1},{28,0,15,0},{14,0,15,0},
    {28,15,29,1},{27,0,14,0},{27,14,28,1},{26,0,14,0},{13,0,14,0},
    {26,14,27,1},{25,0,13,0},{25,13,26,1},{24,0,13,0},{12,0,13,0},
    {24,13,25,1},{23,0,12,0},{23,12,24,1},{22,0,12,0},{11,0,12,0},
    {22,12,23,1},{21,0,11,0},{21,11,22,1},{20,0,11,0},{10,0,11,0},
    {20,11,21,1},{19,0,10,0},{19,10,20,1},{18,0,10,0},{9,0,10,0},
    {18,10,19,1},{17,0,9,0},{17,9,18,1},{16,0,9,0},{8,0,9,0},
    {16,9,17,1},{15,0,8,0},{15,8,16,1},{7,0,8,0},
    {6,0,7,0},{5,0,6,0},{4,0,5,0},{3,0,4,0},{2,0,3,0},{1,0,2,0},{0,0,1,0}
};

__device__ __forceinline__ void stage_kv(char* smbuf,
    const uint16_t* __restrict__ gk, const uint16_t* __restrict__ gv,
    int j, int tid)
{
    #pragma unroll
    for (int i = 0; i < 4; i++) {
        int u = tid + i * 128;
        int r = u >> 3, c8 = (u & 7) * 8;
        uint32_t d = smem_u32(smbuf + (r * APE + c8) * 2);
        cp16(d,       gk + (size_t)(j * 64 + r) * HEAD + c8);
        cp16(d + APB, gv + (size_t)r * SEQ + j * 64 + c8);
    }
    cp_commit();
}

__global__ __launch_bounds__(128) void attn_kernel(float* __restrict__ out)
{
    extern __shared__ char sm[];
    __shared__ int s_flag;
    const uchar4 u = c_units[blockIdx.x];
    const int tile = u.x, c0 = u.y, c1 = u.z, slot = u.w;
    const int b = blockIdx.y;
    const int tid = threadIdx.x;
    const int warp = tid >> 5, lane = tid & 31;
    const int g = lane >> 2, tg = lane & 3;
    const int qr = warp * 16;
    const int l8 = lane & 7, mi = lane >> 3;

    const uint32_t smu = smem_u32(sm);
    const uint32_t aQ = smu + ((qr + ((mi & 1) << 3) + l8) * APE + ((mi >> 1) << 3)) * 2;
    const uint32_t bloc = ((((mi >> 1) << 3) + l8) * APE + ((mi & 1) << 3)) * 2;

    uint16_t* qh = reinterpret_cast<uint16_t*>(sm);

    const uint16_t* __restrict__ gqh = g_qh + (size_t)b * SEQ * HEAD;
    const uint16_t* __restrict__ gkh = g_kh + (size_t)b * SEQ * HEAD;
    const uint16_t* __restrict__ gvh = g_vth + (size_t)b * HEAD * SEQ;

    stage_kv(sm + (1 + (c0 & 1) * 2) * APB, gkh, gvh, c0, tid);
    if (c0 + 1 < c1)
        stage_kv(sm + (1 + ((c0 + 1) & 1) * 2) * APB, gkh, gvh, c0 + 1, tid);

    #pragma unroll
    for (int i = 0; i < 4; i++) {
        int uu = tid + i * 128;
        int r = uu >> 3, c8 = (uu & 7) * 8;
        *reinterpret_cast<uint4*>(&qh[r * APE + c8]) =
            *reinterpret_cast<const uint4*>(&gqh[(size_t)(tile * 64 + r) * HEAD + c8]);
    }

    float mx0 = -CUDART_INF_F, mx1 = -CUDART_INF_F;
    float l0 = 0.f, l1 = 0.f;
    float4 o[8] = {};

    for (int j = c0; j < c1; j++) {
        if (j == c1 - 1) cp_wait<0>(); else cp_wait<1>();
        __syncthreads();

        const uint32_t kb = smu + (1 + (j & 1) * 2) * APB + bloc;
        const uint32_t vb = kb + APB;

        // ---- S = Q·K (Q pre-scaled by 0.125*log2e) ----
        float4 s[8] = {};
        #pragma unroll
        for (int kk = 0; kk < 4; kk++) {
            uint32_t ah0, ah1, ah2, ah3;
            ldsm4(ah0, ah1, ah2, ah3, aQ + kk * 32);
            #pragma unroll
            for (int ntp = 0; ntp < 4; ntp++) {
                uint32_t ba = kb + ntp * (16 * APE * 2) + kk * 32;
                uint32_t bh0, bh1, bh2, bh3;
                ldsm4(bh0, bh1, bh2, bh3, ba);
                mma16(s[2*ntp],   ah0, ah1, ah2, ah3, bh0, bh1);
                mma16(s[2*ntp+1], ah0, ah1, ah2, ah3, bh2, bh3);
            }
        }

        // ---- causal mask (diagonal chunk only; no scale needed) ----
        if (j == tile) {
            const int rg0 = tile * 64 + qr + g;
            const int rg1 = rg0 + 8;
            #pragma unroll
            for (int nt = 0; nt < 8; nt++) {
                const int cg = j * 64 + nt * 8 + 2 * tg;
                if (cg     > rg0) s[nt].x = -CUDART_INF_F;
                if (cg + 1 > rg0) s[nt].y = -CUDART_INF_F;
                if (cg     > rg1) s[nt].z = -CUDART_INF_F;
                if (cg + 1 > rg1) s[nt].w = -CUDART_INF_F;
            }
        }

        // ---- online softmax (exp2 domain) ----
        float rm0 = -CUDART_INF_F, rm1 = -CUDART_INF_F;
        #pragma unroll
        for (int nt = 0; nt < 8; nt++) {
            rm0 = fmaxf(rm0, fmaxf(s[nt].x, s[nt].y));
            rm1 = fmaxf(rm1, fmaxf(s[nt].z, s[nt].w));
        }
        rm0 = fmaxf(rm0, __shfl_xor_sync(0xffffffffu, rm0, 1));
        rm0 = fmaxf(rm0, __shfl_xor_sync(0xffffffffu, rm0, 2));
        rm1 = fmaxf(rm1, __shfl_xor_sync(0xffffffffu, rm1, 1));
        rm1 = fmaxf(rm1, __shfl_xor_sync(0xffffffffu, rm1, 2));
        const float nm0 = fmaxf(mx0, rm0);
        const float nm1 = fmaxf(mx1, rm1);
        const float a0 = exp2f(mx0 - nm0);
        const float a1 = exp2f(mx1 - nm1);

        uint32_t pa[8], pb[8];
        float rs0 = 0.f, rs1 = 0.f;
        #pragma unroll
        for (int nt = 0; nt < 8; nt++) {
            float px = exp2f(s[nt].x - nm0);
            float py = exp2f(s[nt].y - nm0);
            float pz = exp2f(s[nt].z - nm1);
            float pw = exp2f(s[nt].w - nm1);
            rs0 += px + py;
            rs1 += pz + pw;
            pa[nt] = packhf(px, py);
            pb[nt] = packhf(pz, pw);
        }
        rs0 += __shfl_xor_sync(0xffffffffu, rs0, 1);
        rs0 += __shfl_xor_sync(0xffffffffu, rs0, 2);
        rs1 += __shfl_xor_sync(0xffffffffu, rs1, 1);
        rs1 += __shfl_xor_sync(0xffffffffu, rs1, 2);
        l0 = l0 * a0 + rs0;
        l1 = l1 * a1 + rs1;
        mx0 = nm0; mx1 = nm1;
        #pragma unroll
        for (int nt = 0; nt < 8; nt++) {
            o[nt].x *= a0; o[nt].y *= a0;
            o[nt].z *= a1; o[nt].w *= a1;
        }

        // ---- O += P·V ----
        #pragma unroll
        for (int kk = 0; kk < 4; kk++) {
            uint32_t a0f = pa[2 * kk],     a1f = pb[2 * kk];
            uint32_t a2f = pa[2 * kk + 1], a3f = pb[2 * kk + 1];
            #pragma unroll
            for (int ntp = 0; ntp < 4; ntp++) {
                uint32_t ba = vb + ntp * (16 * APE * 2) + kk * 32;
                uint32_t vh0, vh1, vh2, vh3;
                ldsm4(vh0, vh1, vh2, vh3, ba);
                mma16(o[2*ntp],   a0f, a1f, a2f, a3f, vh0, vh1);
                mma16(o[2*ntp+1], a0f, a1f, a2f, a3f, vh2, vh3);
            }
        }
        __syncthreads();
        if (j + 2 < c1)
            stage_kv(sm + (1 + (j & 1) * 2) * APB, gkh, gvh, j + 2, tid);
    }

    if (c0 == 0 && c1 == tile + 1) {
        // full tile: normalize and write output directly
        const float inv0 = __frcp_rn(l0);
        const float inv1 = __frcp_rn(l1);
        #pragma unroll
        for (int nt = 0; nt < 8; nt++) {
            int col = nt * 8 + 2 * tg;
            *reinterpret_cast<float2*>(
                &out[((size_t)b * SEQ + tile * 64 + qr + g    ) * HEAD + col]) =
                make_float2(o[nt].x * inv0, o[nt].y * inv0);
            *reinterpret_cast<float2*>(
                &out[((size_t)b * SEQ + tile * 64 + qr + g + 8) * HEAD + col]) =
                make_float2(o[nt].z * inv1, o[nt].w * inv1);
        }
        return;
    }

    // ---- split tile: publish partial, second finisher merges ----
    const int tix  = b * 32 + tile;
    const int sidx = tix * 2 + slot;
    {
        float* po = g_po + (size_t)sidx * 64 * 64;
        #pragma unroll
        for (int nt = 0; nt < 8; nt++) {
            int col = nt * 8 + 2 * tg;
            *reinterpret_cast<float2*>(&po[(qr + g    ) * 64 + col]) = make_float2(o[nt].x, o[nt].y);
            *reinterpret_cast<float2*>(&po[(qr + g + 8) * 64 + col]) = make_float2(o[nt].z, o[nt].w);
        }
        if (tg == 0) {
            g_pm[sidx * 64 + qr + g    ] = mx0;
            g_pm[sidx * 64 + qr + g + 8] = mx1;
            g_pl[sidx * 64 + qr + g    ] = l0;
            g_pl[sidx * 64 + qr + g + 8] = l1;
        }
    }
    __threadfence();
    __syncthreads();
    if (tid == 0) s_flag = atomicAdd(&g_cnt[tix], 1) & 1;
    __syncthreads();
    if (!s_flag) return;    // first finisher: partner will merge
    __threadfence();        // acquire partner's published data

    // merge own registers with partner's partial
    const int pidx = tix * 2 + (1 - slot);
    const float* pp = g_po + (size_t)pidx * 64 * 64;
    const float pm0 = g_pm[pidx * 64 + qr + g],     pm1 = g_pm[pidx * 64 + qr + g + 8];
    const float pL0 = g_pl[pidx * 64 + qr + g],     pL1 = g_pl[pidx * 64 + qr + g + 8];
    const float m0f = fmaxf(mx0, pm0), m1f = fmaxf(mx1, pm1);
    const float ws0 = exp2f(mx0 - m0f), wp0 = exp2f(pm0 - m0f);
    const float ws1 = exp2f(mx1 - m1f), wp1 = exp2f(pm1 - m1f);
    const float inv0 = __frcp_rn(l0 * ws0 + pL0 * wp0);
    const float inv1 = __frcp_rn(l1 * ws1 + pL1 * wp1);
    const float c00 = ws0 * inv0, c01 = wp0 * inv0;
    const float c10 = ws1 * inv1, c11 = wp1 * inv1;
    #pragma unroll
    for (int nt = 0; nt < 8; nt++) {
        int col = nt * 8 + 2 * tg;
        float2 q0 = *reinterpret_cast<const float2*>(&pp[(qr + g    ) * 64 + col]);
        float2 q1 = *reinterpret_cast<const float2*>(&pp[(qr + g + 8) * 64 + col]);
        *reinterpret_cast<float2*>(
            &out[((size_t)b * SEQ + tile * 64 + qr + g    ) * HEAD + col]) =
            make_float2(o[nt].x * c00 + q0.x * c01, o[nt].y * c00 + q0.y * c01);
        *reinterpret_cast<float2*>(
            &out[((size_t)b * SEQ + tile * 64 + qr + g + 8) * HEAD + col]) =
            make_float2(o[nt].z * c10 + q1.x * c11, o[nt].w * c10 + q1.y * c11);
    }
}

// ---------------------------------------------------------------------------
extern "C" void kernel_launch(void* const* d_in, const int* in_sizes, int n_in,
                              void* d_out, int out_size)
{
    const float* x  = (const float*)d_in[0];
    const float* Wq = (const float*)d_in[1];
    const float* Wk = (const float*)d_in[2];
    const float* Wv = (const float*)d_in[3];
    float* out = (float*)d_out;

    (void)in_sizes; (void)n_in; (void)out_size;

    cudaFuncSetAttribute(proj_kernel,
                         cudaFuncAttributeMaxDynamicSharedMemorySize, PROJ_SMEM);
    cudaFuncSetAttribute(attn_kernel,
                         cudaFuncAttributeMaxDynamicSharedMemorySize, ATTN_SMEM);

    wprep_kernel<<<dim3(16, 3), 256>>>(Wq, Wk, Wv);
    proj_kernel<<<256, 256, PROJ_SMEM>>>(x);
    attn_kernel<<<dim3(49, 8), 128, ATTN_SMEM>>>(out);
}

// round 11
// speedup vs baseline: 7.2531x; 1.5053x over previous
#include <cuda_runtime.h>
#include <cuda_fp16.h>
#include <math_constants.h>
#include <cstdint>

#define N_EMBED 1024
#define HEAD    64
#define BATCH   8
#define SEQ     2048
#define MROWS   (BATCH * SEQ)   // 16384

// ---------------------------------------------------------------------------
// Global scratch (fp16)
// ---------------------------------------------------------------------------
__device__ uint16_t g_qh[MROWS * HEAD];                            // Q*0.125*log2e fp16
__device__ uint16_t g_kh[MROWS * HEAD];                            // K fp16 [row][head]
__device__ uint16_t g_vth[MROWS * HEAD];                           // V^T fp16 [b][head][seq]
__device__ uint16_t g_wth[3 * HEAD * N_EMBED];                     // W^T fp16 [which][n][k]
// split-KV partials + completion counters
__device__ float g_po[BATCH * 32 * 2 * 64 * 64];
__device__ float g_pm[BATCH * 32 * 2 * 64];
__device__ float g_pl[BATCH * 32 * 2 * 64];
__device__ int   g_cnt[BATCH * 32];     // zero-init; +2 per replay per split tile

// ---------------------------------------------------------------------------
// helpers
// ---------------------------------------------------------------------------
__device__ __forceinline__ uint32_t packhf(float x0, float x1) {
    __half2 h = __floats2half2_rn(x0, x1);
    return *reinterpret_cast<uint32_t*>(&h);
}
__device__ __forceinline__ void mma16(float4& c,
                                      uint32_t a0, uint32_t a1, uint32_t a2, uint32_t a3,
                                      uint32_t b0, uint32_t b1) {
    asm volatile(
        "mma.sync.aligned.m16n8k16.row.col.f32.f16.f16.f32 "
        "{%0,%1,%2,%3}, {%4,%5,%6,%7}, {%8,%9}, {%0,%1,%2,%3};"
        : "+f"(c.x), "+f"(c.y), "+f"(c.z), "+f"(c.w)
        : "r"(a0), "r"(a1), "r"(a2), "r"(a3), "r"(b0), "r"(b1));
}
__device__ __forceinline__ void ldsm4(uint32_t& r0, uint32_t& r1, uint32_t& r2,
                                      uint32_t& r3, uint32_t addr) {
    asm volatile("ldmatrix.sync.aligned.m8n8.x4.shared.b16 {%0,%1,%2,%3}, [%4];"
                 : "=r"(r0), "=r"(r1), "=r"(r2), "=r"(r3) : "r"(addr));
}
__device__ __forceinline__ void cp16(uint32_t dst, const void* src) {
    asm volatile("cp.async.cg.shared.global [%0], [%1], 16;" :: "r"(dst), "l"(src));
}
__device__ __forceinline__ void cp_commit() {
    asm volatile("cp.async.commit_group;");
}
template <int N>
__device__ __forceinline__ void cp_wait() {
    asm volatile("cp.async.wait_group %0;" :: "n"(N));
}
__device__ __forceinline__ uint32_t smem_u32(const void* p) {
    return (uint32_t)__cvta_generic_to_shared(p);
}

// 0.125 * log2(e): folded into Q so softmax uses exp2 directly
#define QSCALE 0.18033688011112042f

// ---------------------------------------------------------------------------
// wprep: W [k][n] fp32 -> W^T [n][k] fp16.  grid (16, 3), 256 thr.
// ---------------------------------------------------------------------------
__global__ __launch_bounds__(256) void wprep_kernel(
    const float* __restrict__ Wq, const float* __restrict__ Wk,
    const float* __restrict__ Wv)
{
    const int which = blockIdx.y;
    const float* __restrict__ W = (which == 0) ? Wq : (which == 1) ? Wk : Wv;
    const int k0 = blockIdx.x * 64;

    __shared__ float sw[64][68];
    const int t = threadIdx.x;
    const int r = t >> 2, c16 = (t & 3) * 16;
    #pragma unroll
    for (int rep = 0; rep < 4; rep++) {
        float4 v = *reinterpret_cast<const float4*>(
            &W[(size_t)(k0 + r) * HEAD + c16 + rep * 4]);
        sw[r][c16 + rep * 4 + 0] = v.x; sw[r][c16 + rep * 4 + 1] = v.y;
        sw[r][c16 + rep * 4 + 2] = v.z; sw[r][c16 + rep * 4 + 3] = v.w;
    }
    __syncthreads();
    uint32_t hp[8];
    #pragma unroll
    for (int i = 0; i < 8; i++)
        hp[i] = packhf(sw[c16 + 2 * i][r], sw[c16 + 2 * i + 1][r]);
    size_t off = ((size_t)(which * HEAD + r)) * N_EMBED + k0 + c16;
    *reinterpret_cast<uint4*>(&g_wth[off    ]) = make_uint4(hp[0], hp[1], hp[2], hp[3]);
    *reinterpret_cast<uint4*>(&g_wth[off + 8]) = make_uint4(hp[4], hp[5], hp[6], hp[7]);
}

// ---------------------------------------------------------------------------
// Fused proj: single-term fp16 GEMM. 64-row tiles, 256 CTAs, ldmatrix frags.
// Outputs: Q (scaled, fp16), K (fp16), V^T (fp16).
// smem per buf: xh + w0 + w1 + w2 (each 64x40 halves) = 20 KB; 2 bufs = 40 KB.
// ---------------------------------------------------------------------------
#define WP     40
#define XTILE  (64 * WP * 2)            // 5120 bytes
#define PBUF   (4 * XTILE)              // xh, w0, w1, w2
#define PROJ_SMEM (2 * PBUF)            // 40960 bytes

__device__ __forceinline__ void proj_stage_w(char* sm, int buf, int ch, int t)
{
    const int kc0 = ch * 32;
    #pragma unroll
    for (int i = 0; i < 3; i++) {
        int u = t + i * 256;                // 0..767: 3 tiles x 256 16B-blocks
        int w = u >> 8, blk = u & 255;
        int row = blk >> 2, q = blk & 3;
        const uint16_t* src = g_wth + (size_t)(w * HEAD + row) * N_EMBED + kc0 + q * 8;
        uint32_t d = smem_u32(sm + buf * PBUF + (1 + w) * XTILE + (row * WP + q * 8) * 2);
        cp16(d, src);
    }
    cp_commit();
}

__global__ __launch_bounds__(256) void proj_kernel(const float* __restrict__ x)
{
    extern __shared__ char sm[];
    const int m0 = blockIdx.x * 64;
    const int t = threadIdx.x;
    const int warp = t >> 5, lane = t & 31;
    const int g = lane >> 2, tg = lane & 3;
    const int wm = warp >> 1, wn = warp & 1;
    const int l8 = lane & 7, mi = lane >> 3;

    const uint32_t smu = smem_u32(sm);
    const uint32_t aX = smu + ((wm * 16 + ((mi & 1) << 3) + l8) * WP + ((mi >> 1) << 3)) * 2;
    const uint32_t bW = smu + XTILE +
                        ((wn * 32 + ((mi >> 1) << 3) + l8) * WP + ((mi & 1) << 3)) * 2;

    const int xrow = t >> 2, xc8 = (t & 3) * 8;

    float4 acc[3][4] = {};
    float4 xr0, xr1;

    {
        const float* src = x + (size_t)(m0 + xrow) * N_EMBED + xc8;
        xr0 = *reinterpret_cast<const float4*>(src);
        xr1 = *reinterpret_cast<const float4*>(src + 4);
        *reinterpret_cast<uint4*>(sm + (xrow * WP + xc8) * 2) =
            make_uint4(packhf(xr0.x, xr0.y), packhf(xr0.z, xr0.w),
                       packhf(xr1.x, xr1.y), packhf(xr1.z, xr1.w));
        proj_stage_w(sm, 0, 0, t);
        xr0 = *reinterpret_cast<const float4*>(src + 32);
        xr1 = *reinterpret_cast<const float4*>(src + 36);
    }

    for (int ch = 0; ch < 32; ch++) {
        cp_wait<0>();
        __syncthreads();
        const int buf = ch & 1;

        if (ch + 1 < 32) {
            const int nbuf = (ch + 1) & 1;
            *reinterpret_cast<uint4*>(sm + nbuf * PBUF + (xrow * WP + xc8) * 2) =
                make_uint4(packhf(xr0.x, xr0.y), packhf(xr0.z, xr0.w),
                           packhf(xr1.x, xr1.y), packhf(xr1.z, xr1.w));
            proj_stage_w(sm, nbuf, ch + 1, t);
            if (ch + 2 < 32) {
                const float* src = x + (size_t)(m0 + xrow) * N_EMBED + (ch + 2) * 32 + xc8;
                xr0 = *reinterpret_cast<const float4*>(src);
                xr1 = *reinterpret_cast<const float4*>(src + 4);
            }
        }

        const uint32_t ax = aX + buf * PBUF;
        const uint32_t bw = bW + buf * PBUF;
        #pragma unroll
        for (int kk = 0; kk < 2; kk++) {
            uint32_t ah0, ah1, ah2, ah3;
            ldsm4(ah0, ah1, ah2, ah3, ax + kk * 32);
            #pragma unroll
            for (int w = 0; w < 3; w++) {
                #pragma unroll
                for (int ntp = 0; ntp < 2; ntp++) {
                    uint32_t ba = bw + w * XTILE + ntp * (16 * WP * 2) + kk * 32;
                    uint32_t bh0, bh1, bh2, bh3;
                    ldsm4(bh0, bh1, bh2, bh3, ba);
                    mma16(acc[w][2*ntp],   ah0, ah1, ah2, ah3, bh0, bh1);
                    mma16(acc[w][2*ntp+1], ah0, ah1, ah2, ah3, bh2, bh3);
                }
            }
        }
        __syncthreads();
    }

    // ---- epilogue: Q scaled fp16; K plain fp16 ----
    #pragma unroll
    for (int nt = 0; nt < 4; nt++) {
        int m   = m0 + wm * 16 + g;
        int col = wn * 32 + nt * 8 + 2 * tg;
        reinterpret_cast<uint32_t*>(g_qh)[((size_t)m * HEAD + col) >> 1] =
            packhf(acc[0][nt].x * QSCALE, acc[0][nt].y * QSCALE);
        reinterpret_cast<uint32_t*>(g_qh)[((size_t)(m + 8) * HEAD + col) >> 1] =
            packhf(acc[0][nt].z * QSCALE, acc[0][nt].w * QSCALE);
        reinterpret_cast<uint32_t*>(g_kh)[((size_t)m * HEAD + col) >> 1] =
            packhf(acc[1][nt].x, acc[1][nt].y);
        reinterpret_cast<uint32_t*>(g_kh)[((size_t)(m + 8) * HEAD + col) >> 1] =
            packhf(acc[1][nt].z, acc[1][nt].w);
    }

    // ---- epilogue: V -> V^T fp16 (fused transpose via smem) ----
    float* sv = reinterpret_cast<float*>(sm);   // [64][68] fp32 = 17408 B
    #pragma unroll
    for (int nt = 0; nt < 4; nt++) {
        int r0 = wm * 16 + g;
        int col = wn * 32 + nt * 8 + 2 * tg;
        sv[r0 * 68 + col] = acc[2][nt].x; sv[r0 * 68 + col + 1] = acc[2][nt].y;
        sv[(r0 + 8) * 68 + col] = acc[2][nt].z; sv[(r0 + 8) * 68 + col + 1] = acc[2][nt].w;
    }
    __syncthreads();
    {
        const int r = t >> 2, c16 = (t & 3) * 16;
        uint32_t hp[8];
        #pragma unroll
        for (int i = 0; i < 8; i++)
            hp[i] = packhf(sv[(c16 + 2 * i) * 68 + r], sv[(c16 + 2 * i + 1) * 68 + r]);
        const int b = m0 >> 11;
        const int seq0 = m0 & 2047;
        size_t off = ((size_t)(b * HEAD + r)) * SEQ + seq0 + c16;
        *reinterpret_cast<uint4*>(&g_vth[off    ]) = make_uint4(hp[0], hp[1], hp[2], hp[3]);
        *reinterpret_cast<uint4*>(&g_vth[off + 8]) = make_uint4(hp[4], hp[5], hp[6], hp[7]);
    }
}

// ---------------------------------------------------------------------------
// attn: split-KV causal flash attention, fp16 single-term S and PV,
// exp2 softmax, inline split merge (second finisher merges).
// grid (49, 8), 128 thr. smem: q + 2 x (k, v) = 5 tiles = 46 KB.
// ---------------------------------------------------------------------------
#define APE 72
#define APB (64 * APE * 2)
#define ATTN_SMEM (5 * APB)              // 46080 bytes

__constant__ uchar4 c_units[49] = {
    {31,0,16,0},{31,16,32,1},{30,0,16,0},
    {30,16,31,1},{29,0,15,0},{29,15,30,1},{28,0,15,0},{14,0,15,0},
    {28,15,29,1},{27,0,14,0},{27,14,28,1},{26,0,14,0},{13,0,14,0},
    {26,14,27,1},{25,0,13,0},{25,13,26,1},{24,0,13,0},{12,0,13,0},
    {24,13,25,1},{23,0,12,0},{23,12,24,1},{22,0,12,0},{11,0,12,0},
    {22,12,23,1},{21,0,11,0},{21,11,22,1},{20,0,11,0},{10,0,11,0},
    {20,11,21,1},{19,0,10,0},{19,10,20,1},{18,0,10,0},{9,0,10,0},
    {18,10,19,1},{17,0,9,0},{17,9,18,1},{16,0,9,0},{8,0,9,0},
    {16,9,17,1},{15,0,8,0},{15,8,16,1},{7,0,8,0},
    {6,0,7,0},{5,0,6,0},{4,0,5,0},{3,0,4,0},{2,0,3,0},{1,0,2,0},{0,0,1,0}
};

__device__ __forceinline__ void stage_kv(char* smbuf,
    const uint16_t* __restrict__ gk, const uint16_t* __restrict__ gv,
    int j, int tid)
{
    #pragma unroll
    for (int i = 0; i < 4; i++) {
        int u = tid + i * 128;
        int r = u >> 3, c8 = (u & 7) * 8;
        uint32_t d = smem_u32(smbuf + (r * APE + c8) * 2);
        cp16(d,       gk + (size_t)(j * 64 + r) * HEAD + c8);
        cp16(d + APB, gv + (size_t)r * SEQ + j * 64 + c8);
    }
    cp_commit();
}

__global__ __launch_bounds__(128) void attn_kernel(float* __restrict__ out)
{
    extern __shared__ char sm[];
    __shared__ int s_flag;
    const uchar4 u = c_units[blockIdx.x];
    const int tile = u.x, c0 = u.y, c1 = u.z, slot = u.w;
    const int b = blockIdx.y;
    const int tid = threadIdx.x;
    const int warp = tid >> 5, lane = tid & 31;
    const int g = lane >> 2, tg = lane & 3;
    const int qr = warp * 16;
    const int l8 = lane & 7, mi = lane >> 3;

    const uint32_t smu = smem_u32(sm);
    const uint32_t aQ = smu + ((qr + ((mi & 1) << 3) + l8) * APE + ((mi >> 1) << 3)) * 2;
    const uint32_t bloc = ((((mi >> 1) << 3) + l8) * APE + ((mi & 1) << 3)) * 2;

    uint16_t* qh = reinterpret_cast<uint16_t*>(sm);

    const uint16_t* __restrict__ gqh = g_qh + (size_t)b * SEQ * HEAD;
    const uint16_t* __restrict__ gkh = g_kh + (size_t)b * SEQ * HEAD;
    const uint16_t* __restrict__ gvh = g_vth + (size_t)b * HEAD * SEQ;

    stage_kv(sm + (1 + (c0 & 1) * 2) * APB, gkh, gvh, c0, tid);
    if (c0 + 1 < c1)
        stage_kv(sm + (1 + ((c0 + 1) & 1) * 2) * APB, gkh, gvh, c0 + 1, tid);

    #pragma unroll
    for (int i = 0; i < 4; i++) {
        int uu = tid + i * 128;
        int r = uu >> 3, c8 = (uu & 7) * 8;
        *reinterpret_cast<uint4*>(&qh[r * APE + c8]) =
            *reinterpret_cast<const uint4*>(&gqh[(size_t)(tile * 64 + r) * HEAD + c8]);
    }

    float mx0 = -CUDART_INF_F, mx1 = -CUDART_INF_F;
    float l0 = 0.f, l1 = 0.f;
    float4 o[8] = {};

    for (int j = c0; j < c1; j++) {
        if (j == c1 - 1) cp_wait<0>(); else cp_wait<1>();
        __syncthreads();

        const uint32_t kb = smu + (1 + (j & 1) * 2) * APB + bloc;
        const uint32_t vb = kb + APB;

        // ---- S = Q·K (Q pre-scaled by 0.125*log2e) ----
        float4 s[8] = {};
        #pragma unroll
        for (int kk = 0; kk < 4; kk++) {
            uint32_t ah0, ah1, ah2, ah3;
            ldsm4(ah0, ah1, ah2, ah3, aQ + kk * 32);
            #pragma unroll
            for (int ntp = 0; ntp < 4; ntp++) {
                uint32_t ba = kb + ntp * (16 * APE * 2) + kk * 32;
                uint32_t bh0, bh1, bh2, bh3;
                ldsm4(bh0, bh1, bh2, bh3, ba);
                mma16(s[2*ntp],   ah0, ah1, ah2, ah3, bh0, bh1);
                mma16(s[2*ntp+1], ah0, ah1, ah2, ah3, bh2, bh3);
            }
        }

        // ---- causal mask (diagonal chunk only) ----
        if (j == tile) {
            const int rg0 = tile * 64 + qr + g;
            const int rg1 = rg0 + 8;
            #pragma unroll
            for (int nt = 0; nt < 8; nt++) {
                const int cg = j * 64 + nt * 8 + 2 * tg;
                if (cg     > rg0) s[nt].x = -CUDART_INF_F;
                if (cg + 1 > rg0) s[nt].y = -CUDART_INF_F;
                if (cg     > rg1) s[nt].z = -CUDART_INF_F;
                if (cg + 1 > rg1) s[nt].w = -CUDART_INF_F;
            }
        }

        // ---- online softmax (exp2 domain) ----
        float rm0 = -CUDART_INF_F, rm1 = -CUDART_INF_F;
        #pragma unroll
        for (int nt = 0; nt < 8; nt++) {
            rm0 = fmaxf(rm0, fmaxf(s[nt].x, s[nt].y));
            rm1 = fmaxf(rm1, fmaxf(s[nt].z, s[nt].w));
        }
        rm0 = fmaxf(rm0, __shfl_xor_sync(0xffffffffu, rm0, 1));
        rm0 = fmaxf(rm0, __shfl_xor_sync(0xffffffffu, rm0, 2));
        rm1 = fmaxf(rm1, __shfl_xor_sync(0xffffffffu, rm1, 1));
        rm1 = fmaxf(rm1, __shfl_xor_sync(0xffffffffu, rm1, 2));
        const float nm0 = fmaxf(mx0, rm0);
        const float nm1 = fmaxf(mx1, rm1);
        const float a0 = exp2f(mx0 - nm0);
        const float a1 = exp2f(mx1 - nm1);

        uint32_t pa[8], pb[8];
        float rs0 = 0.f, rs1 = 0.f;
        #pragma unroll
        for (int nt = 0; nt < 8; nt++) {
            float px = exp2f(s[nt].x - nm0);
            float py = exp2f(s[nt].y - nm0);
            float pz = exp2f(s[nt].z - nm1);
            float pw = exp2f(s[nt].w - nm1);
            rs0 += px + py;
            rs1 += pz + pw;
            pa[nt] = packhf(px, py);
            pb[nt] = packhf(pz, pw);
        }
        rs0 += __shfl_xor_sync(0xffffffffu, rs0, 1);
        rs0 += __shfl_xor_sync(0xffffffffu, rs0, 2);
        rs1 += __shfl_xor_sync(0xffffffffu, rs1, 1);
        rs1 += __shfl_xor_sync(0xffffffffu, rs1, 2);
        l0 = l0 * a0 + rs0;
        l1 = l1 * a1 + rs1;
        mx0 = nm0; mx1 = nm1;
        #pragma unroll
        for (int nt = 0; nt < 8; nt++) {
            o[nt].x *= a0; o[nt].y *= a0;
            o[nt].z *= a1; o[nt].w *= a1;
        }

        // ---- O += P·V ----
        #pragma unroll
        for (int kk = 0; kk < 4; kk++) {
            uint32_t a0f = pa[2 * kk],     a1f = pb[2 * kk];
            uint32_t a2f = pa[2 * kk + 1], a3f = pb[2 * kk + 1];
            #pragma unroll
            for (int ntp = 0; ntp < 4; ntp++) {
                uint32_t ba = vb + ntp * (16 * APE * 2) + kk * 32;
                uint32_t vh0, vh1, vh2, vh3;
                ldsm4(vh0, vh1, vh2, vh3, ba);
                mma16(o[2*ntp],   a0f, a1f, a2f, a3f, vh0, vh1);
                mma16(o[2*ntp+1], a0f, a1f, a2f, a3f, vh2, vh3);
            }
        }
        __syncthreads();
        if (j + 2 < c1)
            stage_kv(sm + (1 + (j & 1) * 2) * APB, gkh, gvh, j + 2, tid);
    }

    if (c0 == 0 && c1 == tile + 1) {
        const float inv0 = __frcp_rn(l0);
        const float inv1 = __frcp_rn(l1);
        #pragma unroll
        for (int nt = 0; nt < 8; nt++) {
            int col = nt * 8 + 2 * tg;
            *reinterpret_cast<float2*>(
                &out[((size_t)b * SEQ + tile * 64 + qr + g    ) * HEAD + col]) =
                make_float2(o[nt].x * inv0, o[nt].y * inv0);
            *reinterpret_cast<float2*>(
                &out[((size_t)b * SEQ + tile * 64 + qr + g + 8) * HEAD + col]) =
                make_float2(o[nt].z * inv1, o[nt].w * inv1);
        }
        return;
    }

    // ---- split tile: publish partial, second finisher merges ----
    const int tix  = b * 32 + tile;
    const int sidx = tix * 2 + slot;
    {
        float* po = g_po + (size_t)sidx * 64 * 64;
        #pragma unroll
        for (int nt = 0; nt < 8; nt++) {
            int col = nt * 8 + 2 * tg;
            *reinterpret_cast<float2*>(&po[(qr + g    ) * 64 + col]) = make_float2(o[nt].x, o[nt].y);
            *reinterpret_cast<float2*>(&po[(qr + g + 8) * 64 + col]) = make_float2(o[nt].z, o[nt].w);
        }
        if (tg == 0) {
            g_pm[sidx * 64 + qr + g    ] = mx0;
            g_pm[sidx * 64 + qr + g + 8] = mx1;
            g_pl[sidx * 64 + qr + g    ] = l0;
            g_pl[sidx * 64 + qr + g + 8] = l1;
        }
    }
    __threadfence();
    __syncthreads();
    if (tid == 0) s_flag = atomicAdd(&g_cnt[tix], 1) & 1;
    __syncthreads();
    if (!s_flag) return;    // first finisher: partner will merge
    __threadfence();        // acquire partner's published data

    const int pidx = tix * 2 + (1 - slot);
    const float* pp = g_po + (size_t)pidx * 64 * 64;
    const float pm0 = g_pm[pidx * 64 + qr + g],     pm1 = g_pm[pidx * 64 + qr + g + 8];
    const float pL0 = g_pl[pidx * 64 + qr + g],     pL1 = g_pl[pidx * 64 + qr + g + 8];
    const float m0f = fmaxf(mx0, pm0), m1f = fmaxf(mx1, pm1);
    const float ws0 = exp2f(mx0 - m0f), wp0 = exp2f(pm0 - m0f);
    const float ws1 = exp2f(mx1 - m1f), wp1 = exp2f(pm1 - m1f);
    const float inv0 = __frcp_rn(l0 * ws0 + pL0 * wp0);
    const float inv1 = __frcp_rn(l1 * ws1 + pL1 * wp1);
    const float c00 = ws0 * inv0, c01 = wp0 * inv0;
    const float c10 = ws1 * inv1, c11 = wp1 * inv1;
    #pragma unroll
    for (int nt = 0; nt < 8; nt++) {
        int col = nt * 8 + 2 * tg;
        float2 q0 = *reinterpret_cast<const float2*>(&pp[(qr + g    ) * 64 + col]);
        float2 q1 = *reinterpret_cast<const float2*>(&pp[(qr + g + 8) * 64 + col]);
        *reinterpret_cast<float2*>(
            &out[((size_t)b * SEQ + tile * 64 + qr + g    ) * HEAD + col]) =
            make_float2(o[nt].x * c00 + q0.x * c01, o[nt].y * c00 + q0.y * c01);
        *reinterpret_cast<float2*>(
            &out[((size_t)b * SEQ + tile * 64 + qr + g + 8) * HEAD + col]) =
            make_float2(o[nt].z * c10 + q1.x * c11, o[nt].w * c10 + q1.y * c11);
    }
}

// ---------------------------------------------------------------------------
extern "C" void kernel_launch(void* const* d_in, const int* in_sizes, int n_in,
                              void* d_out, int out_size)
{
    const float* x  = (const float*)d_in[0];
    const float* Wq = (const float*)d_in[1];
    const float* Wk = (const float*)d_in[2];
    const float* Wv = (const float*)d_in[3];
    float* out = (float*)d_out;

    (void)in_sizes; (void)n_in; (void)out_size;

    cudaFuncSetAttribute(proj_kernel,
                         cudaFuncAttributeMaxDynamicSharedMemorySize, PROJ_SMEM);
    cudaFuncSetAttribute(attn_kernel,
                         cudaFuncAttributeMaxDynamicSharedMemorySize, ATTN_SMEM);

    wprep_kernel<<<dim3(16, 3), 256>>>(Wq, Wk, Wv);
    proj_kernel<<<256, 256, PROJ_SMEM>>>(x);
    attn_kernel<<<dim3(49, 8), 128, ATTN_SMEM>>>(out);
}

// round 12
// speedup vs baseline: 7.2820x; 1.0040x over previous
#include <cuda_runtime.h>
#include <cuda_fp16.h>
#include <math_constants.h>
#include <cstdint>

#define N_EMBED 1024
#define HEAD    64
#define BATCH   8
#define SEQ     2048
#define MROWS   (BATCH * SEQ)   // 16384

// ---------------------------------------------------------------------------
// Global scratch (fp16)
// ---------------------------------------------------------------------------
__device__ uint16_t g_qh[MROWS * HEAD];                            // Q*0.125*log2e fp16
__device__ uint16_t g_kh[MROWS * HEAD];                            // K fp16 [row][head]
__device__ uint16_t g_vth[MROWS * HEAD];                           // V^T fp16 [b][head][seq]
__device__ uint16_t g_wth[3 * HEAD * N_EMBED];                     // W^T fp16 [which][n][k]
// split-KV partials + completion counters
__device__ float g_po[BATCH * 32 * 2 * 64 * 64];
__device__ float g_pm[BATCH * 32 * 2 * 64];
__device__ float g_pl[BATCH * 32 * 2 * 64];
__device__ int   g_cnt[BATCH * 32];     // zero-init; +2 per replay per split tile

// ---------------------------------------------------------------------------
// helpers
// ---------------------------------------------------------------------------
__device__ __forceinline__ uint32_t packhf(float x0, float x1) {
    __half2 h = __floats2half2_rn(x0, x1);
    return *reinterpret_cast<uint32_t*>(&h);
}
__device__ __forceinline__ float ex2f(float x) {
    float y;
    asm("ex2.approx.f32 %0, %1;" : "=f"(y) : "f"(x));
    return y;
}
__device__ __forceinline__ void mma16(float4& c,
                                      uint32_t a0, uint32_t a1, uint32_t a2, uint32_t a3,
                                      uint32_t b0, uint32_t b1) {
    asm volatile(
        "mma.sync.aligned.m16n8k16.row.col.f32.f16.f16.f32 "
        "{%0,%1,%2,%3}, {%4,%5,%6,%7}, {%8,%9}, {%0,%1,%2,%3};"
        : "+f"(c.x), "+f"(c.y), "+f"(c.z), "+f"(c.w)
        : "r"(a0), "r"(a1), "r"(a2), "r"(a3), "r"(b0), "r"(b1));
}
__device__ __forceinline__ void ldsm4(uint32_t& r0, uint32_t& r1, uint32_t& r2,
                                      uint32_t& r3, uint32_t addr) {
    asm volatile("ldmatrix.sync.aligned.m8n8.x4.shared.b16 {%0,%1,%2,%3}, [%4];"
                 : "=r"(r0), "=r"(r1), "=r"(r2), "=r"(r3) : "r"(addr));
}
__device__ __forceinline__ void cp16(uint32_t dst, const void* src) {
    asm volatile("cp.async.cg.shared.global [%0], [%1], 16;" :: "r"(dst), "l"(src));
}
__device__ __forceinline__ void cp_commit() {
    asm volatile("cp.async.commit_group;");
}
template <int N>
__device__ __forceinline__ void cp_wait() {
    asm volatile("cp.async.wait_group %0;" :: "n"(N));
}
__device__ __forceinline__ uint32_t smem_u32(const void* p) {
    return (uint32_t)__cvta_generic_to_shared(p);
}

// 0.125 * log2(e): folded into Q so softmax uses exp2 directly
#define QSCALE 0.18033688011112042f

// ---------------------------------------------------------------------------
// wprep: W [k][n] fp32 -> W^T [n][k] fp16.  grid (64, 3), 256 thr.
// Each CTA: 16 k-rows x 64 n.  192 CTAs -> latency hidden.
// ---------------------------------------------------------------------------
__global__ __launch_bounds__(256) void wprep_kernel(
    const float* __restrict__ Wq, const float* __restrict__ Wk,
    const float* __restrict__ Wv)
{
    const int which = blockIdx.y;
    const float* __restrict__ W = (which == 0) ? Wq : (which == 1) ? Wk : Wv;
    const int k0 = blockIdx.x * 16;

    __shared__ float sw[16][68];
    const int t = threadIdx.x;
    {
        const int r = t >> 4, c4 = (t & 15) * 4;
        float4 v = *reinterpret_cast<const float4*>(&W[(size_t)(k0 + r) * HEAD + c4]);
        sw[r][c4 + 0] = v.x; sw[r][c4 + 1] = v.y;
        sw[r][c4 + 2] = v.z; sw[r][c4 + 3] = v.w;
    }
    __syncthreads();
    {
        const int n = t >> 2, kg = (t & 3) * 4;
        uint32_t h0 = packhf(sw[kg + 0][n], sw[kg + 1][n]);
        uint32_t h1 = packhf(sw[kg + 2][n], sw[kg + 3][n]);
        size_t off = ((size_t)(which * HEAD + n)) * N_EMBED + k0 + kg;
        *reinterpret_cast<uint2*>(&g_wth[off]) = make_uint2(h0, h1);
    }
}

// ---------------------------------------------------------------------------
// Fused proj: single-term fp16 GEMM. 64-row tiles, 256 CTAs, ldmatrix frags.
// Outputs: Q (scaled, fp16), K (fp16), V^T (fp16).
// ---------------------------------------------------------------------------
#define WP     40
#define XTILE  (64 * WP * 2)            // 5120 bytes
#define PBUF   (4 * XTILE)              // xh, w0, w1, w2
#define PROJ_SMEM (2 * PBUF)            // 40960 bytes

__device__ __forceinline__ void proj_stage_w(char* sm, int buf, int ch, int t)
{
    const int kc0 = ch * 32;
    #pragma unroll
    for (int i = 0; i < 3; i++) {
        int u = t + i * 256;                // 0..767: 3 tiles x 256 16B-blocks
        int w = u >> 8, blk = u & 255;
        int row = blk >> 2, q = blk & 3;
        const uint16_t* src = g_wth + (size_t)(w * HEAD + row) * N_EMBED + kc0 + q * 8;
        uint32_t d = smem_u32(sm + buf * PBUF + (1 + w) * XTILE + (row * WP + q * 8) * 2);
        cp16(d, src);
    }
    cp_commit();
}

__global__ __launch_bounds__(256) void proj_kernel(const float* __restrict__ x)
{
    extern __shared__ char sm[];
    const int m0 = blockIdx.x * 64;
    const int t = threadIdx.x;
    const int warp = t >> 5, lane = t & 31;
    const int g = lane >> 2, tg = lane & 3;
    const int wm = warp >> 1, wn = warp & 1;
    const int l8 = lane & 7, mi = lane >> 3;

    const uint32_t smu = smem_u32(sm);
    const uint32_t aX = smu + ((wm * 16 + ((mi & 1) << 3) + l8) * WP + ((mi >> 1) << 3)) * 2;
    const uint32_t bW = smu + XTILE +
                        ((wn * 32 + ((mi >> 1) << 3) + l8) * WP + ((mi & 1) << 3)) * 2;

    const int xrow = t >> 2, xc8 = (t & 3) * 8;

    float4 acc[3][4] = {};
    float4 xr0, xr1;

    {
        const float* src = x + (size_t)(m0 + xrow) * N_EMBED + xc8;
        xr0 = *reinterpret_cast<const float4*>(src);
        xr1 = *reinterpret_cast<const float4*>(src + 4);
        *reinterpret_cast<uint4*>(sm + (xrow * WP + xc8) * 2) =
            make_uint4(packhf(xr0.x, xr0.y), packhf(xr0.z, xr0.w),
                       packhf(xr1.x, xr1.y), packhf(xr1.z, xr1.w));
        proj_stage_w(sm, 0, 0, t);
        xr0 = *reinterpret_cast<const float4*>(src + 32);
        xr1 = *reinterpret_cast<const float4*>(src + 36);
    }

    for (int ch = 0; ch < 32; ch++) {
        cp_wait<0>();
        __syncthreads();
        const int buf = ch & 1;

        if (ch + 1 < 32) {
            const int nbuf = (ch + 1) & 1;
            *reinterpret_cast<uint4*>(sm + nbuf * PBUF + (xrow * WP + xc8) * 2) =
                make_uint4(packhf(xr0.x, xr0.y), packhf(xr0.z, xr0.w),
                           packhf(xr1.x, xr1.y), packhf(xr1.z, xr1.w));
            proj_stage_w(sm, nbuf, ch + 1, t);
            if (ch + 2 < 32) {
                const float* src = x + (size_t)(m0 + xrow) * N_EMBED + (ch + 2) * 32 + xc8;
                xr0 = *reinterpret_cast<const float4*>(src);
                xr1 = *reinterpret_cast<const float4*>(src + 4);
            }
        }

        const uint32_t ax = aX + buf * PBUF;
        const uint32_t bw = bW + buf * PBUF;
        #pragma unroll
        for (int kk = 0; kk < 2; kk++) {
            uint32_t ah0, ah1, ah2, ah3;
            ldsm4(ah0, ah1, ah2, ah3, ax + kk * 32);
            #pragma unroll
            for (int w = 0; w < 3; w++) {
                #pragma unroll
                for (int ntp = 0; ntp < 2; ntp++) {
                    uint32_t ba = bw + w * XTILE + ntp * (16 * WP * 2) + kk * 32;
                    uint32_t bh0, bh1, bh2, bh3;
                    ldsm4(bh0, bh1, bh2, bh3, ba);
                    mma16(acc[w][2*ntp],   ah0, ah1, ah2, ah3, bh0, bh1);
                    mma16(acc[w][2*ntp+1], ah0, ah1, ah2, ah3, bh2, bh3);
                }
            }
        }
        __syncthreads();
    }

    // ---- epilogue: Q scaled fp16; K plain fp16 ----
    #pragma unroll
    for (int nt = 0; nt < 4; nt++) {
        int m   = m0 + wm * 16 + g;
        int col = wn * 32 + nt * 8 + 2 * tg;
        reinterpret_cast<uint32_t*>(g_qh)[((size_t)m * HEAD + col) >> 1] =
            packhf(acc[0][nt].x * QSCALE, acc[0][nt].y * QSCALE);
        reinterpret_cast<uint32_t*>(g_qh)[((size_t)(m + 8) * HEAD + col) >> 1] =
            packhf(acc[0][nt].z * QSCALE, acc[0][nt].w * QSCALE);
        reinterpret_cast<uint32_t*>(g_kh)[((size_t)m * HEAD + col) >> 1] =
            packhf(acc[1][nt].x, acc[1][nt].y);
        reinterpret_cast<uint32_t*>(g_kh)[((size_t)(m + 8) * HEAD + col) >> 1] =
            packhf(acc[1][nt].z, acc[1][nt].w);
    }

    // ---- epilogue: V -> V^T fp16 (fused transpose via smem) ----
    float* sv = reinterpret_cast<float*>(sm);   // [64][68] fp32 = 17408 B
    __syncthreads();
    #pragma unroll
    for (int nt = 0; nt < 4; nt++) {
        int r0 = wm * 16 + g;
        int col = wn * 32 + nt * 8 + 2 * tg;
        sv[r0 * 68 + col] = acc[2][nt].x; sv[r0 * 68 + col + 1] = acc[2][nt].y;
        sv[(r0 + 8) * 68 + col] = acc[2][nt].z; sv[(r0 + 8) * 68 + col + 1] = acc[2][nt].w;
    }
    __syncthreads();
    {
        const int r = t >> 2, c16 = (t & 3) * 16;
        uint32_t hp[8];
        #pragma unroll
        for (int i = 0; i < 8; i++)
            hp[i] = packhf(sv[(c16 + 2 * i) * 68 + r], sv[(c16 + 2 * i + 1) * 68 + r]);
        const int b = m0 >> 11;
        const int seq0 = m0 & 2047;
        size_t off = ((size_t)(b * HEAD + r)) * SEQ + seq0 + c16;
        *reinterpret_cast<uint4*>(&g_vth[off    ]) = make_uint4(hp[0], hp[1], hp[2], hp[3]);
        *reinterpret_cast<uint4*>(&g_vth[off + 8]) = make_uint4(hp[4], hp[5], hp[6], hp[7]);
    }
}

// ---------------------------------------------------------------------------
// attn: split-KV causal flash attention, fp16 single-term S and PV,
// ex2.approx softmax, inline split merge, forced 4 CTA/SM occupancy.
// grid (49, 8), 128 thr. smem: q + 2 x (k, v) = 5 tiles = 46 KB.
// ---------------------------------------------------------------------------
#define APE 72
#define APB (64 * APE * 2)
#define ATTN_SMEM (5 * APB)              // 46080 bytes

__constant__ uchar4 c_units[49] = {
    {31,0,16,0},{31,16,32,1},{30,0,16,0},
    {30,16,31,1},{29,0,15,0},{29,15,30,1},{28,0,15,0},{14,0,15,0},
    {28,15,29,1},{27,0,14,0},{27,14,28,1},{26,0,14,0},{13,0,14,0},
    {26,14,27,1},{25,0,13,0},{25,13,26,1},{24,0,13,0},{12,0,13,0},
    {24,13,25,1},{23,0,12,0},{23,12,24,1},{22,0,12,0},{11,0,12,0},
    {22,12,23,1},{21,0,11,0},{21,11,22,1},{20,0,11,0},{10,0,11,0},
    {20,11,21,1},{19,0,10,0},{19,10,20,1},{18,0,10,0},{9,0,10,0},
    {18,10,19,1},{17,0,9,0},{17,9,18,1},{16,0,9,0},{8,0,9,0},
    {16,9,17,1},{15,0,8,0},{15,8,16,1},{7,0,8,0},
    {6,0,7,0},{5,0,6,0},{4,0,5,0},{3,0,4,0},{2,0,3,0},{1,0,2,0},{0,0,1,0}
};

__device__ __forceinline__ void stage_kv(char* smbuf,
    const uint16_t* __restrict__ gk, const uint16_t* __restrict__ gv,
    int j, int tid)
{
    #pragma unroll
    for (int i = 0; i < 4; i++) {
        int u = tid + i * 128;
        int r = u >> 3, c8 = (u & 7) * 8;
        uint32_t d = smem_u32(smbuf + (r * APE + c8) * 2);
        cp16(d,       gk + (size_t)(j * 64 + r) * HEAD + c8);
        cp16(d + APB, gv + (size_t)r * SEQ + j * 64 + c8);
    }
    cp_commit();
}

__global__ __launch_bounds__(128, 4) void attn_kernel(float* __restrict__ out)
{
    extern __shared__ char sm[];
    __shared__ int s_flag;
    const uchar4 u = c_units[blockIdx.x];
    const int tile = u.x, c0 = u.y, c1 = u.z, slot = u.w;
    const int b = blockIdx.y;
    const int tid = threadIdx.x;
    const int warp = tid >> 5, lane = tid & 31;
    const int g = lane >> 2, tg = lane & 3;
    const int qr = warp * 16;
    const int l8 = lane & 7, mi = lane >> 3;

    const uint32_t smu = smem_u32(sm);
    const uint32_t aQ = smu + ((qr + ((mi & 1) << 3) + l8) * APE + ((mi >> 1) << 3)) * 2;
    const uint32_t bloc = ((((mi >> 1) << 3) + l8) * APE + ((mi & 1) << 3)) * 2;

    uint16_t* qh = reinterpret_cast<uint16_t*>(sm);

    const uint16_t* __restrict__ gqh = g_qh + (size_t)b * SEQ * HEAD;
    const uint16_t* __restrict__ gkh = g_kh + (size_t)b * SEQ * HEAD;
    const uint16_t* __restrict__ gvh = g_vth + (size_t)b * HEAD * SEQ;

    stage_kv(sm + (1 + (c0 & 1) * 2) * APB, gkh, gvh, c0, tid);
    if (c0 + 1 < c1)
        stage_kv(sm + (1 + ((c0 + 1) & 1) * 2) * APB, gkh, gvh, c0 + 1, tid);

    #pragma unroll
    for (int i = 0; i < 4; i++) {
        int uu = tid + i * 128;
        int r = uu >> 3, c8 = (uu & 7) * 8;
        *reinterpret_cast<uint4*>(&qh[r * APE + c8]) =
            *reinterpret_cast<const uint4*>(&gqh[(size_t)(tile * 64 + r) * HEAD + c8]);
    }

    float mx0 = -CUDART_INF_F, mx1 = -CUDART_INF_F;
    float l0 = 0.f, l1 = 0.f;
    float4 o[8] = {};

    for (int j = c0; j < c1; j++) {
        if (j == c1 - 1) cp_wait<0>(); else cp_wait<1>();
        __syncthreads();

        const uint32_t kb = smu + (1 + (j & 1) * 2) * APB + bloc;
        const uint32_t vb = kb + APB;

        // ---- S = Q·K (Q pre-scaled by 0.125*log2e) ----
        float4 s[8] = {};
        #pragma unroll
        for (int kk = 0; kk < 4; kk++) {
            uint32_t ah0, ah1, ah2, ah3;
            ldsm4(ah0, ah1, ah2, ah3, aQ + kk * 32);
            #pragma unroll
            for (int ntp = 0; ntp < 4; ntp++) {
                uint32_t ba = kb + ntp * (16 * APE * 2) + kk * 32;
                uint32_t bh0, bh1, bh2, bh3;
                ldsm4(bh0, bh1, bh2, bh3, ba);
                mma16(s[2*ntp],   ah0, ah1, ah2, ah3, bh0, bh1);
                mma16(s[2*ntp+1], ah0, ah1, ah2, ah3, bh2, bh3);
            }
        }

        // ---- causal mask (diagonal chunk only) ----
        if (j == tile) {
            const int rg0 = tile * 64 + qr + g;
            const int rg1 = rg0 + 8;
            #pragma unroll
            for (int nt = 0; nt < 8; nt++) {
                const int cg = j * 64 + nt * 8 + 2 * tg;
                if (cg     > rg0) s[nt].x = -CUDART_INF_F;
                if (cg + 1 > rg0) s[nt].y = -CUDART_INF_F;
                if (cg     > rg1) s[nt].z = -CUDART_INF_F;
                if (cg + 1 > rg1) s[nt].w = -CUDART_INF_F;
            }
        }

        // ---- online softmax (exp2 domain, ex2.approx) ----
        float rm0 = -CUDART_INF_F, rm1 = -CUDART_INF_F;
        #pragma unroll
        for (int nt = 0; nt < 8; nt++) {
            rm0 = fmaxf(rm0, fmaxf(s[nt].x, s[nt].y));
            rm1 = fmaxf(rm1, fmaxf(s[nt].z, s[nt].w));
        }
        rm0 = fmaxf(rm0, __shfl_xor_sync(0xffffffffu, rm0, 1));
        rm0 = fmaxf(rm0, __shfl_xor_sync(0xffffffffu, rm0, 2));
        rm1 = fmaxf(rm1, __shfl_xor_sync(0xffffffffu, rm1, 1));
        rm1 = fmaxf(rm1, __shfl_xor_sync(0xffffffffu, rm1, 2));
        const float nm0 = fmaxf(mx0, rm0);
        const float nm1 = fmaxf(mx1, rm1);
        const float a0 = ex2f(mx0 - nm0);
        const float a1 = ex2f(mx1 - nm1);

        uint32_t pa[8], pb[8];
        float rs0 = 0.f, rs1 = 0.f;
        #pragma unroll
        for (int nt = 0; nt < 8; nt++) {
            float px = ex2f(s[nt].x - nm0);
            float py = ex2f(s[nt].y - nm0);
            float pz = ex2f(s[nt].z - nm1);
            float pw = ex2f(s[nt].w - nm1);
            rs0 += px + py;
            rs1 += pz + pw;
            pa[nt] = packhf(px, py);
            pb[nt] = packhf(pz, pw);
        }
        rs0 += __shfl_xor_sync(0xffffffffu, rs0, 1);
        rs0 += __shfl_xor_sync(0xffffffffu, rs0, 2);
        rs1 += __shfl_xor_sync(0xffffffffu, rs1, 1);
        rs1 += __shfl_xor_sync(0xffffffffu, rs1, 2);
        l0 = l0 * a0 + rs0;
        l1 = l1 * a1 + rs1;
        mx0 = nm0; mx1 = nm1;
        #pragma unroll
        for (int nt = 0; nt < 8; nt++) {
            o[nt].x *= a0; o[nt].y *= a0;
            o[nt].z *= a1; o[nt].w *= a1;
        }

        // ---- O += P·V ----
        #pragma unroll
        for (int kk = 0; kk < 4; kk++) {
            uint32_t a0f = pa[2 * kk],     a1f = pb[2 * kk];
            uint32_t a2f = pa[2 * kk + 1], a3f = pb[2 * kk + 1];
            #pragma unroll
            for (int ntp = 0; ntp < 4; ntp++) {
                uint32_t ba = vb + ntp * (16 * APE * 2) + kk * 32;
                uint32_t vh0, vh1, vh2, vh3;
                ldsm4(vh0, vh1, vh2, vh3, ba);
                mma16(o[2*ntp],   a0f, a1f, a2f, a3f, vh0, vh1);
                mma16(o[2*ntp+1], a0f, a1f, a2f, a3f, vh2, vh3);
            }
        }
        __syncthreads();
        if (j + 2 < c1)
            stage_kv(sm + (1 + (j & 1) * 2) * APB, gkh, gvh, j + 2, tid);
    }

    if (c0 == 0 && c1 == tile + 1) {
        const float inv0 = __frcp_rn(l0);
        const float inv1 = __frcp_rn(l1);
        #pragma unroll
        for (int nt = 0; nt < 8; nt++) {
            int col = nt * 8 + 2 * tg;
            *reinterpret_cast<float2*>(
                &out[((size_t)b * SEQ + tile * 64 + qr + g    ) * HEAD + col]) =
                make_float2(o[nt].x * inv0, o[nt].y * inv0);
            *reinterpret_cast<float2*>(
                &out[((size_t)b * SEQ + tile * 64 + qr + g + 8) * HEAD + col]) =
                make_float2(o[nt].z * inv1, o[nt].w * inv1);
        }
        return;
    }

    // ---- split tile: publish partial, second finisher merges ----
    const int tix  = b * 32 + tile;
    const int sidx = tix * 2 + slot;
    {
        float* po = g_po + (size_t)sidx * 64 * 64;
        #pragma unroll
        for (int nt = 0; nt < 8; nt++) {
            int col = nt * 8 + 2 * tg;
            *reinterpret_cast<float2*>(&po[(qr + g    ) * 64 + col]) = make_float2(o[nt].x, o[nt].y);
            *reinterpret_cast<float2*>(&po[(qr + g + 8) * 64 + col]) = make_float2(o[nt].z, o[nt].w);
        }
        if (tg == 0) {
            g_pm[sidx * 64 + qr + g    ] = mx0;
            g_pm[sidx * 64 + qr + g + 8] = mx1;
            g_pl[sidx * 64 + qr + g    ] = l0;
            g_pl[sidx * 64 + qr + g + 8] = l1;
        }
    }
    __threadfence();
    __syncthreads();
    if (tid == 0) s_flag = atomicAdd(&g_cnt[tix], 1) & 1;
    __syncthreads();
    if (!s_flag) return;    // first finisher: partner will merge
    __threadfence();        // acquire partner's published data

    const int pidx = tix * 2 + (1 - slot);
    const float* pp = g_po + (size_t)pidx * 64 * 64;
    const float pm0 = g_pm[pidx * 64 + qr + g],     pm1 = g_pm[pidx * 64 + qr + g + 8];
    const float pL0 = g_pl[pidx * 64 + qr + g],     pL1 = g_pl[pidx * 64 + qr + g + 8];
    const float m0f = fmaxf(mx0, pm0), m1f = fmaxf(mx1, pm1);
    const float ws0 = ex2f(mx0 - m0f), wp0 = ex2f(pm0 - m0f);
    const float ws1 = ex2f(mx1 - m1f), wp1 = ex2f(pm1 - m1f);
    const float inv0 = __frcp_rn(l0 * ws0 + pL0 * wp0);
    const float inv1 = __frcp_rn(l1 * ws1 + pL1 * wp1);
    const float c00 = ws0 * inv0, c01 = wp0 * inv0;
    const float c10 = ws1 * inv1, c11 = wp1 * inv1;
    #pragma unroll
    for (int nt = 0; nt < 8; nt++) {
        int col = nt * 8 + 2 * tg;
        float2 q0 = *reinterpret_cast<const float2*>(&pp[(qr + g    ) * 64 + col]);
        float2 q1 = *reinterpret_cast<const float2*>(&pp[(qr + g + 8) * 64 + col]);
        *reinterpret_cast<float2*>(
            &out[((size_t)b * SEQ + tile * 64 + qr + g    ) * HEAD + col]) =
            make_float2(o[nt].x * c00 + q0.x * c01, o[nt].y * c00 + q0.y * c01);
        *reinterpret_cast<float2*>(
            &out[((size_t)b * SEQ + tile * 64 + qr + g + 8) * HEAD + col]) =
            make_float2(o[nt].z * c10 + q1.x * c11, o[nt].w * c10 + q1.y * c11);
    }
}

// ---------------------------------------------------------------------------
extern "C" void kernel_launch(void* const* d_in, const int* in_sizes, int n_in,
                              void* d_out, int out_size)
{
    const float* x  = (const float*)d_in[0];
    const float* Wq = (const float*)d_in[1];
    const float* Wk = (const float*)d_in[2];
    const float* Wv = (const float*)d_in[3];
    float* out = (float*)d_out;

    (void)in_sizes; (void)n_in; (void)out_size;

    cudaFuncSetAttribute(proj_kernel,
                         cudaFuncAttributeMaxDynamicSharedMemorySize, PROJ_SMEM);
    cudaFuncSetAttribute(attn_kernel,
                         cudaFuncAttributeMaxDynamicSharedMemorySize, ATTN_SMEM);

    wprep_kernel<<<dim3(64, 3), 256>>>(Wq, Wk, Wv);
    proj_kernel<<<256, 256, PROJ_SMEM>>>(x);
    attn_kernel<<<dim3(49, 8), 128, ATTN_SMEM>>>(out);
}